// round 1
// baseline (speedup 1.0000x reference)
#include <cuda_runtime.h>

#define D_MODEL 1024
#define NB 4
#define TQ 2048
#define TKV 2048
#define MQ (NB * TQ)

// Scratch (static device globals; no runtime allocation allowed)
__device__ float g_buf1[MQ * D_MODEL];                 // 32 MB
__device__ float g_buf2[MQ * D_MODEL];                 // 32 MB
__device__ float g_ST[NB * D_MODEL * TQ];              // 32 MB  (S transposed per batch)
__device__ float g_M[NB * D_MODEL * D_MODEL];          // 16 MB  (l @ ov per batch)

// ---------------------------------------------------------------------------
// Generic tiled SGEMM: C = A * op(B) (+ bias), fp32.
//   BNT=true : B stored [N,K] row-major (i.e. C = A @ B^T)  -> projections
//   BNT=false: B stored [K,N] row-major (i.e. C = A @ B)    -> combine GEMMs
// Tiles: 128x128x8, 256 threads, 8x8 per-thread microtile, register prefetch.
// Requires M,N multiples of 128 and K multiple of 8 (true for all our shapes).
// ---------------------------------------------------------------------------
template <bool BNT, bool HASBIAS>
__global__ void __launch_bounds__(256) sgemm_kernel(
    const float* __restrict__ A, const float* __restrict__ B,
    const float* __restrict__ bias, float* __restrict__ C,
    int M, int N, int K, long sA, long sB, long sC)
{
    A += (long)blockIdx.z * sA;
    B += (long)blockIdx.z * sB;
    C += (long)blockIdx.z * sC;

    __shared__ float As[8][128];
    __shared__ float Bs[8][128];

    const int tid = threadIdx.x;
    const int tx  = tid & 15;
    const int ty  = tid >> 4;

    const int bm = blockIdx.y * 128;
    const int bn = blockIdx.x * 128;

    // A (and B when BNT): row = tid/2 in [0,128), kq = (tid&1)*4
    const int ldRow = tid >> 1;
    const int ldK   = (tid & 1) * 4;
    // B when NN: k = tid/32 in [0,8), n4 = (tid&31)*4
    const int bRow = tid >> 5;
    const int bCol = (tid & 31) * 4;

    const float* Aptr = A + (long)(bm + ldRow) * K + ldK;
    const float* Bnt  = B + (long)(bn + ldRow) * K + ldK;
    const float* Bnn  = B + (long)bRow * N + bn + bCol;

    float4 aReg = *(const float4*)Aptr;
    float4 bReg = BNT ? *(const float4*)Bnt : *(const float4*)Bnn;

    float acc[8][8];
#pragma unroll
    for (int i = 0; i < 8; i++)
#pragma unroll
        for (int j = 0; j < 8; j++) acc[i][j] = 0.0f;

    int k0 = 0;
    while (true) {
        // Commit staged tile to shared
        As[ldK + 0][ldRow] = aReg.x;
        As[ldK + 1][ldRow] = aReg.y;
        As[ldK + 2][ldRow] = aReg.z;
        As[ldK + 3][ldRow] = aReg.w;
        if (BNT) {
            Bs[ldK + 0][ldRow] = bReg.x;
            Bs[ldK + 1][ldRow] = bReg.y;
            Bs[ldK + 2][ldRow] = bReg.z;
            Bs[ldK + 3][ldRow] = bReg.w;
        } else {
            *(float4*)&Bs[bRow][bCol] = bReg;
        }
        __syncthreads();

        k0 += 8;
        const bool more = (k0 < K);
        if (more) {
            aReg = *(const float4*)(Aptr + k0);
            bReg = BNT ? *(const float4*)(Bnt + k0)
                       : *(const float4*)(Bnn + (long)k0 * N);
        }

#pragma unroll
        for (int kk = 0; kk < 8; kk++) {
            float4 a0 = *(const float4*)&As[kk][ty * 8];
            float4 a1 = *(const float4*)&As[kk][ty * 8 + 4];
            float4 b0 = *(const float4*)&Bs[kk][tx * 8];
            float4 b1 = *(const float4*)&Bs[kk][tx * 8 + 4];
            float ar[8] = {a0.x, a0.y, a0.z, a0.w, a1.x, a1.y, a1.z, a1.w};
            float br[8] = {b0.x, b0.y, b0.z, b0.w, b1.x, b1.y, b1.z, b1.w};
#pragma unroll
            for (int i = 0; i < 8; i++)
#pragma unroll
                for (int j = 0; j < 8; j++)
                    acc[i][j] = fmaf(ar[i], br[j], acc[i][j]);
        }

        if (!more) break;
        __syncthreads();
    }

    const int cm = bm + ty * 8;
    const int cn = bn + tx * 8;
    float4 bv0 = make_float4(0.f, 0.f, 0.f, 0.f), bv1 = bv0;
    if (HASBIAS) {
        bv0 = *(const float4*)(bias + cn);
        bv1 = *(const float4*)(bias + cn + 4);
    }
#pragma unroll
    for (int i = 0; i < 8; i++) {
        float4 v0 = make_float4(acc[i][0] + bv0.x, acc[i][1] + bv0.y,
                                acc[i][2] + bv0.z, acc[i][3] + bv0.w);
        float4 v1 = make_float4(acc[i][4] + bv1.x, acc[i][5] + bv1.y,
                                acc[i][6] + bv1.z, acc[i][7] + bv1.w);
        float* crow = C + (long)(cm + i) * N + cn;
        *(float4*)(crow)     = v0;
        *(float4*)(crow + 4) = v1;
    }
}

// ---------------------------------------------------------------------------
// Row softmax over last dim (D_MODEL=1024) with transposed store:
//   ST[b][e][q] = softmax_e(X[b*TQ+q][:])[e]
// One block (256 threads) per row; 4 elements per thread.
// ---------------------------------------------------------------------------
__global__ void __launch_bounds__(256) row_softmax_T_kernel(
    const float* __restrict__ X, float* __restrict__ ST)
{
    const int row = blockIdx.x;           // 0..MQ-1
    const int b = row >> 11;              // TQ = 2048
    const int q = row & (TQ - 1);
    const int t = threadIdx.x;

    __shared__ float red[256];

    const float* x = X + (long)row * D_MODEL;
    float v[4];
    float m = -1e30f;
#pragma unroll
    for (int i = 0; i < 4; i++) {
        v[i] = x[t + i * 256];
        m = fmaxf(m, v[i]);
    }
    red[t] = m;
    __syncthreads();
    for (int s = 128; s > 0; s >>= 1) {
        if (t < s) red[t] = fmaxf(red[t], red[t + s]);
        __syncthreads();
    }
    m = red[0];
    __syncthreads();

    float sum = 0.0f;
#pragma unroll
    for (int i = 0; i < 4; i++) {
        v[i] = __expf(v[i] - m);
        sum += v[i];
    }
    red[t] = sum;
    __syncthreads();
    for (int s = 128; s > 0; s >>= 1) {
        if (t < s) red[t] += red[t + s];
        __syncthreads();
    }
    const float inv = 1.0f / red[0];

    float* dst = ST + (long)b * D_MODEL * TQ + q;
#pragma unroll
    for (int i = 0; i < 4; i++) {
        const int e = t + i * 256;
        dst[(long)e * TQ] = v[i] * inv;
    }
}

// ---------------------------------------------------------------------------
// Column softmax over T_kv (axis=-2), in place.
// grid (D/32, NB), 256 threads: 32 columns/block, 8 threads/column.
// ---------------------------------------------------------------------------
__global__ void __launch_bounds__(256) col_softmax_kernel(float* __restrict__ X)
{
    const int b = blockIdx.y;
    const int c = threadIdx.x & 31;
    const int s = threadIdx.x >> 5;       // 0..7
    const int e = blockIdx.x * 32 + c;

    float* x = X + (long)b * TKV * D_MODEL + e;
    __shared__ float red[8][32];

    float m = -1e30f;
    for (int k = s; k < TKV; k += 8) m = fmaxf(m, x[(long)k * D_MODEL]);
    red[s][c] = m;
    __syncthreads();
    if (s == 0) {
        float mm = red[0][c];
#pragma unroll
        for (int i = 1; i < 8; i++) mm = fmaxf(mm, red[i][c]);
        red[0][c] = mm;
    }
    __syncthreads();
    m = red[0][c];
    __syncthreads();

    float sum = 0.0f;
    for (int k = s; k < TKV; k += 8) sum += __expf(x[(long)k * D_MODEL] - m);
    red[s][c] = sum;
    __syncthreads();
    if (s == 0) {
        float ss = red[0][c];
#pragma unroll
        for (int i = 1; i < 8; i++) ss += red[i][c];
        red[0][c] = ss;
    }
    __syncthreads();
    const float inv = 1.0f / red[0][c];

    for (int k = s; k < TKV; k += 8) {
        const long idx = (long)k * D_MODEL;
        x[idx] = __expf(x[idx] - m) * inv;
    }
}

// ---------------------------------------------------------------------------
// Orchestration:
//   emb0 = latent @ Wl^T + bl
//   S    = softmax(emb0 @ Wu^T + bu, axis=-1); store S^T per batch
//   Dm   = input @ WA^T + bA
//   A    = softmax(Dm @ WV^T + bV, axis=-2)      (over T_kv)
//   ov   = latent @ Wo^T + bo
//   M[b] = S[b]^T @ ov[b]                        ([1024,2048]x[2048,1024])
//   o[b] = A[b] @ M[b]                           ([2048,1024]x[1024,1024])
// ---------------------------------------------------------------------------
extern "C" void kernel_launch(void* const* d_in, const int* in_sizes, int n_in,
                              void* d_out, int out_size)
{
    const float* latent = (const float*)d_in[0];
    const float* input  = (const float*)d_in[1];
    const float* Wl = (const float*)d_in[2];
    const float* bl = (const float*)d_in[3];
    const float* Wu = (const float*)d_in[4];
    const float* bu = (const float*)d_in[5];
    const float* WA = (const float*)d_in[6];
    const float* bA = (const float*)d_in[7];
    const float* WV = (const float*)d_in[8];
    const float* bV = (const float*)d_in[9];
    const float* Wo = (const float*)d_in[10];
    const float* bo = (const float*)d_in[11];
    float* out = (float*)d_out;

    float *buf1, *buf2, *st, *mm;
    cudaGetSymbolAddress((void**)&buf1, g_buf1);
    cudaGetSymbolAddress((void**)&buf2, g_buf2);
    cudaGetSymbolAddress((void**)&st,   g_ST);
    cudaGetSymbolAddress((void**)&mm,   g_M);

    const dim3 blk(256);
    const dim3 gProj(D_MODEL / 128, MQ / 128, 1);      // (8, 64)

    // G1: emb0 = latent @ Wl^T + bl  -> buf1
    sgemm_kernel<true, true><<<gProj, blk>>>(latent, Wl, bl, buf1,
                                             MQ, D_MODEL, D_MODEL, 0, 0, 0);
    // G2: u_logits = emb0 @ Wu^T + bu -> buf2
    sgemm_kernel<true, true><<<gProj, blk>>>(buf1, Wu, bu, buf2,
                                             MQ, D_MODEL, D_MODEL, 0, 0, 0);
    // S^T per batch -> st
    row_softmax_T_kernel<<<MQ, blk>>>(buf2, st);

    // G3: Dm = input @ WA^T + bA -> buf1
    sgemm_kernel<true, true><<<gProj, blk>>>(input, WA, bA, buf1,
                                             MQ, D_MODEL, D_MODEL, 0, 0, 0);
    // G4: V_logits = Dm @ WV^T + bV -> buf2
    sgemm_kernel<true, true><<<gProj, blk>>>(buf1, WV, bV, buf2,
                                             MQ, D_MODEL, D_MODEL, 0, 0, 0);
    // A = col_softmax(V_logits) in place (buf2)
    col_softmax_kernel<<<dim3(D_MODEL / 32, NB), blk>>>(buf2);

    // G5: ov = latent @ Wo^T + bo -> buf1
    sgemm_kernel<true, true><<<gProj, blk>>>(latent, Wo, bo, buf1,
                                             MQ, D_MODEL, D_MODEL, 0, 0, 0);

    // G6: M[b] = ST[b] @ ov[b]   [1024,2048]x[2048,1024] -> mm
    sgemm_kernel<false, false><<<dim3(D_MODEL / 128, D_MODEL / 128, NB), blk>>>(
        st, buf1, nullptr, mm,
        D_MODEL, D_MODEL, TQ,
        (long)D_MODEL * TQ, (long)TQ * D_MODEL, (long)D_MODEL * D_MODEL);

    // G7: o[b] = A[b] @ M[b]     [2048,1024]x[1024,1024] -> out
    sgemm_kernel<false, false><<<dim3(D_MODEL / 128, TKV / 128, NB), blk>>>(
        buf2, mm, nullptr, out,
        TKV, D_MODEL, D_MODEL,
        (long)TKV * D_MODEL, (long)D_MODEL * D_MODEL, (long)TKV * D_MODEL);
}

// round 2
// speedup vs baseline: 2.8289x; 2.8289x over previous
#include <cuda_runtime.h>
#include <cstdint>

#define D_MODEL 1024
#define NB 4
#define TQ 2048
#define TKV 2048
#define MQ (NB * TQ)

// Scratch (static device globals; no runtime allocation allowed)
__device__ float g_buf1[MQ * D_MODEL];                 // 32 MB
__device__ float g_buf2[MQ * D_MODEL];                 // 32 MB
__device__ float g_ST[NB * D_MODEL * TQ];              // 32 MB  (S transposed per batch)
__device__ float g_M[NB * D_MODEL * D_MODEL];          // 16 MB  (l @ ov per batch)

// ---------------------------------------------------------------------------
// PTX helpers
// ---------------------------------------------------------------------------
__device__ __forceinline__ void cp_async16(uint32_t smem, const void* g) {
    asm volatile("cp.async.cg.shared.global [%0], [%1], 16;\n" :: "r"(smem), "l"(g));
}
__device__ __forceinline__ void cp_commit() {
    asm volatile("cp.async.commit_group;\n" ::: "memory");
}
template <int N>
__device__ __forceinline__ void cp_wait() {
    asm volatile("cp.async.wait_group %0;\n" :: "n"(N) : "memory");
}
__device__ __forceinline__ uint32_t f2tf(float x) {
    uint32_t r;
    asm("cvt.rna.tf32.f32 %0, %1;\n" : "=r"(r) : "f"(x));
    return r;
}
__device__ __forceinline__ void mma_tf32(float* c, const uint32_t* a, const uint32_t* b) {
    asm volatile(
        "mma.sync.aligned.m16n8k8.row.col.f32.tf32.tf32.f32 "
        "{%0,%1,%2,%3}, {%4,%5,%6,%7}, {%8,%9}, {%0,%1,%2,%3};\n"
        : "+f"(c[0]), "+f"(c[1]), "+f"(c[2]), "+f"(c[3])
        : "r"(a[0]), "r"(a[1]), "r"(a[2]), "r"(a[3]), "r"(b[0]), "r"(b[1]));
}

// ---------------------------------------------------------------------------
// TF32 tensor-core GEMM: C = A * op(B) (+ bias)
//   BNT=true : B stored [N,K] row-major (C = A @ B^T)  -> projections
//   BNT=false: B stored [K,N] row-major (C = A @ B)    -> combine GEMMs
// Block tile 128x128x16, 256 threads (8 warps: 4 in M x 2 in N).
// Warp tile 32x64 -> 2 m-subtiles x 8 n-subtiles of m16n8k8.
// 2-stage cp.async pipeline. M,N multiples of 128; K multiple of 16.
// ---------------------------------------------------------------------------
#define AS_STRIDE 20      // 16 + 4 pad (conflict-free for [m][k] frag reads)
#define BS2_STRIDE 136    // 128 + 8 pad (conflict-free for [k][n] frag reads)

template <bool BNT, bool HASBIAS>
__global__ void __launch_bounds__(256) tgemm_kernel(
    const float* __restrict__ A, const float* __restrict__ B,
    const float* __restrict__ bias, float* __restrict__ C,
    int M, int N, int K, long sA, long sB, long sC)
{
    A += (long)blockIdx.z * sA;
    B += (long)blockIdx.z * sB;
    C += (long)blockIdx.z * sC;

    __shared__ float As[2][128 * AS_STRIDE];
    __shared__ float Bs[2][BNT ? 128 * AS_STRIDE : 16 * BS2_STRIDE];

    const int tid  = threadIdx.x;
    const int lane = tid & 31;
    const int warp = tid >> 5;
    const int wm   = warp & 3;      // 4 warps along M
    const int wn   = warp >> 2;     // 2 warps along N

    const int bm = blockIdx.y * 128;
    const int bn = blockIdx.x * 128;

    const uint32_t sAs0 = (uint32_t)__cvta_generic_to_shared(&As[0][0]);
    const uint32_t sAs1 = (uint32_t)__cvta_generic_to_shared(&As[1][0]);
    const uint32_t sBs0 = (uint32_t)__cvta_generic_to_shared(&Bs[0][0]);
    const uint32_t sBs1 = (uint32_t)__cvta_generic_to_shared(&Bs[1][0]);

    // Load-index precompute (each thread copies 2x16B for A and 2x16B for B)
    const int c0 = tid, c1 = tid + 256;                 // chunk ids 0..511
    const int aRow0 = c0 >> 2, aKq0 = (c0 & 3) * 4;
    const int aRow1 = c1 >> 2, aKq1 = (c1 & 3) * 4;
    // NN B: chunk -> (krow, n4)
    const int bKr0 = c0 >> 5, bN40 = (c0 & 31) * 4;
    const int bKr1 = c1 >> 5, bN41 = (c1 & 31) * 4;

    auto issue = [&](int stage, int k0) {
        const uint32_t sa = stage ? sAs1 : sAs0;
        const uint32_t sb = stage ? sBs1 : sBs0;
        cp_async16(sa + (aRow0 * AS_STRIDE + aKq0) * 4,
                   A + (long)(bm + aRow0) * K + k0 + aKq0);
        cp_async16(sa + (aRow1 * AS_STRIDE + aKq1) * 4,
                   A + (long)(bm + aRow1) * K + k0 + aKq1);
        if (BNT) {
            cp_async16(sb + (aRow0 * AS_STRIDE + aKq0) * 4,
                       B + (long)(bn + aRow0) * K + k0 + aKq0);
            cp_async16(sb + (aRow1 * AS_STRIDE + aKq1) * 4,
                       B + (long)(bn + aRow1) * K + k0 + aKq1);
        } else {
            cp_async16(sb + (bKr0 * BS2_STRIDE + bN40) * 4,
                       B + (long)(k0 + bKr0) * N + bn + bN40);
            cp_async16(sb + (bKr1 * BS2_STRIDE + bN41) * 4,
                       B + (long)(k0 + bKr1) * N + bn + bN41);
        }
        cp_commit();
    };

    float acc[2][8][4];
#pragma unroll
    for (int mt = 0; mt < 2; mt++)
#pragma unroll
        for (int nt = 0; nt < 8; nt++)
#pragma unroll
            for (int r = 0; r < 4; r++) acc[mt][nt][r] = 0.0f;

    const int KT = K >> 4;          // BK = 16
    issue(0, 0);

    // Per-thread fragment base offsets
    const int aFragBase = (wm * 32 + (lane >> 2)) * AS_STRIDE + (lane & 3);
    const int bFragBaseNT = (wn * 64 + (lane >> 2)) * AS_STRIDE + (lane & 3);
    const int bFragBaseNN = (lane & 3) * BS2_STRIDE + wn * 64 + (lane >> 2);

    for (int kt = 0; kt < KT; kt++) {
        if (kt + 1 < KT) issue((kt + 1) & 1, (kt + 1) << 4);
        if (kt + 1 < KT) cp_wait<1>(); else cp_wait<0>();
        __syncthreads();

        const float* as = As[kt & 1];
        const float* bs = Bs[kt & 1];

#pragma unroll
        for (int kk = 0; kk < 16; kk += 8) {
            uint32_t af[2][4];
#pragma unroll
            for (int mt = 0; mt < 2; mt++) {
                const int base = aFragBase + mt * (16 * AS_STRIDE) + kk;
                af[mt][0] = f2tf(as[base]);
                af[mt][1] = f2tf(as[base + 8 * AS_STRIDE]);
                af[mt][2] = f2tf(as[base + 4]);
                af[mt][3] = f2tf(as[base + 8 * AS_STRIDE + 4]);
            }
            uint32_t bf[8][2];
#pragma unroll
            for (int nt = 0; nt < 8; nt++) {
                if (BNT) {
                    const int base = bFragBaseNT + nt * (8 * AS_STRIDE) + kk;
                    bf[nt][0] = f2tf(bs[base]);
                    bf[nt][1] = f2tf(bs[base + 4]);
                } else {
                    const int base = bFragBaseNN + kk * BS2_STRIDE + nt * 8;
                    bf[nt][0] = f2tf(bs[base]);
                    bf[nt][1] = f2tf(bs[base + 4 * BS2_STRIDE]);
                }
            }
#pragma unroll
            for (int mt = 0; mt < 2; mt++)
#pragma unroll
                for (int nt = 0; nt < 8; nt++)
                    mma_tf32(acc[mt][nt], af[mt], bf[nt]);
        }
        __syncthreads();
    }

    // Epilogue
#pragma unroll
    for (int mt = 0; mt < 2; mt++) {
        const int row0 = bm + wm * 32 + mt * 16 + (lane >> 2);
#pragma unroll
        for (int nt = 0; nt < 8; nt++) {
            const int col = bn + wn * 64 + nt * 8 + (lane & 3) * 2;
            float bx = 0.f, by = 0.f;
            if (HASBIAS) {
                const float2 bb = *(const float2*)(bias + col);
                bx = bb.x; by = bb.y;
            }
            float2 v0 = make_float2(acc[mt][nt][0] + bx, acc[mt][nt][1] + by);
            float2 v1 = make_float2(acc[mt][nt][2] + bx, acc[mt][nt][3] + by);
            *(float2*)(C + (long)row0 * N + col)       = v0;
            *(float2*)(C + (long)(row0 + 8) * N + col) = v1;
        }
    }
}

// ---------------------------------------------------------------------------
// Row softmax over last dim (D_MODEL=1024) with transposed store:
//   ST[b][e][q] = softmax_e(X[b*TQ+q][:])[e]
// ---------------------------------------------------------------------------
__global__ void __launch_bounds__(256) row_softmax_T_kernel(
    const float* __restrict__ X, float* __restrict__ ST)
{
    const int row = blockIdx.x;
    const int b = row >> 11;
    const int q = row & (TQ - 1);
    const int t = threadIdx.x;

    __shared__ float red[256];

    const float* x = X + (long)row * D_MODEL;
    float v[4];
    float m = -1e30f;
#pragma unroll
    for (int i = 0; i < 4; i++) {
        v[i] = x[t + i * 256];
        m = fmaxf(m, v[i]);
    }
    red[t] = m;
    __syncthreads();
    for (int s = 128; s > 0; s >>= 1) {
        if (t < s) red[t] = fmaxf(red[t], red[t + s]);
        __syncthreads();
    }
    m = red[0];
    __syncthreads();

    float sum = 0.0f;
#pragma unroll
    for (int i = 0; i < 4; i++) {
        v[i] = __expf(v[i] - m);
        sum += v[i];
    }
    red[t] = sum;
    __syncthreads();
    for (int s = 128; s > 0; s >>= 1) {
        if (t < s) red[t] += red[t + s];
        __syncthreads();
    }
    const float inv = 1.0f / red[0];

    float* dst = ST + (long)b * D_MODEL * TQ + q;
#pragma unroll
    for (int i = 0; i < 4; i++) {
        const int e = t + i * 256;
        dst[(long)e * TQ] = v[i] * inv;
    }
}

// ---------------------------------------------------------------------------
// Column softmax over T_kv (axis=-2), in place.
// ---------------------------------------------------------------------------
__global__ void __launch_bounds__(256) col_softmax_kernel(float* __restrict__ X)
{
    const int b = blockIdx.y;
    const int c = threadIdx.x & 31;
    const int s = threadIdx.x >> 5;
    const int e = blockIdx.x * 32 + c;

    float* x = X + (long)b * TKV * D_MODEL + e;
    __shared__ float red[8][32];

    float m = -1e30f;
    for (int k = s; k < TKV; k += 8) m = fmaxf(m, x[(long)k * D_MODEL]);
    red[s][c] = m;
    __syncthreads();
    if (s == 0) {
        float mm = red[0][c];
#pragma unroll
        for (int i = 1; i < 8; i++) mm = fmaxf(mm, red[i][c]);
        red[0][c] = mm;
    }
    __syncthreads();
    m = red[0][c];
    __syncthreads();

    float sum = 0.0f;
    for (int k = s; k < TKV; k += 8) sum += __expf(x[(long)k * D_MODEL] - m);
    red[s][c] = sum;
    __syncthreads();
    if (s == 0) {
        float ss = red[0][c];
#pragma unroll
        for (int i = 1; i < 8; i++) ss += red[i][c];
        red[0][c] = ss;
    }
    __syncthreads();
    const float inv = 1.0f / red[0][c];

    for (int k = s; k < TKV; k += 8) {
        const long idx = (long)k * D_MODEL;
        x[idx] = __expf(x[idx] - m) * inv;
    }
}

// ---------------------------------------------------------------------------
// Orchestration (same algebra as round 1: o = A @ (S^T @ ov))
// ---------------------------------------------------------------------------
extern "C" void kernel_launch(void* const* d_in, const int* in_sizes, int n_in,
                              void* d_out, int out_size)
{
    const float* latent = (const float*)d_in[0];
    const float* input  = (const float*)d_in[1];
    const float* Wl = (const float*)d_in[2];
    const float* bl = (const float*)d_in[3];
    const float* Wu = (const float*)d_in[4];
    const float* bu = (const float*)d_in[5];
    const float* WA = (const float*)d_in[6];
    const float* bA = (const float*)d_in[7];
    const float* WV = (const float*)d_in[8];
    const float* bV = (const float*)d_in[9];
    const float* Wo = (const float*)d_in[10];
    const float* bo = (const float*)d_in[11];
    float* out = (float*)d_out;

    float *buf1, *buf2, *st, *mm;
    cudaGetSymbolAddress((void**)&buf1, g_buf1);
    cudaGetSymbolAddress((void**)&buf2, g_buf2);
    cudaGetSymbolAddress((void**)&st,   g_ST);
    cudaGetSymbolAddress((void**)&mm,   g_M);

    const dim3 blk(256);
    const dim3 gProj(D_MODEL / 128, MQ / 128, 1);      // (8, 64)

    // G1: emb0 = latent @ Wl^T + bl  -> buf1
    tgemm_kernel<true, true><<<gProj, blk>>>(latent, Wl, bl, buf1,
                                             MQ, D_MODEL, D_MODEL, 0, 0, 0);
    // G2: u_logits = emb0 @ Wu^T + bu -> buf2
    tgemm_kernel<true, true><<<gProj, blk>>>(buf1, Wu, bu, buf2,
                                             MQ, D_MODEL, D_MODEL, 0, 0, 0);
    // S^T per batch -> st
    row_softmax_T_kernel<<<MQ, blk>>>(buf2, st);

    // G3: Dm = input @ WA^T + bA -> buf1
    tgemm_kernel<true, true><<<gProj, blk>>>(input, WA, bA, buf1,
                                             MQ, D_MODEL, D_MODEL, 0, 0, 0);
    // G4: V_logits = Dm @ WV^T + bV -> buf2
    tgemm_kernel<true, true><<<gProj, blk>>>(buf1, WV, bV, buf2,
                                             MQ, D_MODEL, D_MODEL, 0, 0, 0);
    // A = col_softmax(V_logits) in place (buf2)
    col_softmax_kernel<<<dim3(D_MODEL / 32, NB), blk>>>(buf2);

    // G5: ov = latent @ Wo^T + bo -> buf1
    tgemm_kernel<true, true><<<gProj, blk>>>(latent, Wo, bo, buf1,
                                             MQ, D_MODEL, D_MODEL, 0, 0, 0);

    // G6: M[b] = ST[b] @ ov[b]   [1024,2048]x[2048,1024] -> mm
    tgemm_kernel<false, false><<<dim3(D_MODEL / 128, D_MODEL / 128, NB), blk>>>(
        st, buf1, nullptr, mm,
        D_MODEL, D_MODEL, TQ,
        (long)D_MODEL * TQ, (long)TQ * D_MODEL, (long)D_MODEL * D_MODEL);

    // G7: o[b] = A[b] @ M[b]     [2048,1024]x[1024,1024] -> out
    tgemm_kernel<false, false><<<dim3(D_MODEL / 128, TKV / 128, NB), blk>>>(
        buf2, mm, nullptr, out,
        TKV, D_MODEL, D_MODEL,
        (long)TKV * D_MODEL, (long)D_MODEL * D_MODEL, (long)TKV * D_MODEL);
}

// round 6
// speedup vs baseline: 4.8083x; 1.6997x over previous
#include <cuda_runtime.h>
#include <cuda_fp16.h>
#include <cstdint>

#define D_MODEL 1024
#define NB 4
#define TQ 2048
#define TKV 2048
#define MQ (NB * TQ)

// ---------------------------------------------------------------------------
// Static scratch (no runtime allocation allowed)
// ---------------------------------------------------------------------------
__device__ float  g_buf [MQ * D_MODEL];            // 32 MB f32 logits (reused)
__device__ __half g_lat16 [MQ * D_MODEL];          // 16 MB
__device__ __half g_inp16 [MQ * D_MODEL];          // 16 MB
__device__ __half g_W16   [5 * D_MODEL * D_MODEL]; // 10 MB (Wl,Wu,WA,WV,Wo)
__device__ __half g_emb16 [MQ * D_MODEL];          // 16 MB
__device__ __half g_Dm16  [MQ * D_MODEL];          // 16 MB
__device__ __half g_A16   [MQ * D_MODEL];          // 16 MB
__device__ __half g_ST16  [NB * D_MODEL * TQ];     // 16 MB  S^T [b][d][q]
__device__ __half g_ovT16 [NB * D_MODEL * TQ];     // 16 MB  ov^T[b][e][q]
__device__ __half g_MT16  [NB * D_MODEL * D_MODEL];//  8 MB  P^T [b][e][d]

// ---------------------------------------------------------------------------
// PTX helpers
// ---------------------------------------------------------------------------
__device__ __forceinline__ uint32_t smem_u32(const void* p) {
    uint32_t a;
    asm("{ .reg .u64 t; cvta.to.shared.u64 t, %1; cvt.u32.u64 %0, t; }"
        : "=r"(a) : "l"(p));
    return a;
}
__device__ __forceinline__ void cp_async16(uint32_t smem, const void* g) {
    asm volatile("cp.async.cg.shared.global [%0], [%1], 16;\n" :: "r"(smem), "l"(g));
}
__device__ __forceinline__ void cp_commit() {
    asm volatile("cp.async.commit_group;\n" ::: "memory");
}
template <int N>
__device__ __forceinline__ void cp_wait() {
    asm volatile("cp.async.wait_group %0;\n" :: "n"(N) : "memory");
}
#define LDSM_X4(r, a)                                                         \
    asm volatile("ldmatrix.sync.aligned.m8n8.x4.shared.b16 {%0,%1,%2,%3}, [%4];" \
        : "=r"((r)[0]), "=r"((r)[1]), "=r"((r)[2]), "=r"((r)[3]) : "r"(a))

__device__ __forceinline__ void mma16816(float* c, const uint32_t* a,
                                         uint32_t b0, uint32_t b1) {
    asm volatile(
        "mma.sync.aligned.m16n8k16.row.col.f32.f16.f16.f32 "
        "{%0,%1,%2,%3}, {%4,%5,%6,%7}, {%8,%9}, {%0,%1,%2,%3};\n"
        : "+f"(c[0]), "+f"(c[1]), "+f"(c[2]), "+f"(c[3])
        : "r"(a[0]), "r"(a[1]), "r"(a[2]), "r"(a[3]), "r"(b0), "r"(b1));
}

// ---------------------------------------------------------------------------
// FP16 NT-GEMM: C[M,N] = A[M,K] @ B[N,K]^T (+ bias); A,B K-major __half.
// Block tile 128x128x32(halves). 256 threads, 8 warps = 2(M) x 4(N),
// warp tile 64x32 = 4x4 m16n8k16. 3-stage cp.async pipeline, ldmatrix.x4.
// SMEM row stride: 40 halves (80B) -> conflict-free ldmatrix.
// BIAS: 0 none, 1 bias[col], 2 bias[row].  F16OUT: 1 -> Ch, 0 -> Cf.
// ---------------------------------------------------------------------------
#define BKH 32                    // K halves per tile
#define ROWB 80                   // bytes per smem row (40 halves)
#define OPBYTES (128 * ROWB)      // 10240 per operand tile
#define STAGEB (2 * OPBYTES)      // 20480 per stage
#define SMEM_BYTES (3 * STAGEB)   // 61440

template <int BIAS, int F16OUT>
__global__ void __launch_bounds__(256, 2) hgemm(
    const __half* __restrict__ A, const __half* __restrict__ B,
    const float* __restrict__ bias, float* __restrict__ Cf,
    __half* __restrict__ Ch,
    int M, int N, int K, long sA, long sB, long sC)
{
    A += (long)blockIdx.z * sA;
    B += (long)blockIdx.z * sB;

    extern __shared__ char smem[];
    const uint32_t sbase = smem_u32(smem);

    const int tid  = threadIdx.x;
    const int lane = tid & 31;
    const int warp = tid >> 5;
    const int wm   = warp & 1;        // 2 warps along M (64 rows each)
    const int wn   = warp >> 1;       // 4 warps along N (32 cols each)

    const int bm = blockIdx.y * 128;
    const int bn = blockIdx.x * 128;

    // loader: per stage, A: 512 16B chunks, B: 512. Each thread: 2+2.
    const int r0 = tid >> 2, kc0 = (tid & 3);
    const int r1 = (tid + 256) >> 2, kc1 = ((tid + 256) & 3);

    auto issue = [&](int stage, int k0) {   // k0 in halves
        const __half* Ab = A + (long)bm * K + k0;
        const __half* Bb = B + (long)bn * K + k0;
        const uint32_t sa = sbase + stage * STAGEB;
        const uint32_t sb = sa + OPBYTES;
        cp_async16(sa + r0 * ROWB + kc0 * 16, Ab + (long)r0 * K + kc0 * 8);
        cp_async16(sa + r1 * ROWB + kc1 * 16, Ab + (long)r1 * K + kc1 * 8);
        cp_async16(sb + r0 * ROWB + kc0 * 16, Bb + (long)r0 * K + kc0 * 8);
        cp_async16(sb + r1 * ROWB + kc1 * 16, Bb + (long)r1 * K + kc1 * 8);
        cp_commit();
    };

    float acc[4][4][4];
#pragma unroll
    for (int i = 0; i < 4; i++)
#pragma unroll
        for (int j = 0; j < 4; j++)
#pragma unroll
            for (int r = 0; r < 4; r++) acc[i][j][r] = 0.0f;

    const int T = K / BKH;
    issue(0, 0);
    issue(1, BKH);

    // Per-lane ldmatrix address components
    const int aRow = wm * 64 + (lane & 15);          // + mt*16
    const int aKB  = (lane >> 4) * 16;               // + kk*32
    const int bRow = wn * 32 + ((lane >> 4) & 1) * 8 + (lane & 7);  // + np*16
    const int bKB  = ((lane >> 3) & 1) * 16;         // + kk*32

    for (int t = 0; t < T; t++) {
        if (t + 2 < T) { issue((t + 2) % 3, (t + 2) * BKH); cp_wait<2>(); }
        else           { cp_wait<0>(); }
        __syncthreads();

        const uint32_t sa = sbase + (t % 3) * STAGEB;
        const uint32_t sb = sa + OPBYTES;

#pragma unroll
        for (int kk = 0; kk < 2; kk++) {             // two k16 halves
            uint32_t af[4][4];
#pragma unroll
            for (int mt = 0; mt < 4; mt++)
                LDSM_X4(af[mt], sa + (aRow + mt * 16) * ROWB + kk * 32 + aKB);
            uint32_t bf[2][4];
#pragma unroll
            for (int np = 0; np < 2; np++)
                LDSM_X4(bf[np], sb + (bRow + np * 16) * ROWB + kk * 32 + bKB);
#pragma unroll
            for (int mt = 0; mt < 4; mt++)
#pragma unroll
                for (int nt = 0; nt < 4; nt++)
                    mma16816(acc[mt][nt], af[mt],
                             bf[nt >> 1][(nt & 1) * 2],
                             bf[nt >> 1][(nt & 1) * 2 + 1]);
        }
        __syncthreads();
    }

    // Epilogue
#pragma unroll
    for (int mt = 0; mt < 4; mt++) {
        const int row0 = bm + wm * 64 + mt * 16 + (lane >> 2);
        const float rb0 = (BIAS == 2) ? bias[row0] : 0.0f;
        const float rb1 = (BIAS == 2) ? bias[row0 + 8] : 0.0f;
#pragma unroll
        for (int nt = 0; nt < 4; nt++) {
            const int col = bn + wn * 32 + nt * 8 + (lane & 3) * 2;
            float bx = 0.f, by = 0.f;
            if (BIAS == 1) {
                const float2 bb = *(const float2*)(bias + col);
                bx = bb.x; by = bb.y;
            }
            const float c0 = acc[mt][nt][0] + bx + rb0;
            const float c1 = acc[mt][nt][1] + by + rb0;
            const float c2 = acc[mt][nt][2] + bx + rb1;
            const float c3 = acc[mt][nt][3] + by + rb1;
            if (F16OUT) {
                __half* p = Ch + (long)blockIdx.z * sC + (long)row0 * N + col;
                *(__half2*)p                 = __floats2half2_rn(c0, c1);
                *(__half2*)(p + (long)8 * N) = __floats2half2_rn(c2, c3);
            } else {
                float* p = Cf + (long)blockIdx.z * sC + (long)row0 * N + col;
                *(float2*)p                 = make_float2(c0, c1);
                *(float2*)(p + (long)8 * N) = make_float2(c2, c3);
            }
        }
    }
}

// ---------------------------------------------------------------------------
// f32 -> f16 conversion (vectorized)
// ---------------------------------------------------------------------------
__global__ void __launch_bounds__(256) f32to16_kernel(
    const float* __restrict__ x, __half* __restrict__ y, int n)
{
    const int i = (blockIdx.x * 256 + threadIdx.x) * 4;
    if (i < n) {
        const float4 v = *(const float4*)(x + i);
        *(__half2*)(y + i)     = __floats2half2_rn(v.x, v.y);
        *(__half2*)(y + i + 2) = __floats2half2_rn(v.z, v.w);
    }
}

// ---------------------------------------------------------------------------
// Row softmax over last dim (1024), f32 in, transposed f16 store ST[b][d][q]
// ---------------------------------------------------------------------------
__global__ void __launch_bounds__(256) row_softmax_T_kernel(
    const float* __restrict__ X, __half* __restrict__ ST)
{
    const int row = blockIdx.x;
    const int b = row >> 11;
    const int q = row & (TQ - 1);
    const int t = threadIdx.x;

    __shared__ float red[256];

    const float* x = X + (long)row * D_MODEL;
    float v[4];
    float m = -1e30f;
#pragma unroll
    for (int i = 0; i < 4; i++) {
        v[i] = x[t + i * 256];
        m = fmaxf(m, v[i]);
    }
    red[t] = m;
    __syncthreads();
    for (int s = 128; s > 0; s >>= 1) {
        if (t < s) red[t] = fmaxf(red[t], red[t + s]);
        __syncthreads();
    }
    m = red[0];
    __syncthreads();

    float sum = 0.0f;
#pragma unroll
    for (int i = 0; i < 4; i++) {
        v[i] = __expf(v[i] - m);
        sum += v[i];
    }
    red[t] = sum;
    __syncthreads();
    for (int s = 128; s > 0; s >>= 1) {
        if (t < s) red[t] += red[t + s];
        __syncthreads();
    }
    const float inv = 1.0f / red[0];

    __half* dst = ST + (long)b * D_MODEL * TQ + q;
#pragma unroll
    for (int i = 0; i < 4; i++) {
        const int e = t + i * 256;
        dst[(long)e * TQ] = __float2half(v[i] * inv);
    }
}

// ---------------------------------------------------------------------------
// Column softmax over T_kv (axis=-2): f32 in, f16 out (same [k][d] layout)
// ---------------------------------------------------------------------------
__global__ void __launch_bounds__(256) col_softmax_kernel(
    const float* __restrict__ X, __half* __restrict__ Y)
{
    const int b = blockIdx.y;
    const int c = threadIdx.x & 31;
    const int s = threadIdx.x >> 5;
    const int e = blockIdx.x * 32 + c;

    const float* x = X + (long)b * TKV * D_MODEL + e;
    __half* y = Y + (long)b * TKV * D_MODEL + e;
    __shared__ float red[8][32];

    float m = -1e30f;
    for (int k = s; k < TKV; k += 8) m = fmaxf(m, x[(long)k * D_MODEL]);
    red[s][c] = m;
    __syncthreads();
    if (s == 0) {
        float mm = red[0][c];
#pragma unroll
        for (int i = 1; i < 8; i++) mm = fmaxf(mm, red[i][c]);
        red[0][c] = mm;
    }
    __syncthreads();
    m = red[0][c];
    __syncthreads();

    float sum = 0.0f;
    for (int k = s; k < TKV; k += 8) sum += __expf(x[(long)k * D_MODEL] - m);
    red[s][c] = sum;
    __syncthreads();
    if (s == 0) {
        float ss = red[0][c];
#pragma unroll
        for (int i = 1; i < 8; i++) ss += red[i][c];
        red[0][c] = ss;
    }
    __syncthreads();
    const float inv = 1.0f / red[0][c];

    for (int k = s; k < TKV; k += 8) {
        const long idx = (long)k * D_MODEL;
        y[idx] = __float2half(__expf(x[idx] - m) * inv);
    }
}

// ---------------------------------------------------------------------------
// Orchestration. All GEMMs NT (A[M,K] @ B[N,K]^T), K-major f16 operands:
//   emb0  = NT(lat, Wl)+bl        S^T = rsmT(NT(emb0,Wu)+bu)
//   Dm    = NT(inp, WA)+bA        A   = csm(NT(Dm,WV)+bV)
//   ovT_b = NT(Wo, lat_b)+bo(row)           [e,q]
//   PT_b  = NT(ovT_b, ST_b)                 [e,d]
//   o_b   = NT(A_b, PT_b)                   [k,e]
// ---------------------------------------------------------------------------
extern "C" void kernel_launch(void* const* d_in, const int* in_sizes, int n_in,
                              void* d_out, int out_size)
{
    const float* latent = (const float*)d_in[0];
    const float* input  = (const float*)d_in[1];
    const float* Wl = (const float*)d_in[2];
    const float* bl = (const float*)d_in[3];
    const float* Wu = (const float*)d_in[4];
    const float* bu = (const float*)d_in[5];
    const float* WA = (const float*)d_in[6];
    const float* bA = (const float*)d_in[7];
    const float* WV = (const float*)d_in[8];
    const float* bV = (const float*)d_in[9];
    const float* Wo = (const float*)d_in[10];
    const float* bo = (const float*)d_in[11];
    float* out = (float*)d_out;

    float* buf;
    __half *lat16, *inp16, *w16, *emb16, *dm16, *a16, *st16, *ovt16, *mt16;
    cudaGetSymbolAddress((void**)&buf,   g_buf);
    cudaGetSymbolAddress((void**)&lat16, g_lat16);
    cudaGetSymbolAddress((void**)&inp16, g_inp16);
    cudaGetSymbolAddress((void**)&w16,   g_W16);
    cudaGetSymbolAddress((void**)&emb16, g_emb16);
    cudaGetSymbolAddress((void**)&dm16,  g_Dm16);
    cudaGetSymbolAddress((void**)&a16,   g_A16);
    cudaGetSymbolAddress((void**)&st16,  g_ST16);
    cudaGetSymbolAddress((void**)&ovt16, g_ovT16);
    cudaGetSymbolAddress((void**)&mt16,  g_MT16);

    __half* Wl16 = w16 + 0L * D_MODEL * D_MODEL;
    __half* Wu16 = w16 + 1L * D_MODEL * D_MODEL;
    __half* WA16 = w16 + 2L * D_MODEL * D_MODEL;
    __half* WV16 = w16 + 3L * D_MODEL * D_MODEL;
    __half* Wo16 = w16 + 4L * D_MODEL * D_MODEL;

    cudaFuncSetAttribute(hgemm<1,1>, cudaFuncAttributeMaxDynamicSharedMemorySize, SMEM_BYTES);
    cudaFuncSetAttribute(hgemm<1,0>, cudaFuncAttributeMaxDynamicSharedMemorySize, SMEM_BYTES);
    cudaFuncSetAttribute(hgemm<2,1>, cudaFuncAttributeMaxDynamicSharedMemorySize, SMEM_BYTES);
    cudaFuncSetAttribute(hgemm<0,1>, cudaFuncAttributeMaxDynamicSharedMemorySize, SMEM_BYTES);
    cudaFuncSetAttribute(hgemm<0,0>, cudaFuncAttributeMaxDynamicSharedMemorySize, SMEM_BYTES);

    const dim3 blk(256);
    const int NACT = MQ * D_MODEL;          // 8M
    const int NW   = D_MODEL * D_MODEL;     // 1M

    // One-time rounding of primary inputs to f16
    f32to16_kernel<<<NACT / 1024, blk>>>(latent, lat16, NACT);
    f32to16_kernel<<<NACT / 1024, blk>>>(input,  inp16, NACT);
    f32to16_kernel<<<NW / 1024, blk>>>(Wl, Wl16, NW);
    f32to16_kernel<<<NW / 1024, blk>>>(Wu, Wu16, NW);
    f32to16_kernel<<<NW / 1024, blk>>>(WA, WA16, NW);
    f32to16_kernel<<<NW / 1024, blk>>>(WV, WV16, NW);
    f32to16_kernel<<<NW / 1024, blk>>>(Wo, Wo16, NW);

    const dim3 gProj(D_MODEL / 128, MQ / 128, 1);       // (8, 64)

    // G1: emb0 (f16)
    hgemm<1,1><<<gProj, blk, SMEM_BYTES>>>(lat16, Wl16, bl, nullptr, emb16,
                                           MQ, D_MODEL, D_MODEL, 0, 0, 0);
    // G2: u_logits (f32) ; S^T (f16)
    hgemm<1,0><<<gProj, blk, SMEM_BYTES>>>(emb16, Wu16, bu, buf, nullptr,
                                           MQ, D_MODEL, D_MODEL, 0, 0, 0);
    row_softmax_T_kernel<<<MQ, blk>>>(buf, st16);

    // G3: Dm (f16)
    hgemm<1,1><<<gProj, blk, SMEM_BYTES>>>(inp16, WA16, bA, nullptr, dm16,
                                           MQ, D_MODEL, D_MODEL, 0, 0, 0);
    // G4: V_logits (f32) ; A (f16)
    hgemm<1,0><<<gProj, blk, SMEM_BYTES>>>(dm16, WV16, bV, buf, nullptr,
                                           MQ, D_MODEL, D_MODEL, 0, 0, 0);
    col_softmax_kernel<<<dim3(D_MODEL / 32, NB), blk>>>(buf, a16);

    // G5: ovT[b] = Wo @ lat_b^T + bo(row)    M=1024(e), N=2048(q), K=1024
    hgemm<2,1><<<dim3(TQ / 128, D_MODEL / 128, NB), blk, SMEM_BYTES>>>(
        Wo16, lat16, bo, nullptr, ovt16,
        D_MODEL, TQ, D_MODEL,
        0, (long)TQ * D_MODEL, (long)D_MODEL * TQ);

    // G6: PT[b] = ovT[b] @ ST[b]^T           M=1024(e), N=1024(d), K=2048
    hgemm<0,1><<<dim3(D_MODEL / 128, D_MODEL / 128, NB), blk, SMEM_BYTES>>>(
        ovt16, st16, nullptr, nullptr, mt16,
        D_MODEL, D_MODEL, TQ,
        (long)D_MODEL * TQ, (long)D_MODEL * TQ, (long)D_MODEL * D_MODEL);

    // G7: o[b] = A[b] @ PT[b]^T              M=2048(k), N=1024(e), K=1024
    hgemm<0,0><<<dim3(D_MODEL / 128, TKV / 128, NB), blk, SMEM_BYTES>>>(
        a16, mt16, nullptr, out, nullptr,
        TKV, D_MODEL, D_MODEL,
        (long)TKV * D_MODEL, (long)D_MODEL * D_MODEL, (long)TKV * D_MODEL);
}

// round 9
// speedup vs baseline: 5.2223x; 1.0861x over previous
#include <cuda_runtime.h>
#include <cuda_fp16.h>
#include <cstdint>

#define D_MODEL 1024
#define NB 4
#define TQ 2048
#define TKV 2048
#define MQ (NB * TQ)

// ---------------------------------------------------------------------------
// Static scratch (no runtime allocation allowed)
// ---------------------------------------------------------------------------
__device__ float  g_buf   [MQ * D_MODEL];           // 32 MB f32 logits (reused)
__device__ __half g_lat16 [MQ * D_MODEL];           // 16 MB
__device__ __half g_inp16 [MQ * D_MODEL];           // 16 MB
__device__ __half g_W16   [5 * D_MODEL * D_MODEL];  // Wu, WV, Wo, Wl^T, WA^T
__device__ __half g_Weff  [2 * D_MODEL * D_MODEL];  // Wu@Wl, WV@WA (fp16)
__device__ float  g_beff  [2 * D_MODEL];            // folded biases
__device__ __half g_A16   [MQ * D_MODEL];           // 16 MB
__device__ __half g_ST16  [NB * D_MODEL * TQ];      // 16 MB  S^T [b][d][q]
__device__ __half g_ovT16 [NB * D_MODEL * TQ];      // 16 MB  ov^T[b][e][q]
__device__ __half g_MT16  [NB * D_MODEL * D_MODEL]; //  8 MB  P^T [b][e][d]

// ---------------------------------------------------------------------------
// PTX helpers
// ---------------------------------------------------------------------------
__device__ __forceinline__ uint32_t smem_u32(const void* p) {
    uint32_t a;
    asm("{ .reg .u64 t; cvta.to.shared.u64 t, %1; cvt.u32.u64 %0, t; }"
        : "=r"(a) : "l"(p));
    return a;
}
__device__ __forceinline__ void cp_async16(uint32_t smem, const void* g) {
    asm volatile("cp.async.cg.shared.global [%0], [%1], 16;\n" :: "r"(smem), "l"(g));
}
__device__ __forceinline__ void cp_commit() {
    asm volatile("cp.async.commit_group;\n" ::: "memory");
}
template <int N>
__device__ __forceinline__ void cp_wait() {
    asm volatile("cp.async.wait_group %0;\n" :: "n"(N) : "memory");
}
#define LDSM_X4(r, a)                                                         \
    asm volatile("ldmatrix.sync.aligned.m8n8.x4.shared.b16 {%0,%1,%2,%3}, [%4];" \
        : "=r"((r)[0]), "=r"((r)[1]), "=r"((r)[2]), "=r"((r)[3]) : "r"(a))

__device__ __forceinline__ void mma16816(float* c, const uint32_t* a,
                                         uint32_t b0, uint32_t b1) {
    asm volatile(
        "mma.sync.aligned.m16n8k16.row.col.f32.f16.f16.f32 "
        "{%0,%1,%2,%3}, {%4,%5,%6,%7}, {%8,%9}, {%0,%1,%2,%3};\n"
        : "+f"(c[0]), "+f"(c[1]), "+f"(c[2]), "+f"(c[3])
        : "r"(a[0]), "r"(a[1]), "r"(a[2]), "r"(a[3]), "r"(b0), "r"(b1));
}

// ---------------------------------------------------------------------------
// FP16 NT-GEMM: C[M,N] = A[M,K] @ B[N,K]^T (+ bias); A,B K-major __half.
// Block tile 128(M) x 256(N) x 32(K halves). 256 threads, 8 warps = 2(M)x4(N),
// warp tile 64x64 = 4x8 m16n8k16 (32 MMA : 8 LDSM per k16).
// 4-stage cp.async pipeline. SMEM row stride 80B (conflict-free ldmatrix).
// BIAS: 0 none, 1 bias[col], 2 bias[row].  F16OUT: 1 -> Ch, 0 -> Cf.
// ---------------------------------------------------------------------------
#define BKH 32                      // K halves per stage
#define ROWB 80                     // bytes per smem row (32 halves + pad)
#define A_BYTES (128 * ROWB)        // 10240
#define B_BYTES (256 * ROWB)        // 20480
#define STAGEB (A_BYTES + B_BYTES)  // 30720
#define NSTAGE 4
#define SMEM_BYTES (NSTAGE * STAGEB)  // 122880

template <int BIAS, int F16OUT>
__global__ void __launch_bounds__(256, 1) hgemm(
    const __half* __restrict__ A, const __half* __restrict__ B,
    const float* __restrict__ bias, float* __restrict__ Cf,
    __half* __restrict__ Ch,
    int M, int N, int K, long sA, long sB, long sC)
{
    A += (long)blockIdx.z * sA;
    B += (long)blockIdx.z * sB;

    extern __shared__ char smem[];
    const uint32_t sbase = smem_u32(smem);

    const int tid  = threadIdx.x;
    const int lane = tid & 31;
    const int warp = tid >> 5;
    const int wm   = warp & 1;        // 2 warps along M (64 rows each)
    const int wn   = warp >> 1;       // 4 warps along N (64 cols each)

    const int bm = blockIdx.y * 128;
    const int bn = blockIdx.x * 256;

    auto issue = [&](int stage, int k0) {   // k0 in halves
        const __half* Ab = A + (long)bm * K + k0;
        const __half* Bb = B + (long)bn * K + k0;
        const uint32_t sa = sbase + stage * STAGEB;
        const uint32_t sb = sa + A_BYTES;
#pragma unroll
        for (int i = 0; i < 2; i++) {            // A: 512 chunks of 16B
            const int c = tid + i * 256;
            const int r = c >> 2, kc = c & 3;
            cp_async16(sa + r * ROWB + kc * 16, Ab + (long)r * K + kc * 8);
        }
#pragma unroll
        for (int i = 0; i < 4; i++) {            // B: 1024 chunks of 16B
            const int c = tid + i * 256;
            const int r = c >> 2, kc = c & 3;
            cp_async16(sb + r * ROWB + kc * 16, Bb + (long)r * K + kc * 8);
        }
        cp_commit();
    };

    float acc[4][8][4];
#pragma unroll
    for (int i = 0; i < 4; i++)
#pragma unroll
        for (int j = 0; j < 8; j++)
#pragma unroll
            for (int r = 0; r < 4; r++) acc[i][j][r] = 0.0f;

    const int T = K / BKH;
    issue(0, 0);
    issue(1, BKH);
    issue(2, 2 * BKH);

    // Per-lane ldmatrix address components
    const int aRow = wm * 64 + (lane & 15);                          // + mt*16
    const int aKB  = (lane >> 4) * 16;                               // + kk*32
    const int bRow = wn * 64 + ((lane >> 4) & 1) * 8 + (lane & 7);   // + np*16
    const int bKB  = ((lane >> 3) & 1) * 16;                         // + kk*32

    for (int t = 0; t < T; t++) {
        if (t + 3 < T) { issue((t + 3) % NSTAGE, (t + 3) * BKH); cp_wait<3>(); }
        else           { cp_wait<0>(); }
        __syncthreads();

        const uint32_t sa = sbase + (t % NSTAGE) * STAGEB;
        const uint32_t sb = sa + A_BYTES;

#pragma unroll
        for (int kk = 0; kk < 2; kk++) {             // two k16 halves
            uint32_t af[4][4];
#pragma unroll
            for (int mt = 0; mt < 4; mt++)
                LDSM_X4(af[mt], sa + (aRow + mt * 16) * ROWB + kk * 32 + aKB);
            uint32_t bf[4][4];
#pragma unroll
            for (int np = 0; np < 4; np++)
                LDSM_X4(bf[np], sb + (bRow + np * 16) * ROWB + kk * 32 + bKB);
#pragma unroll
            for (int mt = 0; mt < 4; mt++)
#pragma unroll
                for (int nt = 0; nt < 8; nt++)
                    mma16816(acc[mt][nt], af[mt],
                             bf[nt >> 1][(nt & 1) * 2],
                             bf[nt >> 1][(nt & 1) * 2 + 1]);
        }
        __syncthreads();
    }

    // Epilogue
#pragma unroll
    for (int mt = 0; mt < 4; mt++) {
        const int row0 = bm + wm * 64 + mt * 16 + (lane >> 2);
        const float rb0 = (BIAS == 2) ? bias[row0] : 0.0f;
        const float rb1 = (BIAS == 2) ? bias[row0 + 8] : 0.0f;
#pragma unroll
        for (int nt = 0; nt < 8; nt++) {
            const int col = bn + wn * 64 + nt * 8 + (lane & 3) * 2;
            float bx = 0.f, by = 0.f;
            if (BIAS == 1) {
                const float2 bb = *(const float2*)(bias + col);
                bx = bb.x; by = bb.y;
            }
            const float c0 = acc[mt][nt][0] + bx + rb0;
            const float c1 = acc[mt][nt][1] + by + rb0;
            const float c2 = acc[mt][nt][2] + bx + rb1;
            const float c3 = acc[mt][nt][3] + by + rb1;
            if (F16OUT) {
                __half* p = Ch + (long)blockIdx.z * sC + (long)row0 * N + col;
                *(__half2*)p                 = __floats2half2_rn(c0, c1);
                *(__half2*)(p + (long)8 * N) = __floats2half2_rn(c2, c3);
            } else {
                float* p = Cf + (long)blockIdx.z * sC + (long)row0 * N + col;
                *(float2*)p                 = make_float2(c0, c1);
                *(float2*)(p + (long)8 * N) = make_float2(c2, c3);
            }
        }
    }
}

// ---------------------------------------------------------------------------
// f32 -> f16 conversion (vectorized)
// ---------------------------------------------------------------------------
__global__ void __launch_bounds__(256) f32to16_kernel(
    const float* __restrict__ x, __half* __restrict__ y, int n)
{
    const int i = (blockIdx.x * 256 + threadIdx.x) * 4;
    if (i < n) {
        const float4 v = *(const float4*)(x + i);
        *(__half2*)(y + i)     = __floats2half2_rn(v.x, v.y);
        *(__half2*)(y + i + 2) = __floats2half2_rn(v.z, v.w);
    }
}

// ---------------------------------------------------------------------------
// f32 [1024][1024] -> transposed f16 [1024][1024] (tiled)
// ---------------------------------------------------------------------------
__global__ void __launch_bounds__(256) f32to16T_kernel(
    const float* __restrict__ x, __half* __restrict__ y)
{
    __shared__ float tile[32][33];
    const int tx = threadIdx.x & 31;
    const int ty = threadIdx.x >> 5;           // 0..7
    const int bx = blockIdx.x * 32;            // col of x
    const int by = blockIdx.y * 32;            // row of x
#pragma unroll
    for (int j = 0; j < 4; j++)
        tile[ty + j * 8][tx] = x[(long)(by + ty + j * 8) * D_MODEL + bx + tx];
    __syncthreads();
#pragma unroll
    for (int j = 0; j < 4; j++)
        y[(long)(bx + ty + j * 8) * D_MODEL + by + tx] =
            __float2half(tile[tx][ty + j * 8]);
}

// ---------------------------------------------------------------------------
// beff[i] = sum_e W[i,e]*bin[e] + badd[i]   (f32, one warp per row)
// ---------------------------------------------------------------------------
__global__ void __launch_bounds__(256) beff_kernel(
    const float* __restrict__ W, const float* __restrict__ bin,
    const float* __restrict__ badd, float* __restrict__ out)
{
    const int row  = blockIdx.x * 8 + (threadIdx.x >> 5);
    const int lane = threadIdx.x & 31;
    const float* w = W + (long)row * D_MODEL;
    float s = 0.0f;
    for (int e = lane * 4; e < D_MODEL; e += 128) {
        const float4 wv = *(const float4*)(w + e);
        const float4 bv = *(const float4*)(bin + e);
        s += wv.x * bv.x + wv.y * bv.y + wv.z * bv.z + wv.w * bv.w;
    }
#pragma unroll
    for (int o = 16; o; o >>= 1) s += __shfl_xor_sync(0xFFFFFFFF, s, o);
    if (lane == 0) out[row] = s + badd[row];
}

// ---------------------------------------------------------------------------
// Row softmax over last dim (1024), f32 in, transposed f16 store ST[b][d][q]
// ---------------------------------------------------------------------------
__global__ void __launch_bounds__(256) row_softmax_T_kernel(
    const float* __restrict__ X, __half* __restrict__ ST)
{
    const int row = blockIdx.x;
    const int b = row >> 11;
    const int q = row & (TQ - 1);
    const int t = threadIdx.x;

    __shared__ float red[256];

    const float* x = X + (long)row * D_MODEL;
    float v[4];
    float m = -1e30f;
#pragma unroll
    for (int i = 0; i < 4; i++) {
        v[i] = x[t + i * 256];
        m = fmaxf(m, v[i]);
    }
    red[t] = m;
    __syncthreads();
    for (int s = 128; s > 0; s >>= 1) {
        if (t < s) red[t] = fmaxf(red[t], red[t + s]);
        __syncthreads();
    }
    m = red[0];
    __syncthreads();

    float sum = 0.0f;
#pragma unroll
    for (int i = 0; i < 4; i++) {
        v[i] = __expf(v[i] - m);
        sum += v[i];
    }
    red[t] = sum;
    __syncthreads();
    for (int s = 128; s > 0; s >>= 1) {
        if (t < s) red[t] += red[t + s];
        __syncthreads();
    }
    const float inv = 1.0f / red[0];

    __half* dst = ST + (long)b * D_MODEL * TQ + q;
#pragma unroll
    for (int i = 0; i < 4; i++) {
        const int e = t + i * 256;
        dst[(long)e * TQ] = __float2half(v[i] * inv);
    }
}

// ---------------------------------------------------------------------------
// Column softmax over T_kv (axis=-2): f32 in, f16 out (same [k][d] layout)
// ---------------------------------------------------------------------------
__global__ void __launch_bounds__(256) col_softmax_kernel(
    const float* __restrict__ X, __half* __restrict__ Y)
{
    const int b = blockIdx.y;
    const int c = threadIdx.x & 31;
    const int s = threadIdx.x >> 5;
    const int e = blockIdx.x * 32 + c;

    const float* x = X + (long)b * TKV * D_MODEL + e;
    __half* y = Y + (long)b * TKV * D_MODEL + e;
    __shared__ float red[8][32];

    float m = -1e30f;
    for (int k = s; k < TKV; k += 8) m = fmaxf(m, x[(long)k * D_MODEL]);
    red[s][c] = m;
    __syncthreads();
    if (s == 0) {
        float mm = red[0][c];
#pragma unroll
        for (int i = 1; i < 8; i++) mm = fmaxf(mm, red[i][c]);
        red[0][c] = mm;
    }
    __syncthreads();
    m = red[0][c];
    __syncthreads();

    float sum = 0.0f;
    for (int k = s; k < TKV; k += 8) sum += __expf(x[(long)k * D_MODEL] - m);
    red[s][c] = sum;
    __syncthreads();
    if (s == 0) {
        float ss = red[0][c];
#pragma unroll
        for (int i = 1; i < 8; i++) ss += red[i][c];
        red[0][c] = ss;
    }
    __syncthreads();
    const float inv = 1.0f / red[0][c];

    for (int k = s; k < TKV; k += 8) {
        const long idx = (long)k * D_MODEL;
        y[idx] = __float2half(__expf(x[idx] - m) * inv);
    }
}

// ---------------------------------------------------------------------------
// Orchestration (folded algebra):
//   Weff_u = Wu@Wl (fp16 NT via Wl^T), beff_u = Wu@bl + bu
//   Weff_v = WV@WA,                    beff_v = WV@bA + bV
//   u_logits = lat @ Weff_u^T + beff_u      -> S^T (row softmax, transposed)
//   V_logits = inp @ Weff_v^T + beff_v      -> A   (col softmax over T_kv)
//   ovT_b = Wo @ lat_b^T + bo(row)          [e,q]
//   PT_b  = ovT_b @ ST_b^T                  [e,d]
//   o_b   = A_b @ PT_b^T                    [k,e]
// ---------------------------------------------------------------------------
extern "C" void kernel_launch(void* const* d_in, const int* in_sizes, int n_in,
                              void* d_out, int out_size)
{
    const float* latent = (const float*)d_in[0];
    const float* input  = (const float*)d_in[1];
    const float* Wl = (const float*)d_in[2];
    const float* bl = (const float*)d_in[3];
    const float* Wu = (const float*)d_in[4];
    const float* bu = (const float*)d_in[5];
    const float* WA = (const float*)d_in[6];
    const float* bA = (const float*)d_in[7];
    const float* WV = (const float*)d_in[8];
    const float* bV = (const float*)d_in[9];
    const float* Wo = (const float*)d_in[10];
    const float* bo = (const float*)d_in[11];
    float* out = (float*)d_out;

    float *buf, *beff;
    __half *lat16, *inp16, *w16, *weff, *a16, *st16, *ovt16, *mt16;
    cudaGetSymbolAddress((void**)&buf,   g_buf);
    cudaGetSymbolAddress((void**)&beff,  g_beff);
    cudaGetSymbolAddress((void**)&lat16, g_lat16);
    cudaGetSymbolAddress((void**)&inp16, g_inp16);
    cudaGetSymbolAddress((void**)&w16,   g_W16);
    cudaGetSymbolAddress((void**)&weff,  g_Weff);
    cudaGetSymbolAddress((void**)&a16,   g_A16);
    cudaGetSymbolAddress((void**)&st16,  g_ST16);
    cudaGetSymbolAddress((void**)&ovt16, g_ovT16);
    cudaGetSymbolAddress((void**)&mt16,  g_MT16);

    const long NW = (long)D_MODEL * D_MODEL;
    __half* Wu16  = w16 + 0 * NW;
    __half* WV16  = w16 + 1 * NW;
    __half* Wo16  = w16 + 2 * NW;
    __half* WlT16 = w16 + 3 * NW;
    __half* WAT16 = w16 + 4 * NW;
    __half* WeffU = weff + 0 * NW;
    __half* WeffV = weff + 1 * NW;
    float* beffU = beff;
    float* beffV = beff + D_MODEL;

    cudaFuncSetAttribute(hgemm<0,1>, cudaFuncAttributeMaxDynamicSharedMemorySize, SMEM_BYTES);
    cudaFuncSetAttribute(hgemm<0,0>, cudaFuncAttributeMaxDynamicSharedMemorySize, SMEM_BYTES);
    cudaFuncSetAttribute(hgemm<1,0>, cudaFuncAttributeMaxDynamicSharedMemorySize, SMEM_BYTES);
    cudaFuncSetAttribute(hgemm<2,1>, cudaFuncAttributeMaxDynamicSharedMemorySize, SMEM_BYTES);

    const dim3 blk(256);
    const int NACT = MQ * D_MODEL;

    // Converts
    f32to16_kernel<<<NACT / 1024, blk>>>(latent, lat16, NACT);
    f32to16_kernel<<<NACT / 1024, blk>>>(input,  inp16, NACT);
    f32to16_kernel<<<(int)(NW / 1024), blk>>>(Wu, Wu16, (int)NW);
    f32to16_kernel<<<(int)(NW / 1024), blk>>>(WV, WV16, (int)NW);
    f32to16_kernel<<<(int)(NW / 1024), blk>>>(Wo, Wo16, (int)NW);
    f32to16T_kernel<<<dim3(32, 32), blk>>>(Wl, WlT16);
    f32to16T_kernel<<<dim3(32, 32), blk>>>(WA, WAT16);

    // Folded biases (f32, from original weights)
    beff_kernel<<<128, blk>>>(Wu, bl, bu, beffU);
    beff_kernel<<<128, blk>>>(WV, bA, bV, beffV);

    // Effective weights: WeffU = Wu @ Wl, WeffV = WV @ WA   (1024^3 each)
    hgemm<0,1><<<dim3(4, 8), blk, SMEM_BYTES>>>(Wu16, WlT16, nullptr, nullptr,
        WeffU, D_MODEL, D_MODEL, D_MODEL, 0, 0, 0);
    hgemm<0,1><<<dim3(4, 8), blk, SMEM_BYTES>>>(WV16, WAT16, nullptr, nullptr,
        WeffV, D_MODEL, D_MODEL, D_MODEL, 0, 0, 0);

    // u_logits -> S^T
    hgemm<1,0><<<dim3(4, 64), blk, SMEM_BYTES>>>(lat16, WeffU, beffU, buf,
        nullptr, MQ, D_MODEL, D_MODEL, 0, 0, 0);
    row_softmax_T_kernel<<<MQ, blk>>>(buf, st16);

    // V_logits -> A
    hgemm<1,0><<<dim3(4, 64), blk, SMEM_BYTES>>>(inp16, WeffV, beffV, buf,
        nullptr, MQ, D_MODEL, D_MODEL, 0, 0, 0);
    col_softmax_kernel<<<dim3(D_MODEL / 32, NB), blk>>>(buf, a16);

    // ovT[b] = Wo @ lat_b^T + bo(row)    M=1024(e), N=2048(q), K=1024
    hgemm<2,1><<<dim3(TQ / 256, D_MODEL / 128, NB), blk, SMEM_BYTES>>>(
        Wo16, lat16, bo, nullptr, ovt16,
        D_MODEL, TQ, D_MODEL,
        0, (long)TQ * D_MODEL, (long)D_MODEL * TQ);

    // PT[b] = ovT[b] @ ST[b]^T           M=1024(e), N=1024(d), K=2048
    hgemm<0,1><<<dim3(D_MODEL / 256, D_MODEL / 128, NB), blk, SMEM_BYTES>>>(
        ovt16, st16, nullptr, nullptr, mt16,
        D_MODEL, D_MODEL, TQ,
        (long)D_MODEL * TQ, (long)D_MODEL * TQ, (long)D_MODEL * D_MODEL);

    // o[b] = A[b] @ PT[b]^T              M=2048(k), N=1024(e), K=1024
    hgemm<0,0><<<dim3(D_MODEL / 256, TKV / 128, NB), blk, SMEM_BYTES>>>(
        a16, mt16, nullptr, out, nullptr,
        TKV, D_MODEL, D_MODEL,
        (long)TKV * D_MODEL, (long)D_MODEL * D_MODEL, (long)TKV * D_MODEL);
}

// round 10
// speedup vs baseline: 7.0287x; 1.3459x over previous
#include <cuda_runtime.h>
#include <cuda_fp16.h>
#include <cstdint>

#define D_MODEL 1024
#define NB 4
#define TQ 2048
#define TKV 2048
#define MQ (NB * TQ)

// ---------------------------------------------------------------------------
// Static scratch (no runtime allocation allowed)
// ---------------------------------------------------------------------------
__device__ __half g_act   [2 * MQ * D_MODEL];        // lat16 | inp16   (32 MB)
__device__ __half g_latT  [MQ * D_MODEL];            // lat^T per batch (16 MB)
__device__ __half g_W16   [5 * D_MODEL * D_MODEL];   // Wu, WV, Wo, Wl^T, WA^T
__device__ __half g_Weff  [2 * D_MODEL * D_MODEL];   // Wu@Wl | WV@WA
__device__ float  g_beff  [2 * D_MODEL];             // folded biases
__device__ __half g_logits[2 * MQ * D_MODEL];        // u | V logits f16 (32 MB)
__device__ __half g_ST16  [MQ * D_MODEL];            // S^T [b][d][q]   (16 MB)
__device__ __half g_X16   [NB * D_MODEL * D_MODEL];  // X = S^T@lat     ( 8 MB)
__device__ __half g_MT16  [NB * D_MODEL * D_MODEL];  // P^T [b][e][d]   ( 8 MB)
__device__ float  g_s     [NB * D_MODEL];            // s[d] = sum_q S[q,d]

// ---------------------------------------------------------------------------
// PTX helpers
// ---------------------------------------------------------------------------
__device__ __forceinline__ uint32_t smem_u32(const void* p) {
    uint32_t a;
    asm("{ .reg .u64 t; cvta.to.shared.u64 t, %1; cvt.u32.u64 %0, t; }"
        : "=r"(a) : "l"(p));
    return a;
}
__device__ __forceinline__ void cp_async16(uint32_t smem, const void* g) {
    asm volatile("cp.async.cg.shared.global [%0], [%1], 16;\n" :: "r"(smem), "l"(g));
}
__device__ __forceinline__ void cp_commit() {
    asm volatile("cp.async.commit_group;\n" ::: "memory");
}
template <int N>
__device__ __forceinline__ void cp_wait() {
    asm volatile("cp.async.wait_group %0;\n" :: "n"(N) : "memory");
}
#define LDSM_X4(r, a)                                                         \
    asm volatile("ldmatrix.sync.aligned.m8n8.x4.shared.b16 {%0,%1,%2,%3}, [%4];" \
        : "=r"((r)[0]), "=r"((r)[1]), "=r"((r)[2]), "=r"((r)[3]) : "r"(a))

__device__ __forceinline__ void mma16816(float* c, const uint32_t* a,
                                         uint32_t b0, uint32_t b1) {
    asm volatile(
        "mma.sync.aligned.m16n8k16.row.col.f32.f16.f16.f32 "
        "{%0,%1,%2,%3}, {%4,%5,%6,%7}, {%8,%9}, {%0,%1,%2,%3};\n"
        : "+f"(c[0]), "+f"(c[1]), "+f"(c[2]), "+f"(c[3])
        : "r"(a[0]), "r"(a[1]), "r"(a[2]), "r"(a[3]), "r"(b0), "r"(b1));
}

// ---------------------------------------------------------------------------
// FP16 NT-GEMM: C[M,N] = A[M,K] @ B[N,K]^T (+ bias); A,B K-major __half.
// Block tile 128(M) x 256(N) x 32(K halves). 256 threads, 8 warps = 2(M)x4(N),
// warp tile 64x64. 5-stage cp.async pipeline, ONE __syncthreads per k-tile
// (stage t+4 never collides with stages being read at skew <= 1 iter).
// BIAS: 0 none, 1 bias[col] (per-z via sBias), 3 outer bias[row]*bias2[col]
// (bias2 per-z via sBias2).  F16OUT: 1 -> Ch, 0 -> Cf.
// ---------------------------------------------------------------------------
#define BKH 32                      // K halves per stage
#define ROWB 80                     // bytes per smem row (32 halves + pad)
#define A_BYTES (128 * ROWB)        // 10240
#define B_BYTES (256 * ROWB)        // 20480
#define STAGEB (A_BYTES + B_BYTES)  // 30720
#define NSTAGE 5
#define SMEM_BYTES (NSTAGE * STAGEB)  // 153600

template <int BIAS, int F16OUT>
__global__ void __launch_bounds__(256, 1) hgemm(
    const __half* __restrict__ A, const __half* __restrict__ B,
    const float* __restrict__ bias, const float* __restrict__ bias2,
    float* __restrict__ Cf, __half* __restrict__ Ch,
    int M, int N, int K, long sA, long sB, long sC, long sBias, long sBias2)
{
    A += (long)blockIdx.z * sA;
    B += (long)blockIdx.z * sB;
    if (BIAS) bias += (long)blockIdx.z * sBias;
    if (BIAS == 3) bias2 += (long)blockIdx.z * sBias2;

    extern __shared__ char smem[];
    const uint32_t sbase = smem_u32(smem);

    const int tid  = threadIdx.x;
    const int lane = tid & 31;
    const int warp = tid >> 5;
    const int wm   = warp & 1;        // 2 warps along M (64 rows each)
    const int wn   = warp >> 1;       // 4 warps along N (64 cols each)

    const int bm = blockIdx.y * 128;
    const int bn = blockIdx.x * 256;

    auto issue = [&](int stage, int k0) {   // k0 in halves
        const __half* Ab = A + (long)bm * K + k0;
        const __half* Bb = B + (long)bn * K + k0;
        const uint32_t sa = sbase + stage * STAGEB;
        const uint32_t sb = sa + A_BYTES;
#pragma unroll
        for (int i = 0; i < 2; i++) {            // A: 512 chunks of 16B
            const int c = tid + i * 256;
            const int r = c >> 2, kc = c & 3;
            cp_async16(sa + r * ROWB + kc * 16, Ab + (long)r * K + kc * 8);
        }
#pragma unroll
        for (int i = 0; i < 4; i++) {            // B: 1024 chunks of 16B
            const int c = tid + i * 256;
            const int r = c >> 2, kc = c & 3;
            cp_async16(sb + r * ROWB + kc * 16, Bb + (long)r * K + kc * 8);
        }
        cp_commit();
    };

    float acc[4][8][4];
#pragma unroll
    for (int i = 0; i < 4; i++)
#pragma unroll
        for (int j = 0; j < 8; j++)
#pragma unroll
            for (int r = 0; r < 4; r++) acc[i][j][r] = 0.0f;

    const int T = K / BKH;
    issue(0, 0);
    issue(1, BKH);
    issue(2, 2 * BKH);

    // Per-lane ldmatrix address components
    const int aRow = wm * 64 + (lane & 15);                          // + mt*16
    const int aKB  = (lane >> 4) * 16;                               // + kk*32
    const int bRow = wn * 64 + ((lane >> 4) & 1) * 8 + (lane & 7);   // + np*16
    const int bKB  = ((lane >> 3) & 1) * 16;                         // + kk*32

    for (int t = 0; t < T; t++) {
        if (t + 3 < T) { issue((t + 3) % NSTAGE, (t + 3) * BKH); cp_wait<3>(); }
        else           { cp_wait<0>(); }
        __syncthreads();

        const uint32_t sa = sbase + (t % NSTAGE) * STAGEB;
        const uint32_t sb = sa + A_BYTES;

#pragma unroll
        for (int kk = 0; kk < 2; kk++) {             // two k16 halves
            uint32_t af[4][4];
#pragma unroll
            for (int mt = 0; mt < 4; mt++)
                LDSM_X4(af[mt], sa + (aRow + mt * 16) * ROWB + kk * 32 + aKB);
            uint32_t bf[4][4];
#pragma unroll
            for (int np = 0; np < 4; np++)
                LDSM_X4(bf[np], sb + (bRow + np * 16) * ROWB + kk * 32 + bKB);
#pragma unroll
            for (int mt = 0; mt < 4; mt++)
#pragma unroll
                for (int nt = 0; nt < 8; nt++)
                    mma16816(acc[mt][nt], af[mt],
                             bf[nt >> 1][(nt & 1) * 2],
                             bf[nt >> 1][(nt & 1) * 2 + 1]);
        }
    }

    // Epilogue
#pragma unroll
    for (int mt = 0; mt < 4; mt++) {
        const int row0 = bm + wm * 64 + mt * 16 + (lane >> 2);
        const float rb0 = (BIAS == 3) ? bias[row0] : 0.0f;
        const float rb1 = (BIAS == 3) ? bias[row0 + 8] : 0.0f;
#pragma unroll
        for (int nt = 0; nt < 8; nt++) {
            const int col = bn + wn * 64 + nt * 8 + (lane & 3) * 2;
            float b0x = 0.f, b0y = 0.f, b1x = 0.f, b1y = 0.f;
            if (BIAS == 1) {
                const float2 bb = *(const float2*)(bias + col);
                b0x = bb.x; b0y = bb.y; b1x = bb.x; b1y = bb.y;
            } else if (BIAS == 3) {
                const float2 sv = *(const float2*)(bias2 + col);
                b0x = rb0 * sv.x; b0y = rb0 * sv.y;
                b1x = rb1 * sv.x; b1y = rb1 * sv.y;
            }
            const float c0 = acc[mt][nt][0] + b0x;
            const float c1 = acc[mt][nt][1] + b0y;
            const float c2 = acc[mt][nt][2] + b1x;
            const float c3 = acc[mt][nt][3] + b1y;
            if (F16OUT) {
                __half* p = Ch + (long)blockIdx.z * sC + (long)row0 * N + col;
                *(__half2*)p                 = __floats2half2_rn(c0, c1);
                *(__half2*)(p + (long)8 * N) = __floats2half2_rn(c2, c3);
            } else {
                float* p = Cf + (long)blockIdx.z * sC + (long)row0 * N + col;
                *(float2*)p                 = make_float2(c0, c1);
                *(float2*)(p + (long)8 * N) = make_float2(c2, c3);
            }
        }
    }
}

// ---------------------------------------------------------------------------
// f32 -> f16 conversion (vectorized)
// ---------------------------------------------------------------------------
__global__ void __launch_bounds__(256) f32to16_kernel(
    const float* __restrict__ x, __half* __restrict__ y, int n)
{
    const int i = (blockIdx.x * 256 + threadIdx.x) * 4;
    if (i < n) {
        const float4 v = *(const float4*)(x + i);
        *(__half2*)(y + i)     = __floats2half2_rn(v.x, v.y);
        *(__half2*)(y + i + 2) = __floats2half2_rn(v.z, v.w);
    }
}

// ---------------------------------------------------------------------------
// f32 [R,C] -> transposed f16 [C,R], batched via blockIdx.z
// ---------------------------------------------------------------------------
__global__ void __launch_bounds__(256) f32to16T_kernel(
    const float* __restrict__ x, __half* __restrict__ y,
    int R, int C, long sIn, long sOut)
{
    x += (long)blockIdx.z * sIn;
    y += (long)blockIdx.z * sOut;
    __shared__ float tile[32][33];
    const int tx = threadIdx.x & 31;
    const int ty = threadIdx.x >> 5;
    const int bx = blockIdx.x * 32;            // col of x
    const int by = blockIdx.y * 32;            // row of x
#pragma unroll
    for (int j = 0; j < 4; j++)
        tile[ty + j * 8][tx] = x[(long)(by + ty + j * 8) * C + bx + tx];
    __syncthreads();
#pragma unroll
    for (int j = 0; j < 4; j++)
        y[(long)(bx + ty + j * 8) * R + by + tx] =
            __float2half(tile[tx][ty + j * 8]);
}

// ---------------------------------------------------------------------------
// f16 [R,C] -> transposed f16 [C,R], batched via blockIdx.z
// ---------------------------------------------------------------------------
__global__ void __launch_bounds__(256) h16T_kernel(
    const __half* __restrict__ x, __half* __restrict__ y,
    int R, int C, long sIn, long sOut)
{
    x += (long)blockIdx.z * sIn;
    y += (long)blockIdx.z * sOut;
    __shared__ __half tile[32][34];
    const int tx = threadIdx.x & 31;
    const int ty = threadIdx.x >> 5;
    const int bx = blockIdx.x * 32;
    const int by = blockIdx.y * 32;
#pragma unroll
    for (int j = 0; j < 4; j++)
        tile[ty + j * 8][tx] = x[(long)(by + ty + j * 8) * C + bx + tx];
    __syncthreads();
#pragma unroll
    for (int j = 0; j < 4; j++)
        y[(long)(bx + ty + j * 8) * R + by + tx] = tile[tx][ty + j * 8];
}

// ---------------------------------------------------------------------------
// beff[i] = sum_e W[i,e]*bin[e] + badd[i]   (f32, one warp per row)
// ---------------------------------------------------------------------------
__global__ void __launch_bounds__(256) beff_kernel(
    const float* __restrict__ W, const float* __restrict__ bin,
    const float* __restrict__ badd, float* __restrict__ out)
{
    const int row  = blockIdx.x * 8 + (threadIdx.x >> 5);
    const int lane = threadIdx.x & 31;
    const float* w = W + (long)row * D_MODEL;
    float s = 0.0f;
    for (int e = lane * 4; e < D_MODEL; e += 128) {
        const float4 wv = *(const float4*)(w + e);
        const float4 bv = *(const float4*)(bin + e);
        s += wv.x * bv.x + wv.y * bv.y + wv.z * bv.z + wv.w * bv.w;
    }
#pragma unroll
    for (int o = 16; o; o >>= 1) s += __shfl_xor_sync(0xFFFFFFFF, s, o);
    if (lane == 0) out[row] = s + badd[row];
}

// ---------------------------------------------------------------------------
// Row softmax over last dim (1024), f16 in-place (one block per row)
// ---------------------------------------------------------------------------
__global__ void __launch_bounds__(256) row_softmax_kernel(__half* __restrict__ X)
{
    const int row = blockIdx.x;
    const int t = threadIdx.x;
    __shared__ float red[256];

    __half* x = X + (long)row * D_MODEL;
    float v[4];
    float m = -1e30f;
#pragma unroll
    for (int i = 0; i < 4; i++) {
        v[i] = __half2float(x[t + i * 256]);
        m = fmaxf(m, v[i]);
    }
    red[t] = m;
    __syncthreads();
    for (int s = 128; s > 0; s >>= 1) {
        if (t < s) red[t] = fmaxf(red[t], red[t + s]);
        __syncthreads();
    }
    m = red[0];
    __syncthreads();

    float sum = 0.0f;
#pragma unroll
    for (int i = 0; i < 4; i++) {
        v[i] = __expf(v[i] - m);
        sum += v[i];
    }
    red[t] = sum;
    __syncthreads();
    for (int s = 128; s > 0; s >>= 1) {
        if (t < s) red[t] += red[t + s];
        __syncthreads();
    }
    const float inv = 1.0f / red[0];
#pragma unroll
    for (int i = 0; i < 4; i++)
        x[t + i * 256] = __float2half(v[i] * inv);
}

// ---------------------------------------------------------------------------
// Column softmax over T_kv (axis=-2), f16 in-place, half2 columns.
// grid (D/64, NB), 256 threads: 32 half2-columns/block, 8 threads/column.
// ---------------------------------------------------------------------------
__global__ void __launch_bounds__(256) col_softmax_kernel(__half* __restrict__ X)
{
    const int b = blockIdx.y;
    const int c = threadIdx.x & 31;            // half2 column within block
    const int s = threadIdx.x >> 5;            // 0..7
    const int e2 = blockIdx.x * 32 + c;        // half2 index

    __half2* x = (__half2*)(X + (long)b * TKV * D_MODEL) + e2;
    __shared__ float2 red[8][32];
    const int LD2 = D_MODEL / 2;

    float mx = -1e30f, my = -1e30f;
    for (int k = s; k < TKV; k += 8) {
        const float2 v = __half22float2(x[(long)k * LD2]);
        mx = fmaxf(mx, v.x); my = fmaxf(my, v.y);
    }
    red[s][c] = make_float2(mx, my);
    __syncthreads();
    if (s == 0) {
        float2 mm = red[0][c];
#pragma unroll
        for (int i = 1; i < 8; i++) {
            mm.x = fmaxf(mm.x, red[i][c].x);
            mm.y = fmaxf(mm.y, red[i][c].y);
        }
        red[0][c] = mm;
    }
    __syncthreads();
    mx = red[0][c].x; my = red[0][c].y;
    __syncthreads();

    float sx = 0.0f, sy = 0.0f;
    for (int k = s; k < TKV; k += 8) {
        const float2 v = __half22float2(x[(long)k * LD2]);
        sx += __expf(v.x - mx); sy += __expf(v.y - my);
    }
    red[s][c] = make_float2(sx, sy);
    __syncthreads();
    if (s == 0) {
        float2 ss = red[0][c];
#pragma unroll
        for (int i = 1; i < 8; i++) {
            ss.x += red[i][c].x; ss.y += red[i][c].y;
        }
        red[0][c] = ss;
    }
    __syncthreads();
    const float ix = 1.0f / red[0][c].x;
    const float iy = 1.0f / red[0][c].y;

    for (int k = s; k < TKV; k += 8) {
        const long idx = (long)k * LD2;
        const float2 v = __half22float2(x[idx]);
        x[idx] = __floats2half2_rn(__expf(v.x - mx) * ix, __expf(v.y - my) * iy);
    }
}

// ---------------------------------------------------------------------------
// s[r] = sum over TQ halves of ST row r (one warp per row)
// ---------------------------------------------------------------------------
__global__ void __launch_bounds__(256) rowsum_kernel(
    const __half* __restrict__ ST, float* __restrict__ out)
{
    const int row  = blockIdx.x * 8 + (threadIdx.x >> 5);
    const int lane = threadIdx.x & 31;
    const __half2* x = (const __half2*)(ST + (long)row * TQ);
    float s = 0.0f;
    for (int e = lane; e < TQ / 2; e += 32) {
        const float2 v = __half22float2(x[e]);
        s += v.x + v.y;
    }
#pragma unroll
    for (int o = 16; o; o >>= 1) s += __shfl_xor_sync(0xFFFFFFFF, s, o);
    if (lane == 0) out[row] = s;
}

// ---------------------------------------------------------------------------
// Orchestration:
//   WeffU|V = (Wu@Wl | WV@WA),  beffU|V folded           [z-batched GEMM]
//   logits  = (lat|inp) @ Weff^T + beff  (f16)           [z-batched GEMM]
//   S = row_softmax(logitsU) in place; ST = S^T; s = rowsum(ST)
//   Amat = col_softmax(logitsV) in place
//   X_b  = ST_b @ latT_b^T                  [d2, d]
//   PT_b = Wo @ X_b^T + bo (x) s_b          [e, d2]
//   o_b  = Amat_b @ PT_b^T                  [k, e]  (f32 out)
// ---------------------------------------------------------------------------
extern "C" void kernel_launch(void* const* d_in, const int* in_sizes, int n_in,
                              void* d_out, int out_size)
{
    const float* latent = (const float*)d_in[0];
    const float* input  = (const float*)d_in[1];
    const float* Wl = (const float*)d_in[2];
    const float* bl = (const float*)d_in[3];
    const float* Wu = (const float*)d_in[4];
    const float* bu = (const float*)d_in[5];
    const float* WA = (const float*)d_in[6];
    const float* bA = (const float*)d_in[7];
    const float* WV = (const float*)d_in[8];
    const float* bV = (const float*)d_in[9];
    const float* Wo = (const float*)d_in[10];
    const float* bo = (const float*)d_in[11];
    float* out = (float*)d_out;

    __half *act, *latT, *w16, *weff, *logits, *st16, *x16, *mt16;
    float *beff, *svec;
    cudaGetSymbolAddress((void**)&act,    g_act);
    cudaGetSymbolAddress((void**)&latT,   g_latT);
    cudaGetSymbolAddress((void**)&w16,    g_W16);
    cudaGetSymbolAddress((void**)&weff,   g_Weff);
    cudaGetSymbolAddress((void**)&beff,   g_beff);
    cudaGetSymbolAddress((void**)&logits, g_logits);
    cudaGetSymbolAddress((void**)&st16,   g_ST16);
    cudaGetSymbolAddress((void**)&x16,    g_X16);
    cudaGetSymbolAddress((void**)&mt16,   g_MT16);
    cudaGetSymbolAddress((void**)&svec,   g_s);

    const long NW = (long)D_MODEL * D_MODEL;
    const long NACT = (long)MQ * D_MODEL;
    __half* Wu16  = w16 + 0 * NW;
    __half* WV16  = w16 + 1 * NW;
    __half* Wo16  = w16 + 2 * NW;
    __half* WlT16 = w16 + 3 * NW;
    __half* lat16 = act;
    __half* inp16 = act + NACT;
    __half* logU  = logits;
    __half* logV  = logits + NACT;

    cudaFuncSetAttribute(hgemm<0,1>, cudaFuncAttributeMaxDynamicSharedMemorySize, SMEM_BYTES);
    cudaFuncSetAttribute(hgemm<0,0>, cudaFuncAttributeMaxDynamicSharedMemorySize, SMEM_BYTES);
    cudaFuncSetAttribute(hgemm<1,1>, cudaFuncAttributeMaxDynamicSharedMemorySize, SMEM_BYTES);
    cudaFuncSetAttribute(hgemm<3,1>, cudaFuncAttributeMaxDynamicSharedMemorySize, SMEM_BYTES);

    const dim3 blk(256);

    // Converts
    f32to16_kernel<<<(int)(NACT / 1024), blk>>>(latent, lat16, (int)NACT);
    f32to16_kernel<<<(int)(NACT / 1024), blk>>>(input,  inp16, (int)NACT);
    f32to16_kernel<<<(int)(NW / 1024), blk>>>(Wu, Wu16, (int)NW);
    f32to16_kernel<<<(int)(NW / 1024), blk>>>(WV, WV16, (int)NW);
    f32to16_kernel<<<(int)(NW / 1024), blk>>>(Wo, Wo16, (int)NW);
    f32to16T_kernel<<<dim3(32, 32, 1), blk>>>(Wl, WlT16, D_MODEL, D_MODEL, 0, 0);
    f32to16T_kernel<<<dim3(32, 32, 1), blk>>>(WA, WlT16 + NW, D_MODEL, D_MODEL, 0, 0);
    // latT[b] = lat_b^T  ([2048,1024] -> [1024,2048] per batch)
    f32to16T_kernel<<<dim3(32, 64, NB), blk>>>(latent, latT, TQ, D_MODEL,
                                               (long)TQ * D_MODEL, (long)D_MODEL * TQ);

    // Folded biases
    beff_kernel<<<128, blk>>>(Wu, bl, bu, beff);
    beff_kernel<<<128, blk>>>(WV, bA, bV, beff + D_MODEL);

    // Weff = (Wu@Wl | WV@WA): z-batched, A = Wu16|WV16, B = WlT16|WAT16
    hgemm<0,1><<<dim3(4, 8, 2), blk, SMEM_BYTES>>>(
        Wu16, WlT16, nullptr, nullptr, nullptr, weff,
        D_MODEL, D_MODEL, D_MODEL, NW, NW, NW, 0, 0);

    // logits = (lat|inp) @ Weff^T + beff  (f16 out)
    hgemm<1,1><<<dim3(4, 64, 2), blk, SMEM_BYTES>>>(
        act, weff, beff, nullptr, nullptr, logits,
        MQ, D_MODEL, D_MODEL, NACT, NW, NACT, D_MODEL, 0);

    // S = row softmax (in place on logU), ST = S^T, s = rowsum(ST)
    row_softmax_kernel<<<MQ, blk>>>(logU);
    h16T_kernel<<<dim3(32, 64, NB), blk>>>(logU, st16, TQ, D_MODEL,
                                           (long)TQ * D_MODEL, (long)D_MODEL * TQ);
    rowsum_kernel<<<NB * D_MODEL / 8, blk>>>(st16, svec);

    // Amat = col softmax (in place on logV)
    col_softmax_kernel<<<dim3(D_MODEL / 64, NB), blk>>>(logV);

    // X_b = ST_b @ latT_b^T        M=1024(d2), N=1024(d), K=2048(q)
    hgemm<0,1><<<dim3(4, 8, NB), blk, SMEM_BYTES>>>(
        st16, latT, nullptr, nullptr, nullptr, x16,
        D_MODEL, D_MODEL, TQ,
        (long)D_MODEL * TQ, (long)D_MODEL * TQ, NW, 0, 0);

    // PT_b = Wo @ X_b^T + bo (x) s_b   M=1024(e), N=1024(d2), K=1024(d)
    hgemm<3,1><<<dim3(4, 8, NB), blk, SMEM_BYTES>>>(
        Wo16, x16, bo, svec, nullptr, mt16,
        D_MODEL, D_MODEL, D_MODEL,
        0, NW, NW, 0, (long)D_MODEL);

    // o_b = Amat_b @ PT_b^T        M=2048(k), N=1024(e), K=1024(d2)  (f32 out)
    hgemm<0,0><<<dim3(4, 16, NB), blk, SMEM_BYTES>>>(
        logV, mt16, nullptr, nullptr, out, nullptr,
        TKV, D_MODEL, D_MODEL,
        (long)TKV * D_MODEL, NW, (long)TKV * D_MODEL, 0, 0);
}

// round 11
// speedup vs baseline: 7.2231x; 1.0277x over previous
#include <cuda_runtime.h>
#include <cuda_fp16.h>
#include <cstdint>

#define D_MODEL 1024
#define NB 4
#define TQ 2048
#define TKV 2048
#define MQ (NB * TQ)

// ---------------------------------------------------------------------------
// Static scratch (no runtime allocation allowed)
// ---------------------------------------------------------------------------
__device__ __half g_act   [2 * MQ * D_MODEL];        // lat16 | inp16   (32 MB)
__device__ __half g_W16   [5 * D_MODEL * D_MODEL];   // Wu, WV, Wo, Wl^T, WA^T
__device__ __half g_Weff  [2 * D_MODEL * D_MODEL];   // Wu@Wl | WV@WA
__device__ float  g_beff  [2 * D_MODEL];             // folded biases
__device__ __half g_logits[2 * MQ * D_MODEL];        // u | V logits f16 (32 MB)
__device__ __half g_X16   [NB * D_MODEL * D_MODEL];  // X = S^T@lat     ( 8 MB)
__device__ __half g_MT16  [NB * D_MODEL * D_MODEL];  // P^T [b][e][d]   ( 8 MB)
__device__ float  g_s     [NB * D_MODEL];            // s[d] = sum_q S[q,d]

// ---------------------------------------------------------------------------
// PTX helpers
// ---------------------------------------------------------------------------
__device__ __forceinline__ uint32_t smem_u32(const void* p) {
    uint32_t a;
    asm("{ .reg .u64 t; cvta.to.shared.u64 t, %1; cvt.u32.u64 %0, t; }"
        : "=r"(a) : "l"(p));
    return a;
}
__device__ __forceinline__ void cp_async16(uint32_t smem, const void* g) {
    asm volatile("cp.async.cg.shared.global [%0], [%1], 16;\n" :: "r"(smem), "l"(g));
}
__device__ __forceinline__ void cp_commit() {
    asm volatile("cp.async.commit_group;\n" ::: "memory");
}
template <int N>
__device__ __forceinline__ void cp_wait() {
    asm volatile("cp.async.wait_group %0;\n" :: "n"(N) : "memory");
}
#define LDSM_X4(r, a)                                                         \
    asm volatile("ldmatrix.sync.aligned.m8n8.x4.shared.b16 {%0,%1,%2,%3}, [%4];" \
        : "=r"((r)[0]), "=r"((r)[1]), "=r"((r)[2]), "=r"((r)[3]) : "r"(a))
#define LDSM_X4_T(r, a)                                                       \
    asm volatile("ldmatrix.sync.aligned.m8n8.x4.trans.shared.b16 {%0,%1,%2,%3}, [%4];" \
        : "=r"((r)[0]), "=r"((r)[1]), "=r"((r)[2]), "=r"((r)[3]) : "r"(a))

__device__ __forceinline__ void mma16816(float* c, const uint32_t* a,
                                         uint32_t b0, uint32_t b1) {
    asm volatile(
        "mma.sync.aligned.m16n8k16.row.col.f32.f16.f16.f32 "
        "{%0,%1,%2,%3}, {%4,%5,%6,%7}, {%8,%9}, {%0,%1,%2,%3};\n"
        : "+f"(c[0]), "+f"(c[1]), "+f"(c[2]), "+f"(c[3])
        : "r"(a[0]), "r"(a[1]), "r"(a[2]), "r"(a[3]), "r"(b0), "r"(b1));
}

// ---------------------------------------------------------------------------
// FP16 NT-GEMM: C[M,N] = A[M,K] @ B[N,K]^T (+ bias); A,B K-major __half.
// Block tile 128(M) x 256(N) x 32(K halves). 256 threads, 8 warps = 2(M)x4(N),
// warp tile 64x64. 5-stage cp.async pipeline, one __syncthreads per k-tile.
// BIAS: 0 none, 1 bias[col] (per-z via sBias), 3 outer bias[row]*bias2[col].
// F16OUT: 1 -> Ch, 0 -> Cf.
// ---------------------------------------------------------------------------
#define BKH 32                      // K halves per stage
#define ROWB 80                     // bytes per smem row (32 halves + pad)
#define A_BYTES (128 * ROWB)        // 10240
#define B_BYTES (256 * ROWB)        // 20480
#define STAGEB (A_BYTES + B_BYTES)  // 30720
#define NSTAGE 5
#define SMEM_BYTES (NSTAGE * STAGEB)  // 153600

template <int BIAS, int F16OUT>
__global__ void __launch_bounds__(256, 1) hgemm(
    const __half* __restrict__ A, const __half* __restrict__ B,
    const float* __restrict__ bias, const float* __restrict__ bias2,
    float* __restrict__ Cf, __half* __restrict__ Ch,
    int M, int N, int K, long sA, long sB, long sC, long sBias, long sBias2)
{
    A += (long)blockIdx.z * sA;
    B += (long)blockIdx.z * sB;
    if (BIAS) bias += (long)blockIdx.z * sBias;
    if (BIAS == 3) bias2 += (long)blockIdx.z * sBias2;

    extern __shared__ char smem[];
    const uint32_t sbase = smem_u32(smem);

    const int tid  = threadIdx.x;
    const int lane = tid & 31;
    const int warp = tid >> 5;
    const int wm   = warp & 1;
    const int wn   = warp >> 1;

    const int bm = blockIdx.y * 128;
    const int bn = blockIdx.x * 256;

    auto issue = [&](int stage, int k0) {
        const __half* Ab = A + (long)bm * K + k0;
        const __half* Bb = B + (long)bn * K + k0;
        const uint32_t sa = sbase + stage * STAGEB;
        const uint32_t sb = sa + A_BYTES;
#pragma unroll
        for (int i = 0; i < 2; i++) {
            const int c = tid + i * 256;
            const int r = c >> 2, kc = c & 3;
            cp_async16(sa + r * ROWB + kc * 16, Ab + (long)r * K + kc * 8);
        }
#pragma unroll
        for (int i = 0; i < 4; i++) {
            const int c = tid + i * 256;
            const int r = c >> 2, kc = c & 3;
            cp_async16(sb + r * ROWB + kc * 16, Bb + (long)r * K + kc * 8);
        }
        cp_commit();
    };

    float acc[4][8][4];
#pragma unroll
    for (int i = 0; i < 4; i++)
#pragma unroll
        for (int j = 0; j < 8; j++)
#pragma unroll
            for (int r = 0; r < 4; r++) acc[i][j][r] = 0.0f;

    const int T = K / BKH;
    issue(0, 0);
    issue(1, BKH);
    issue(2, 2 * BKH);

    const int aRow = wm * 64 + (lane & 15);
    const int aKB  = (lane >> 4) * 16;
    const int bRow = wn * 64 + ((lane >> 4) & 1) * 8 + (lane & 7);
    const int bKB  = ((lane >> 3) & 1) * 16;

    for (int t = 0; t < T; t++) {
        if (t + 3 < T) { issue((t + 3) % NSTAGE, (t + 3) * BKH); cp_wait<3>(); }
        else           { cp_wait<0>(); }
        __syncthreads();

        const uint32_t sa = sbase + (t % NSTAGE) * STAGEB;
        const uint32_t sb = sa + A_BYTES;

#pragma unroll
        for (int kk = 0; kk < 2; kk++) {
            uint32_t af[4][4];
#pragma unroll
            for (int mt = 0; mt < 4; mt++)
                LDSM_X4(af[mt], sa + (aRow + mt * 16) * ROWB + kk * 32 + aKB);
            uint32_t bf[4][4];
#pragma unroll
            for (int np = 0; np < 4; np++)
                LDSM_X4(bf[np], sb + (bRow + np * 16) * ROWB + kk * 32 + bKB);
#pragma unroll
            for (int mt = 0; mt < 4; mt++)
#pragma unroll
                for (int nt = 0; nt < 8; nt++)
                    mma16816(acc[mt][nt], af[mt],
                             bf[nt >> 1][(nt & 1) * 2],
                             bf[nt >> 1][(nt & 1) * 2 + 1]);
        }
    }

#pragma unroll
    for (int mt = 0; mt < 4; mt++) {
        const int row0 = bm + wm * 64 + mt * 16 + (lane >> 2);
        const float rb0 = (BIAS == 3) ? bias[row0] : 0.0f;
        const float rb1 = (BIAS == 3) ? bias[row0 + 8] : 0.0f;
#pragma unroll
        for (int nt = 0; nt < 8; nt++) {
            const int col = bn + wn * 64 + nt * 8 + (lane & 3) * 2;
            float b0x = 0.f, b0y = 0.f, b1x = 0.f, b1y = 0.f;
            if (BIAS == 1) {
                const float2 bb = *(const float2*)(bias + col);
                b0x = bb.x; b0y = bb.y; b1x = bb.x; b1y = bb.y;
            } else if (BIAS == 3) {
                const float2 sv = *(const float2*)(bias2 + col);
                b0x = rb0 * sv.x; b0y = rb0 * sv.y;
                b1x = rb1 * sv.x; b1y = rb1 * sv.y;
            }
            const float c0 = acc[mt][nt][0] + b0x;
            const float c1 = acc[mt][nt][1] + b0y;
            const float c2 = acc[mt][nt][2] + b1x;
            const float c3 = acc[mt][nt][3] + b1y;
            if (F16OUT) {
                __half* p = Ch + (long)blockIdx.z * sC + (long)row0 * N + col;
                *(__half2*)p                 = __floats2half2_rn(c0, c1);
                *(__half2*)(p + (long)8 * N) = __floats2half2_rn(c2, c3);
            } else {
                float* p = Cf + (long)blockIdx.z * sC + (long)row0 * N + col;
                *(float2*)p                 = make_float2(c0, c1);
                *(float2*)(p + (long)8 * N) = make_float2(c2, c3);
            }
        }
    }
}

// ---------------------------------------------------------------------------
// FP16 TN-GEMM: C[M,N] = A^T @ B with A stored [K,M], B stored [K,N] (f16,
// row-major, leading dims lda/ldb). Both operands loaded via ldmatrix.trans.
// Same block/warp tiling as hgemm. No bias; f16 out.
// Used for X_b = S_b^T @ lat_b (kills the latT and S-transpose kernels).
// ---------------------------------------------------------------------------
#define TN_RA 272                    // 128 halves + 16B pad
#define TN_RB 528                    // 256 halves + 16B pad
#define TN_AB (32 * TN_RA)           // 8704
#define TN_BB (32 * TN_RB)           // 16896
#define TN_STAGE (TN_AB + TN_BB)     // 25600
#define TN_SMEM (NSTAGE * TN_STAGE)  // 128000

__global__ void __launch_bounds__(256, 1) hgemm_tn(
    const __half* __restrict__ A, const __half* __restrict__ B,
    __half* __restrict__ Ch,
    int M, int N, int K, int lda, int ldb, long sA, long sB, long sC)
{
    A += (long)blockIdx.z * sA;
    B += (long)blockIdx.z * sB;

    extern __shared__ char smem[];
    const uint32_t sbase = smem_u32(smem);

    const int tid  = threadIdx.x;
    const int lane = tid & 31;
    const int warp = tid >> 5;
    const int wm   = warp & 1;
    const int wn   = warp >> 1;

    const int bm = blockIdx.y * 128;
    const int bn = blockIdx.x * 256;

    auto issue = [&](int stage, int k0) {
        const __half* Ab = A + (long)k0 * lda + bm;
        const __half* Bb = B + (long)k0 * ldb + bn;
        const uint32_t sa = sbase + stage * TN_STAGE;
        const uint32_t sb = sa + TN_AB;
#pragma unroll
        for (int i = 0; i < 2; i++) {            // A: 512 chunks (32r x 16c)
            const int c = tid + i * 256;
            const int r = c >> 4, kc = c & 15;
            cp_async16(sa + r * TN_RA + kc * 16, Ab + (long)r * lda + kc * 8);
        }
#pragma unroll
        for (int i = 0; i < 4; i++) {            // B: 1024 chunks (32r x 32c)
            const int c = tid + i * 256;
            const int r = c >> 5, kc = c & 31;
            cp_async16(sb + r * TN_RB + kc * 16, Bb + (long)r * ldb + kc * 8);
        }
        cp_commit();
    };

    float acc[4][8][4];
#pragma unroll
    for (int i = 0; i < 4; i++)
#pragma unroll
        for (int j = 0; j < 8; j++)
#pragma unroll
            for (int r = 0; r < 4; r++) acc[i][j][r] = 0.0f;

    const int T = K / BKH;
    issue(0, 0);
    issue(1, BKH);
    issue(2, 2 * BKH);

    // trans-A: k-row = (lane&7) + ((lane>>4)&1)*8 ; m-col = wm*64 + ((lane>>3)&1)*8
    // trans-B: k-row = (lane&7) + ((lane>>3)&1)*8 ; n-col = wn*64 + (lane>>4)*8
    const int aK  = (lane & 7) + ((lane >> 4) & 1) * 8;
    const int aM2 = (wm * 64 + ((lane >> 3) & 1) * 8) * 2;
    const int bK  = (lane & 7) + ((lane >> 3) & 1) * 8;
    const int bN2 = (wn * 64 + (lane >> 4) * 8) * 2;

    for (int t = 0; t < T; t++) {
        if (t + 3 < T) { issue((t + 3) % NSTAGE, (t + 3) * BKH); cp_wait<3>(); }
        else           { cp_wait<0>(); }
        __syncthreads();

        const uint32_t sa = sbase + (t % NSTAGE) * TN_STAGE;
        const uint32_t sb = sa + TN_AB;

#pragma unroll
        for (int kk = 0; kk < 2; kk++) {
            uint32_t af[4][4];
#pragma unroll
            for (int mt = 0; mt < 4; mt++)
                LDSM_X4_T(af[mt], sa + (kk * 16 + aK) * TN_RA + aM2 + mt * 32);
            uint32_t bf[4][4];
#pragma unroll
            for (int np = 0; np < 4; np++)
                LDSM_X4_T(bf[np], sb + (kk * 16 + bK) * TN_RB + bN2 + np * 32);
#pragma unroll
            for (int mt = 0; mt < 4; mt++)
#pragma unroll
                for (int nt = 0; nt < 8; nt++)
                    mma16816(acc[mt][nt], af[mt],
                             bf[nt >> 1][(nt & 1) * 2],
                             bf[nt >> 1][(nt & 1) * 2 + 1]);
        }
    }

#pragma unroll
    for (int mt = 0; mt < 4; mt++) {
        const int row0 = bm + wm * 64 + mt * 16 + (lane >> 2);
#pragma unroll
        for (int nt = 0; nt < 8; nt++) {
            const int col = bn + wn * 64 + nt * 8 + (lane & 3) * 2;
            __half* p = Ch + (long)blockIdx.z * sC + (long)row0 * N + col;
            *(__half2*)p = __floats2half2_rn(acc[mt][nt][0], acc[mt][nt][1]);
            *(__half2*)(p + (long)8 * N) =
                __floats2half2_rn(acc[mt][nt][2], acc[mt][nt][3]);
        }
    }
}

// ---------------------------------------------------------------------------
// f32 -> f16 conversion, z-batched over up to 3 tensors
// ---------------------------------------------------------------------------
__global__ void __launch_bounds__(256) f32to16z_kernel(
    const float* __restrict__ x0, const float* __restrict__ x1,
    const float* __restrict__ x2,
    __half* __restrict__ y0, __half* __restrict__ y1, __half* __restrict__ y2,
    int n)
{
    const float* x = (blockIdx.z == 0) ? x0 : (blockIdx.z == 1) ? x1 : x2;
    __half*      y = (blockIdx.z == 0) ? y0 : (blockIdx.z == 1) ? y1 : y2;
    const int i = (blockIdx.x * 256 + threadIdx.x) * 4;
    if (i < n) {
        const float4 v = *(const float4*)(x + i);
        *(__half2*)(y + i)     = __floats2half2_rn(v.x, v.y);
        *(__half2*)(y + i + 2) = __floats2half2_rn(v.z, v.w);
    }
}

// ---------------------------------------------------------------------------
// f32 [1024,1024] -> transposed f16, z-batched over 2 tensors
// ---------------------------------------------------------------------------
__global__ void __launch_bounds__(256) f32to16Tz_kernel(
    const float* __restrict__ x0, const float* __restrict__ x1,
    __half* __restrict__ y0, __half* __restrict__ y1)
{
    const float* x = blockIdx.z ? x1 : x0;
    __half*      y = blockIdx.z ? y1 : y0;
    __shared__ float tile[32][33];
    const int tx = threadIdx.x & 31;
    const int ty = threadIdx.x >> 5;
    const int bx = blockIdx.x * 32;
    const int by = blockIdx.y * 32;
#pragma unroll
    for (int j = 0; j < 4; j++)
        tile[ty + j * 8][tx] = x[(long)(by + ty + j * 8) * D_MODEL + bx + tx];
    __syncthreads();
#pragma unroll
    for (int j = 0; j < 4; j++)
        y[(long)(bx + ty + j * 8) * D_MODEL + by + tx] =
            __float2half(tile[tx][ty + j * 8]);
}

// ---------------------------------------------------------------------------
// beff[i] = sum_e W[i,e]*bin[e] + badd[i]   (f32, one warp per row)
// ---------------------------------------------------------------------------
__global__ void __launch_bounds__(256) beff_kernel(
    const float* __restrict__ W, const float* __restrict__ bin,
    const float* __restrict__ badd, float* __restrict__ out)
{
    const int row  = blockIdx.x * 8 + (threadIdx.x >> 5);
    const int lane = threadIdx.x & 31;
    const float* w = W + (long)row * D_MODEL;
    float s = 0.0f;
    for (int e = lane * 4; e < D_MODEL; e += 128) {
        const float4 wv = *(const float4*)(w + e);
        const float4 bv = *(const float4*)(bin + e);
        s += wv.x * bv.x + wv.y * bv.y + wv.z * bv.z + wv.w * bv.w;
    }
#pragma unroll
    for (int o = 16; o; o >>= 1) s += __shfl_xor_sync(0xFFFFFFFF, s, o);
    if (lane == 0) out[row] = s + badd[row];
}

// ---------------------------------------------------------------------------
// Zero fill (svec)
// ---------------------------------------------------------------------------
__global__ void __launch_bounds__(256) zero_kernel(float* __restrict__ p, int n)
{
    for (int i = blockIdx.x * 256 + threadIdx.x; i < n; i += gridDim.x * 256)
        p[i] = 0.0f;
}

// ---------------------------------------------------------------------------
// Row softmax over last dim (1024), f16 in-place (one block per row)
// ---------------------------------------------------------------------------
__global__ void __launch_bounds__(256) row_softmax_kernel(__half* __restrict__ X)
{
    const int row = blockIdx.x;
    const int t = threadIdx.x;
    __shared__ float red[256];

    __half* x = X + (long)row * D_MODEL;
    float v[4];
    float m = -1e30f;
#pragma unroll
    for (int i = 0; i < 4; i++) {
        v[i] = __half2float(x[t + i * 256]);
        m = fmaxf(m, v[i]);
    }
    red[t] = m;
    __syncthreads();
    for (int s = 128; s > 0; s >>= 1) {
        if (t < s) red[t] = fmaxf(red[t], red[t + s]);
        __syncthreads();
    }
    m = red[0];
    __syncthreads();

    float sum = 0.0f;
#pragma unroll
    for (int i = 0; i < 4; i++) {
        v[i] = __expf(v[i] - m);
        sum += v[i];
    }
    red[t] = sum;
    __syncthreads();
    for (int s = 128; s > 0; s >>= 1) {
        if (t < s) red[t] += red[t + s];
        __syncthreads();
    }
    const float inv = 1.0f / red[0];
#pragma unroll
    for (int i = 0; i < 4; i++)
        x[t + i * 256] = __float2half(v[i] * inv);
}

// ---------------------------------------------------------------------------
// Column sums of S: svec[b][d] += sum_{q in chunk} S[b][q][d]
// grid (2, 8, NB): x = half2-col block (256 half2), y = q chunk (256 rows)
// ---------------------------------------------------------------------------
__global__ void __launch_bounds__(256) colsum_kernel(
    const __half* __restrict__ S, float* __restrict__ svec)
{
    const int b = blockIdx.z;
    const int e2 = blockIdx.x * 256 + threadIdx.x;     // half2 col, 0..511
    const int q0 = blockIdx.y * 256;
    const __half2* x = (const __half2*)(S + (long)b * TQ * D_MODEL) + e2;
    float sx = 0.0f, sy = 0.0f;
#pragma unroll 4
    for (int q = q0; q < q0 + 256; q++) {
        const float2 v = __half22float2(x[(long)q * (D_MODEL / 2)]);
        sx += v.x; sy += v.y;
    }
    atomicAdd(svec + b * D_MODEL + e2 * 2,     sx);
    atomicAdd(svec + b * D_MODEL + e2 * 2 + 1, sy);
}

// ---------------------------------------------------------------------------
// Column softmax over T_kv (axis=-2), f16 in-place, half2 columns.
// ---------------------------------------------------------------------------
__global__ void __launch_bounds__(256) col_softmax_kernel(__half* __restrict__ X)
{
    const int b = blockIdx.y;
    const int c = threadIdx.x & 31;
    const int s = threadIdx.x >> 5;
    const int e2 = blockIdx.x * 32 + c;

    __half2* x = (__half2*)(X + (long)b * TKV * D_MODEL) + e2;
    __shared__ float2 red[8][32];
    const int LD2 = D_MODEL / 2;

    float mx = -1e30f, my = -1e30f;
    for (int k = s; k < TKV; k += 8) {
        const float2 v = __half22float2(x[(long)k * LD2]);
        mx = fmaxf(mx, v.x); my = fmaxf(my, v.y);
    }
    red[s][c] = make_float2(mx, my);
    __syncthreads();
    if (s == 0) {
        float2 mm = red[0][c];
#pragma unroll
        for (int i = 1; i < 8; i++) {
            mm.x = fmaxf(mm.x, red[i][c].x);
            mm.y = fmaxf(mm.y, red[i][c].y);
        }
        red[0][c] = mm;
    }
    __syncthreads();
    mx = red[0][c].x; my = red[0][c].y;
    __syncthreads();

    float sx = 0.0f, sy = 0.0f;
    for (int k = s; k < TKV; k += 8) {
        const float2 v = __half22float2(x[(long)k * LD2]);
        sx += __expf(v.x - mx); sy += __expf(v.y - my);
    }
    red[s][c] = make_float2(sx, sy);
    __syncthreads();
    if (s == 0) {
        float2 ss = red[0][c];
#pragma unroll
        for (int i = 1; i < 8; i++) {
            ss.x += red[i][c].x; ss.y += red[i][c].y;
        }
        red[0][c] = ss;
    }
    __syncthreads();
    const float ix = 1.0f / red[0][c].x;
    const float iy = 1.0f / red[0][c].y;

    for (int k = s; k < TKV; k += 8) {
        const long idx = (long)k * LD2;
        const float2 v = __half22float2(x[idx]);
        x[idx] = __floats2half2_rn(__expf(v.x - mx) * ix, __expf(v.y - my) * iy);
    }
}

// ---------------------------------------------------------------------------
// Orchestration:
//   WeffU|V = (Wu@Wl | WV@WA), beff folded              [z-batched NT GEMM]
//   logits  = (lat|inp) @ Weff^T + beff (f16)           [z-batched NT GEMM]
//   S = row_softmax(logU) in place; svec = colsum(S)
//   Amat = col_softmax(logV) in place
//   X_b  = S_b^T @ lat_b                    [d2,d]   (TN GEMM, no transposes)
//   PT_b = Wo @ X_b^T + bo (x) s_b          [e,d2]
//   o_b  = Amat_b @ PT_b^T                  [k,e]    (f32 out)
// ---------------------------------------------------------------------------
extern "C" void kernel_launch(void* const* d_in, const int* in_sizes, int n_in,
                              void* d_out, int out_size)
{
    const float* latent = (const float*)d_in[0];
    const float* input  = (const float*)d_in[1];
    const float* Wl = (const float*)d_in[2];
    const float* bl = (const float*)d_in[3];
    const float* Wu = (const float*)d_in[4];
    const float* bu = (const float*)d_in[5];
    const float* WA = (const float*)d_in[6];
    const float* bA = (const float*)d_in[7];
    const float* WV = (const float*)d_in[8];
    const float* bV = (const float*)d_in[9];
    const float* Wo = (const float*)d_in[10];
    const float* bo = (const float*)d_in[11];
    float* out = (float*)d_out;

    __half *act, *w16, *weff, *logits, *x16, *mt16;
    float *beff, *svec;
    cudaGetSymbolAddress((void**)&act,    g_act);
    cudaGetSymbolAddress((void**)&w16,    g_W16);
    cudaGetSymbolAddress((void**)&weff,   g_Weff);
    cudaGetSymbolAddress((void**)&beff,   g_beff);
    cudaGetSymbolAddress((void**)&logits, g_logits);
    cudaGetSymbolAddress((void**)&x16,    g_X16);
    cudaGetSymbolAddress((void**)&mt16,   g_MT16);
    cudaGetSymbolAddress((void**)&svec,   g_s);

    const long NW = (long)D_MODEL * D_MODEL;
    const long NACT = (long)MQ * D_MODEL;
    __half* Wu16  = w16 + 0 * NW;
    __half* WV16  = w16 + 1 * NW;
    __half* Wo16  = w16 + 2 * NW;
    __half* WlT16 = w16 + 3 * NW;
    __half* WAT16 = w16 + 4 * NW;
    __half* lat16 = act;
    __half* inp16 = act + NACT;
    __half* logU  = logits;
    __half* logV  = logits + NACT;

    cudaFuncSetAttribute(hgemm<0,1>, cudaFuncAttributeMaxDynamicSharedMemorySize, SMEM_BYTES);
    cudaFuncSetAttribute(hgemm<0,0>, cudaFuncAttributeMaxDynamicSharedMemorySize, SMEM_BYTES);
    cudaFuncSetAttribute(hgemm<1,1>, cudaFuncAttributeMaxDynamicSharedMemorySize, SMEM_BYTES);
    cudaFuncSetAttribute(hgemm<3,1>, cudaFuncAttributeMaxDynamicSharedMemorySize, SMEM_BYTES);
    cudaFuncSetAttribute(hgemm_tn,   cudaFuncAttributeMaxDynamicSharedMemorySize, TN_SMEM);

    const dim3 blk(256);

    // Converts (z-batched)
    f32to16z_kernel<<<dim3((int)(NACT / 1024), 1, 2), blk>>>(
        latent, input, nullptr, lat16, inp16, nullptr, (int)NACT);
    f32to16z_kernel<<<dim3((int)(NW / 1024), 1, 3), blk>>>(
        Wu, WV, Wo, Wu16, WV16, Wo16, (int)NW);
    f32to16Tz_kernel<<<dim3(32, 32, 2), blk>>>(Wl, WA, WlT16, WAT16);

    // Folded biases + zero svec
    beff_kernel<<<128, blk>>>(Wu, bl, bu, beff);
    beff_kernel<<<128, blk>>>(WV, bA, bV, beff + D_MODEL);
    zero_kernel<<<4, blk>>>(svec, NB * D_MODEL);

    // Weff = (Wu@Wl | WV@WA): z-batched
    hgemm<0,1><<<dim3(4, 8, 2), blk, SMEM_BYTES>>>(
        Wu16, WlT16, nullptr, nullptr, nullptr, weff,
        D_MODEL, D_MODEL, D_MODEL, NW, NW, NW, 0, 0);

    // logits = (lat|inp) @ Weff^T + beff  (f16 out)
    hgemm<1,1><<<dim3(4, 64, 2), blk, SMEM_BYTES>>>(
        act, weff, beff, nullptr, nullptr, logits,
        MQ, D_MODEL, D_MODEL, NACT, NW, NACT, D_MODEL, 0);

    // S = row softmax (in place on logU); svec = column sums of S
    row_softmax_kernel<<<MQ, blk>>>(logU);
    colsum_kernel<<<dim3(2, 8, NB), blk>>>(logU, svec);

    // Amat = col softmax (in place on logV)
    col_softmax_kernel<<<dim3(D_MODEL / 64, NB), blk>>>(logV);

    // X_b = S_b^T @ lat_b   (TN)   M=1024(d2), N=1024(d), K=2048(q)
    hgemm_tn<<<dim3(4, 8, NB), blk, TN_SMEM>>>(
        logU, lat16, x16,
        D_MODEL, D_MODEL, TQ, D_MODEL, D_MODEL,
        (long)TQ * D_MODEL, (long)TQ * D_MODEL, NW);

    // PT_b = Wo @ X_b^T + bo (x) s_b   M=1024(e), N=1024(d2), K=1024(d)
    hgemm<3,1><<<dim3(4, 8, NB), blk, SMEM_BYTES>>>(
        Wo16, x16, bo, svec, nullptr, mt16,
        D_MODEL, D_MODEL, D_MODEL,
        0, NW, NW, 0, (long)D_MODEL);

    // o_b = Amat_b @ PT_b^T   M=2048(k), N=1024(e), K=1024(d2)  (f32 out)
    hgemm<0,0><<<dim3(4, 16, NB), blk, SMEM_BYTES>>>(
        logV, mt16, nullptr, nullptr, out, nullptr,
        TKV, D_MODEL, D_MODEL,
        (long)TKV * D_MODEL, NW, (long)TKV * D_MODEL, 0, 0);
}

// round 13
// speedup vs baseline: 7.5035x; 1.0388x over previous
#include <cuda_runtime.h>
#include <cuda_fp16.h>
#include <cstdint>

#define D_MODEL 1024
#define NB 4
#define TQ 2048
#define TKV 2048
#define MQ (NB * TQ)

// ---------------------------------------------------------------------------
// Static scratch (no runtime allocation allowed)
// ---------------------------------------------------------------------------
__device__ __half g_act   [2 * MQ * D_MODEL];        // lat16 | inp16   (32 MB)
__device__ __half g_W16   [5 * D_MODEL * D_MODEL];   // Wu, WV, Wo, Wl^T, WA^T
__device__ __half g_Weff  [2 * D_MODEL * D_MODEL];   // Wu@Wl | WV@WA
__device__ float  g_beff  [2 * D_MODEL];             // folded biases
__device__ __half g_logits[2 * MQ * D_MODEL];        // u | V logits f16 (32 MB)
__device__ __half g_X16   [NB * D_MODEL * D_MODEL];  // X = S^T@lat     ( 8 MB)
__device__ __half g_MT16  [NB * D_MODEL * D_MODEL];  // P^T [b][e][d]   ( 8 MB)
__device__ float  g_s     [NB * D_MODEL];            // s[d] = sum_q S[q,d]

// ---------------------------------------------------------------------------
// PTX helpers
// ---------------------------------------------------------------------------
__device__ __forceinline__ uint32_t smem_u32(const void* p) {
    uint32_t a;
    asm("{ .reg .u64 t; cvta.to.shared.u64 t, %1; cvt.u32.u64 %0, t; }"
        : "=r"(a) : "l"(p));
    return a;
}
__device__ __forceinline__ void cp_async16(uint32_t smem, const void* g) {
    asm volatile("cp.async.cg.shared.global [%0], [%1], 16;\n" :: "r"(smem), "l"(g));
}
__device__ __forceinline__ void cp_commit() {
    asm volatile("cp.async.commit_group;\n" ::: "memory");
}
template <int N>
__device__ __forceinline__ void cp_wait() {
    asm volatile("cp.async.wait_group %0;\n" :: "n"(N) : "memory");
}
#define LDSM_X4(r, a)                                                         \
    asm volatile("ldmatrix.sync.aligned.m8n8.x4.shared.b16 {%0,%1,%2,%3}, [%4];" \
        : "=r"((r)[0]), "=r"((r)[1]), "=r"((r)[2]), "=r"((r)[3]) : "r"(a))
#define LDSM_X4_T(r, a)                                                       \
    asm volatile("ldmatrix.sync.aligned.m8n8.x4.trans.shared.b16 {%0,%1,%2,%3}, [%4];" \
        : "=r"((r)[0]), "=r"((r)[1]), "=r"((r)[2]), "=r"((r)[3]) : "r"(a))

__device__ __forceinline__ void mma16816(float* c, const uint32_t* a,
                                         uint32_t b0, uint32_t b1) {
    asm volatile(
        "mma.sync.aligned.m16n8k16.row.col.f32.f16.f16.f32 "
        "{%0,%1,%2,%3}, {%4,%5,%6,%7}, {%8,%9}, {%0,%1,%2,%3};\n"
        : "+f"(c[0]), "+f"(c[1]), "+f"(c[2]), "+f"(c[3])
        : "r"(a[0]), "r"(a[1]), "r"(a[2]), "r"(a[3]), "r"(b0), "r"(b1));
}

// ---------------------------------------------------------------------------
// FP16 NT-GEMM: C[M,N] = A[M,K] @ B[N,K]^T (+ bias); A,B K-major __half.
// Block tile 128(M) x 256(N) x 32(K halves). 256 threads, 8 warps = 2(M)x4(N),
// warp tile 64x64. 5-stage cp.async pipeline, one __syncthreads per k-tile,
// double-buffered register fragments (LDSM for kk+1 overlaps MMAs of kk).
// BIAS: 0 none, 1 bias[col] (per-z via sBias), 3 outer bias[row]*bias2[col].
// F16OUT: 1 -> Ch, 0 -> Cf.
// ---------------------------------------------------------------------------
#define BKH 32                      // K halves per stage
#define ROWB 80                     // bytes per smem row (32 halves + pad)
#define A_BYTES (128 * ROWB)        // 10240
#define B_BYTES (256 * ROWB)        // 20480
#define STAGEB (A_BYTES + B_BYTES)  // 30720
#define NSTAGE 5
#define SMEM_BYTES (NSTAGE * STAGEB)  // 153600

template <int BIAS, int F16OUT>
__global__ void __launch_bounds__(256, 1) hgemm(
    const __half* __restrict__ A, const __half* __restrict__ B,
    const float* __restrict__ bias, const float* __restrict__ bias2,
    float* __restrict__ Cf, __half* __restrict__ Ch,
    int M, int N, int K, long sA, long sB, long sC, long sBias, long sBias2)
{
    A += (long)blockIdx.z * sA;
    B += (long)blockIdx.z * sB;
    if (BIAS) bias += (long)blockIdx.z * sBias;
    if (BIAS == 3) bias2 += (long)blockIdx.z * sBias2;

    extern __shared__ char smem[];
    const uint32_t sbase = smem_u32(smem);

    const int tid  = threadIdx.x;
    const int lane = tid & 31;
    const int warp = tid >> 5;
    const int wm   = warp & 1;
    const int wn   = warp >> 1;

    const int bm = blockIdx.y * 128;
    const int bn = blockIdx.x * 256;

    auto issue = [&](int stage, int k0) {
        const __half* Ab = A + (long)bm * K + k0;
        const __half* Bb = B + (long)bn * K + k0;
        const uint32_t sa = sbase + stage * STAGEB;
        const uint32_t sb = sa + A_BYTES;
#pragma unroll
        for (int i = 0; i < 2; i++) {
            const int c = tid + i * 256;
            const int r = c >> 2, kc = c & 3;
            cp_async16(sa + r * ROWB + kc * 16, Ab + (long)r * K + kc * 8);
        }
#pragma unroll
        for (int i = 0; i < 4; i++) {
            const int c = tid + i * 256;
            const int r = c >> 2, kc = c & 3;
            cp_async16(sb + r * ROWB + kc * 16, Bb + (long)r * K + kc * 8);
        }
        cp_commit();
    };

    float acc[4][8][4];
#pragma unroll
    for (int i = 0; i < 4; i++)
#pragma unroll
        for (int j = 0; j < 8; j++)
#pragma unroll
            for (int r = 0; r < 4; r++) acc[i][j][r] = 0.0f;

    const int T = K / BKH;
    issue(0, 0);
    issue(1, BKH);
    issue(2, 2 * BKH);

    const int aRow = wm * 64 + (lane & 15);
    const int aKB  = (lane >> 4) * 16;
    const int bRow = wn * 64 + ((lane >> 4) & 1) * 8 + (lane & 7);
    const int bKB  = ((lane >> 3) & 1) * 16;

    uint32_t af[2][4][4], bf[2][4][4];

    for (int t = 0; t < T; t++) {
        if (t + 3 < T) { issue((t + 3) % NSTAGE, (t + 3) * BKH); cp_wait<3>(); }
        else           { cp_wait<0>(); }
        __syncthreads();

        const uint32_t sa = sbase + (t % NSTAGE) * STAGEB;
        const uint32_t sb = sa + A_BYTES;

        // kk = 0 fragments
#pragma unroll
        for (int mt = 0; mt < 4; mt++)
            LDSM_X4(af[0][mt], sa + (aRow + mt * 16) * ROWB + aKB);
#pragma unroll
        for (int np = 0; np < 4; np++)
            LDSM_X4(bf[0][np], sb + (bRow + np * 16) * ROWB + bKB);

        // kk = 1 fragments issued BEFORE kk = 0 MMAs (overlap)
#pragma unroll
        for (int mt = 0; mt < 4; mt++)
            LDSM_X4(af[1][mt], sa + (aRow + mt * 16) * ROWB + 32 + aKB);
#pragma unroll
        for (int np = 0; np < 4; np++)
            LDSM_X4(bf[1][np], sb + (bRow + np * 16) * ROWB + 32 + bKB);

#pragma unroll
        for (int kk = 0; kk < 2; kk++)
#pragma unroll
            for (int mt = 0; mt < 4; mt++)
#pragma unroll
                for (int nt = 0; nt < 8; nt++)
                    mma16816(acc[mt][nt], af[kk][mt],
                             bf[kk][nt >> 1][(nt & 1) * 2],
                             bf[kk][nt >> 1][(nt & 1) * 2 + 1]);
    }

#pragma unroll
    for (int mt = 0; mt < 4; mt++) {
        const int row0 = bm + wm * 64 + mt * 16 + (lane >> 2);
        const float rb0 = (BIAS == 3) ? bias[row0] : 0.0f;
        const float rb1 = (BIAS == 3) ? bias[row0 + 8] : 0.0f;
#pragma unroll
        for (int nt = 0; nt < 8; nt++) {
            const int col = bn + wn * 64 + nt * 8 + (lane & 3) * 2;
            float b0x = 0.f, b0y = 0.f, b1x = 0.f, b1y = 0.f;
            if (BIAS == 1) {
                const float2 bb = *(const float2*)(bias + col);
                b0x = bb.x; b0y = bb.y; b1x = bb.x; b1y = bb.y;
            } else if (BIAS == 3) {
                const float2 sv = *(const float2*)(bias2 + col);
                b0x = rb0 * sv.x; b0y = rb0 * sv.y;
                b1x = rb1 * sv.x; b1y = rb1 * sv.y;
            }
            const float c0 = acc[mt][nt][0] + b0x;
            const float c1 = acc[mt][nt][1] + b0y;
            const float c2 = acc[mt][nt][2] + b1x;
            const float c3 = acc[mt][nt][3] + b1y;
            if (F16OUT) {
                __half* p = Ch + (long)blockIdx.z * sC + (long)row0 * N + col;
                *(__half2*)p                 = __floats2half2_rn(c0, c1);
                *(__half2*)(p + (long)8 * N) = __floats2half2_rn(c2, c3);
            } else {
                float* p = Cf + (long)blockIdx.z * sC + (long)row0 * N + col;
                *(float2*)p                 = make_float2(c0, c1);
                *(float2*)(p + (long)8 * N) = make_float2(c2, c3);
            }
        }
    }
}

// ---------------------------------------------------------------------------
// FP16 TN-GEMM: C[M,N] = A^T @ B with A stored [K,M], B stored [K,N] (f16).
// Both operands via ldmatrix.trans. Same tiling; frag double-buffered.
// ---------------------------------------------------------------------------
#define TN_RA 272                    // 128 halves + 16B pad
#define TN_RB 528                    // 256 halves + 16B pad
#define TN_AB (32 * TN_RA)           // 8704
#define TN_BB (32 * TN_RB)           // 16896
#define TN_STAGE (TN_AB + TN_BB)     // 25600
#define TN_SMEM (NSTAGE * TN_STAGE)  // 128000

__global__ void __launch_bounds__(256, 1) hgemm_tn(
    const __half* __restrict__ A, const __half* __restrict__ B,
    __half* __restrict__ Ch,
    int M, int N, int K, int lda, int ldb, long sA, long sB, long sC)
{
    A += (long)blockIdx.z * sA;
    B += (long)blockIdx.z * sB;

    extern __shared__ char smem[];
    const uint32_t sbase = smem_u32(smem);

    const int tid  = threadIdx.x;
    const int lane = tid & 31;
    const int warp = tid >> 5;
    const int wm   = warp & 1;
    const int wn   = warp >> 1;

    const int bm = blockIdx.y * 128;
    const int bn = blockIdx.x * 256;

    auto issue = [&](int stage, int k0) {
        const __half* Ab = A + (long)k0 * lda + bm;
        const __half* Bb = B + (long)k0 * ldb + bn;
        const uint32_t sa = sbase + stage * TN_STAGE;
        const uint32_t sb = sa + TN_AB;
#pragma unroll
        for (int i = 0; i < 2; i++) {
            const int c = tid + i * 256;
            const int r = c >> 4, kc = c & 15;
            cp_async16(sa + r * TN_RA + kc * 16, Ab + (long)r * lda + kc * 8);
        }
#pragma unroll
        for (int i = 0; i < 4; i++) {
            const int c = tid + i * 256;
            const int r = c >> 5, kc = c & 31;
            cp_async16(sb + r * TN_RB + kc * 16, Bb + (long)r * ldb + kc * 8);
        }
        cp_commit();
    };

    float acc[4][8][4];
#pragma unroll
    for (int i = 0; i < 4; i++)
#pragma unroll
        for (int j = 0; j < 8; j++)
#pragma unroll
            for (int r = 0; r < 4; r++) acc[i][j][r] = 0.0f;

    const int T = K / BKH;
    issue(0, 0);
    issue(1, BKH);
    issue(2, 2 * BKH);

    const int aK  = (lane & 7) + ((lane >> 4) & 1) * 8;
    const int aM2 = (wm * 64 + ((lane >> 3) & 1) * 8) * 2;
    const int bK  = (lane & 7) + ((lane >> 3) & 1) * 8;
    const int bN2 = (wn * 64 + (lane >> 4) * 8) * 2;

    uint32_t af[2][4][4], bf[2][4][4];

    for (int t = 0; t < T; t++) {
        if (t + 3 < T) { issue((t + 3) % NSTAGE, (t + 3) * BKH); cp_wait<3>(); }
        else           { cp_wait<0>(); }
        __syncthreads();

        const uint32_t sa = sbase + (t % NSTAGE) * TN_STAGE;
        const uint32_t sb = sa + TN_AB;

#pragma unroll
        for (int mt = 0; mt < 4; mt++)
            LDSM_X4_T(af[0][mt], sa + aK * TN_RA + aM2 + mt * 32);
#pragma unroll
        for (int np = 0; np < 4; np++)
            LDSM_X4_T(bf[0][np], sb + bK * TN_RB + bN2 + np * 32);
#pragma unroll
        for (int mt = 0; mt < 4; mt++)
            LDSM_X4_T(af[1][mt], sa + (16 + aK) * TN_RA + aM2 + mt * 32);
#pragma unroll
        for (int np = 0; np < 4; np++)
            LDSM_X4_T(bf[1][np], sb + (16 + bK) * TN_RB + bN2 + np * 32);

#pragma unroll
        for (int kk = 0; kk < 2; kk++)
#pragma unroll
            for (int mt = 0; mt < 4; mt++)
#pragma unroll
                for (int nt = 0; nt < 8; nt++)
                    mma16816(acc[mt][nt], af[kk][mt],
                             bf[kk][nt >> 1][(nt & 1) * 2],
                             bf[kk][nt >> 1][(nt & 1) * 2 + 1]);
    }

#pragma unroll
    for (int mt = 0; mt < 4; mt++) {
        const int row0 = bm + wm * 64 + mt * 16 + (lane >> 2);
#pragma unroll
        for (int nt = 0; nt < 8; nt++) {
            const int col = bn + wn * 64 + nt * 8 + (lane & 3) * 2;
            __half* p = Ch + (long)blockIdx.z * sC + (long)row0 * N + col;
            *(__half2*)p = __floats2half2_rn(acc[mt][nt][0], acc[mt][nt][1]);
            *(__half2*)(p + (long)8 * N) =
                __floats2half2_rn(acc[mt][nt][2], acc[mt][nt][3]);
        }
    }
}

// ---------------------------------------------------------------------------
// f32 -> f16 conversion, z-batched over up to 3 tensors
// ---------------------------------------------------------------------------
__global__ void __launch_bounds__(256) f32to16z_kernel(
    const float* __restrict__ x0, const float* __restrict__ x1,
    const float* __restrict__ x2,
    __half* __restrict__ y0, __half* __restrict__ y1, __half* __restrict__ y2,
    int n)
{
    const float* x = (blockIdx.z == 0) ? x0 : (blockIdx.z == 1) ? x1 : x2;
    __half*      y = (blockIdx.z == 0) ? y0 : (blockIdx.z == 1) ? y1 : y2;
    const int i = (blockIdx.x * 256 + threadIdx.x) * 4;
    if (i < n) {
        const float4 v = *(const float4*)(x + i);
        *(__half2*)(y + i)     = __floats2half2_rn(v.x, v.y);
        *(__half2*)(y + i + 2) = __floats2half2_rn(v.z, v.w);
    }
}

// ---------------------------------------------------------------------------
// f32 [1024,1024] -> transposed f16, z-batched over 2 tensors
// ---------------------------------------------------------------------------
__global__ void __launch_bounds__(256) f32to16Tz_kernel(
    const float* __restrict__ x0, const float* __restrict__ x1,
    __half* __restrict__ y0, __half* __restrict__ y1)
{
    const float* x = blockIdx.z ? x1 : x0;
    __half*      y = blockIdx.z ? y1 : y0;
    __shared__ float tile[32][33];
    const int tx = threadIdx.x & 31;
    const int ty = threadIdx.x >> 5;
    const int bx = blockIdx.x * 32;
    const int by = blockIdx.y * 32;
#pragma unroll
    for (int j = 0; j < 4; j++)
        tile[ty + j * 8][tx] = x[(long)(by + ty + j * 8) * D_MODEL + bx + tx];
    __syncthreads();
#pragma unroll
    for (int j = 0; j < 4; j++)
        y[(long)(bx + ty + j * 8) * D_MODEL + by + tx] =
            __float2half(tile[tx][ty + j * 8]);
}

// ---------------------------------------------------------------------------
// beff[i] = sum_e W[i,e]*bin[e] + badd[i], z-batched over the two folds
// ---------------------------------------------------------------------------
__global__ void __launch_bounds__(256) beffz_kernel(
    const float* __restrict__ W0, const float* __restrict__ bin0,
    const float* __restrict__ badd0, float* __restrict__ out0,
    const float* __restrict__ W1, const float* __restrict__ bin1,
    const float* __restrict__ badd1, float* __restrict__ out1)
{
    const float* W    = blockIdx.z ? W1 : W0;
    const float* bin  = blockIdx.z ? bin1 : bin0;
    const float* badd = blockIdx.z ? badd1 : badd0;
    float* out        = blockIdx.z ? out1 : out0;

    const int row  = blockIdx.x * 8 + (threadIdx.x >> 5);
    const int lane = threadIdx.x & 31;
    const float* w = W + (long)row * D_MODEL;
    float s = 0.0f;
    for (int e = lane * 4; e < D_MODEL; e += 128) {
        const float4 wv = *(const float4*)(w + e);
        const float4 bv = *(const float4*)(bin + e);
        s += wv.x * bv.x + wv.y * bv.y + wv.z * bv.z + wv.w * bv.w;
    }
#pragma unroll
    for (int o = 16; o; o >>= 1) s += __shfl_xor_sync(0xFFFFFFFF, s, o);
    if (lane == 0) out[row] = s + badd[row];
}

// ---------------------------------------------------------------------------
// Zero fill (svec)
// ---------------------------------------------------------------------------
__global__ void __launch_bounds__(256) zero_kernel(float* __restrict__ p, int n)
{
    for (int i = blockIdx.x * 256 + threadIdx.x; i < n; i += gridDim.x * 256)
        p[i] = 0.0f;
}

// ---------------------------------------------------------------------------
// Row softmax over last dim (1024), f16 in-place (one block per row)
// ---------------------------------------------------------------------------
__global__ void __launch_bounds__(256) row_softmax_kernel(__half* __restrict__ X)
{
    const int row = blockIdx.x;
    const int t = threadIdx.x;
    __shared__ float red[256];

    __half* x = X + (long)row * D_MODEL;
    float v[4];
    float m = -1e30f;
#pragma unroll
    for (int i = 0; i < 4; i++) {
        v[i] = __half2float(x[t + i * 256]);
        m = fmaxf(m, v[i]);
    }
    red[t] = m;
    __syncthreads();
    for (int s = 128; s > 0; s >>= 1) {
        if (t < s) red[t] = fmaxf(red[t], red[t + s]);
        __syncthreads();
    }
    m = red[0];
    __syncthreads();

    float sum = 0.0f;
#pragma unroll
    for (int i = 0; i < 4; i++) {
        v[i] = __expf(v[i] - m);
        sum += v[i];
    }
    red[t] = sum;
    __syncthreads();
    for (int s = 128; s > 0; s >>= 1) {
        if (t < s) red[t] += red[t + s];
        __syncthreads();
    }
    const float inv = 1.0f / red[0];
#pragma unroll
    for (int i = 0; i < 4; i++)
        x[t + i * 256] = __float2half(v[i] * inv);
}

// ---------------------------------------------------------------------------
// Column sums of S: svec[b][d] += sum_{q in chunk} S[b][q][d]
// grid (2, 16, NB): x = half2-col block (256 half2), y = q chunk (128 rows)
// ---------------------------------------------------------------------------
__global__ void __launch_bounds__(256) colsum_kernel(
    const __half* __restrict__ S, float* __restrict__ svec)
{
    const int b = blockIdx.z;
    const int e2 = blockIdx.x * 256 + threadIdx.x;     // half2 col, 0..511
    const int q0 = blockIdx.y * 128;
    const __half2* x = (const __half2*)(S + (long)b * TQ * D_MODEL) + e2;
    float sx = 0.0f, sy = 0.0f;
#pragma unroll 4
    for (int q = q0; q < q0 + 128; q++) {
        const float2 v = __half22float2(x[(long)q * (D_MODEL / 2)]);
        sx += v.x; sy += v.y;
    }
    atomicAdd(svec + b * D_MODEL + e2 * 2,     sx);
    atomicAdd(svec + b * D_MODEL + e2 * 2 + 1, sy);
}

// ---------------------------------------------------------------------------
// Column softmax over T_kv (axis=-2), f16 in-place, half2 columns.
// ---------------------------------------------------------------------------
__global__ void __launch_bounds__(256) col_softmax_kernel(__half* __restrict__ X)
{
    const int b = blockIdx.y;
    const int c = threadIdx.x & 31;
    const int s = threadIdx.x >> 5;
    const int e2 = blockIdx.x * 32 + c;

    __half2* x = (__half2*)(X + (long)b * TKV * D_MODEL) + e2;
    __shared__ float2 red[8][32];
    const int LD2 = D_MODEL / 2;

    float mx = -1e30f, my = -1e30f;
    for (int k = s; k < TKV; k += 8) {
        const float2 v = __half22float2(x[(long)k * LD2]);
        mx = fmaxf(mx, v.x); my = fmaxf(my, v.y);
    }
    red[s][c] = make_float2(mx, my);
    __syncthreads();
    if (s == 0) {
        float2 mm = red[0][c];
#pragma unroll
        for (int i = 1; i < 8; i++) {
            mm.x = fmaxf(mm.x, red[i][c].x);
            mm.y = fmaxf(mm.y, red[i][c].y);
        }
        red[0][c] = mm;
    }
    __syncthreads();
    mx = red[0][c].x; my = red[0][c].y;
    __syncthreads();

    float sx = 0.0f, sy = 0.0f;
    for (int k = s; k < TKV; k += 8) {
        const float2 v = __half22float2(x[(long)k * LD2]);
        sx += __expf(v.x - mx); sy += __expf(v.y - my);
    }
    red[s][c] = make_float2(sx, sy);
    __syncthreads();
    if (s == 0) {
        float2 ss = red[0][c];
#pragma unroll
        for (int i = 1; i < 8; i++) {
            ss.x += red[i][c].x; ss.y += red[i][c].y;
        }
        red[0][c] = ss;
    }
    __syncthreads();
    const float ix = 1.0f / red[0][c].x;
    const float iy = 1.0f / red[0][c].y;

    for (int k = s; k < TKV; k += 8) {
        const long idx = (long)k * LD2;
        const float2 v = __half22float2(x[idx]);
        x[idx] = __floats2half2_rn(__expf(v.x - mx) * ix, __expf(v.y - my) * iy);
    }
}

// ---------------------------------------------------------------------------
// Orchestration:
//   WeffU|V = (Wu@Wl | WV@WA), beff folded              [z-batched NT GEMM]
//   logits  = (lat|inp) @ Weff^T + beff (f16)           [z-batched NT GEMM]
//   S = row_softmax(logU) in place; svec = colsum(S)
//   Amat = col_softmax(logV) in place
//   X_b  = S_b^T @ lat_b                    [d2,d]   (TN GEMM)
//   PT_b = Wo @ X_b^T + bo (x) s_b          [e,d2]
//   o_b  = Amat_b @ PT_b^T                  [k,e]    (f32 out)
// ---------------------------------------------------------------------------
extern "C" void kernel_launch(void* const* d_in, const int* in_sizes, int n_in,
                              void* d_out, int out_size)
{
    const float* latent = (const float*)d_in[0];
    const float* input  = (const float*)d_in[1];
    const float* Wl = (const float*)d_in[2];
    const float* bl = (const float*)d_in[3];
    const float* Wu = (const float*)d_in[4];
    const float* bu = (const float*)d_in[5];
    const float* WA = (const float*)d_in[6];
    const float* bA = (const float*)d_in[7];
    const float* WV = (const float*)d_in[8];
    const float* bV = (const float*)d_in[9];
    const float* Wo = (const float*)d_in[10];
    const float* bo = (const float*)d_in[11];
    float* out = (float*)d_out;

    __half *act, *w16, *weff, *logits, *x16, *mt16;
    float *beff, *svec;
    cudaGetSymbolAddress((void**)&act,    g_act);
    cudaGetSymbolAddress((void**)&w16,    g_W16);
    cudaGetSymbolAddress((void**)&weff,   g_Weff);
    cudaGetSymbolAddress((void**)&beff,   g_beff);
    cudaGetSymbolAddress((void**)&logits, g_logits);
    cudaGetSymbolAddress((void**)&x16,    g_X16);
    cudaGetSymbolAddress((void**)&mt16,   g_MT16);
    cudaGetSymbolAddress((void**)&svec,   g_s);

    const long NW = (long)D_MODEL * D_MODEL;
    const long NACT = (long)MQ * D_MODEL;
    __half* Wu16  = w16 + 0 * NW;
    __half* WV16  = w16 + 1 * NW;
    __half* Wo16  = w16 + 2 * NW;
    __half* WlT16 = w16 + 3 * NW;
    __half* WAT16 = w16 + 4 * NW;
    __half* lat16 = act;
    __half* inp16 = act + NACT;
    __half* logU  = logits;
    __half* logV  = logits + NACT;

    cudaFuncSetAttribute(hgemm<0,1>, cudaFuncAttributeMaxDynamicSharedMemorySize, SMEM_BYTES);
    cudaFuncSetAttribute(hgemm<0,0>, cudaFuncAttributeMaxDynamicSharedMemorySize, SMEM_BYTES);
    cudaFuncSetAttribute(hgemm<1,1>, cudaFuncAttributeMaxDynamicSharedMemorySize, SMEM_BYTES);
    cudaFuncSetAttribute(hgemm<3,1>, cudaFuncAttributeMaxDynamicSharedMemorySize, SMEM_BYTES);
    cudaFuncSetAttribute(hgemm_tn,   cudaFuncAttributeMaxDynamicSharedMemorySize, TN_SMEM);

    const dim3 blk(256);

    // Converts (z-batched)
    f32to16z_kernel<<<dim3((int)(NACT / 1024), 1, 2), blk>>>(
        latent, input, nullptr, lat16, inp16, nullptr, (int)NACT);
    f32to16z_kernel<<<dim3((int)(NW / 1024), 1, 3), blk>>>(
        Wu, WV, Wo, Wu16, WV16, Wo16, (int)NW);
    f32to16Tz_kernel<<<dim3(32, 32, 2), blk>>>(Wl, WA, WlT16, WAT16);

    // Folded biases (z-batched) + zero svec
    beffz_kernel<<<dim3(128, 1, 2), blk>>>(Wu, bl, bu, beff,
                                           WV, bA, bV, beff + D_MODEL);
    zero_kernel<<<4, blk>>>(svec, NB * D_MODEL);

    // Weff = (Wu@Wl | WV@WA): z-batched
    hgemm<0,1><<<dim3(4, 8, 2), blk, SMEM_BYTES>>>(
        Wu16, WlT16, nullptr, nullptr, nullptr, weff,
        D_MODEL, D_MODEL, D_MODEL, NW, NW, NW, 0, 0);

    // logits = (lat|inp) @ Weff^T + beff  (f16 out)
    hgemm<1,1><<<dim3(4, 64, 2), blk, SMEM_BYTES>>>(
        act, weff, beff, nullptr, nullptr, logits,
        MQ, D_MODEL, D_MODEL, NACT, NW, NACT, D_MODEL, 0);

    // S = row softmax (in place on logU); svec = column sums of S
    row_softmax_kernel<<<MQ, blk>>>(logU);
    colsum_kernel<<<dim3(2, 16, NB), blk>>>(logU, svec);

    // Amat = col softmax (in place on logV)
    col_softmax_kernel<<<dim3(D_MODEL / 64, NB), blk>>>(logV);

    // X_b = S_b^T @ lat_b   (TN)   M=1024(d2), N=1024(d), K=2048(q)
    hgemm_tn<<<dim3(4, 8, NB), blk, TN_SMEM>>>(
        logU, lat16, x16,
        D_MODEL, D_MODEL, TQ, D_MODEL, D_MODEL,
        (long)TQ * D_MODEL, (long)TQ * D_MODEL, NW);

    // PT_b = Wo @ X_b^T + bo (x) s_b   M=1024(e), N=1024(d2), K=1024(d)
    hgemm<3,1><<<dim3(4, 8, NB), blk, SMEM_BYTES>>>(
        Wo16, x16, bo, svec, nullptr, mt16,
        D_MODEL, D_MODEL, D_MODEL,
        0, NW, NW, 0, (long)D_MODEL);

    // o_b = Amat_b @ PT_b^T   M=2048(k), N=1024(e), K=1024(d2)  (f32 out)
    hgemm<0,0><<<dim3(4, 16, NB), blk, SMEM_BYTES>>>(
        logV, mt16, nullptr, nullptr, out, nullptr,
        TKV, D_MODEL, D_MODEL,
        (long)TKV * D_MODEL, NW, (long)TKV * D_MODEL, 0, 0);
}

// round 14
// speedup vs baseline: 8.4718x; 1.1290x over previous
#include <cuda_runtime.h>
#include <cuda_fp16.h>
#include <cstdint>

#define D_MODEL 1024
#define NB 4
#define TQ 2048
#define TKV 2048
#define MQ (NB * TQ)

// ---------------------------------------------------------------------------
// Static scratch (no runtime allocation allowed)
// ---------------------------------------------------------------------------
__device__ __half g_act   [2 * MQ * D_MODEL];        // lat16 | inp16   (32 MB)
__device__ __half g_W16   [5 * D_MODEL * D_MODEL];   // Wu, WV, Wo, Wl^T, WA^T
__device__ __half g_Weff  [2 * D_MODEL * D_MODEL];   // Wu@Wl | WV@WA
__device__ float  g_beff  [2 * D_MODEL];             // folded biases
__device__ __half g_logits[2 * MQ * D_MODEL];        // u | V logits f16 (32 MB)
__device__ __half g_X16   [NB * D_MODEL * D_MODEL];  // X = S^T@lat     ( 8 MB)
__device__ __half g_MT16  [NB * D_MODEL * D_MODEL];  // P^T [b][e][d]   ( 8 MB)
__device__ float  g_s     [NB * D_MODEL];            // s[d] = sum_q S[q,d]

// ---------------------------------------------------------------------------
// PTX helpers
// ---------------------------------------------------------------------------
__device__ __forceinline__ uint32_t smem_u32(const void* p) {
    uint32_t a;
    asm("{ .reg .u64 t; cvta.to.shared.u64 t, %1; cvt.u32.u64 %0, t; }"
        : "=r"(a) : "l"(p));
    return a;
}
__device__ __forceinline__ void cp_async16(uint32_t smem, const void* g) {
    asm volatile("cp.async.cg.shared.global [%0], [%1], 16;\n" :: "r"(smem), "l"(g));
}
__device__ __forceinline__ void cp_commit() {
    asm volatile("cp.async.commit_group;\n" ::: "memory");
}
template <int N>
__device__ __forceinline__ void cp_wait() {
    asm volatile("cp.async.wait_group %0;\n" :: "n"(N) : "memory");
}
#define LDSM_X4(r, a)                                                         \
    asm volatile("ldmatrix.sync.aligned.m8n8.x4.shared.b16 {%0,%1,%2,%3}, [%4];" \
        : "=r"((r)[0]), "=r"((r)[1]), "=r"((r)[2]), "=r"((r)[3]) : "r"(a))
#define LDSM_X4_T(r, a)                                                       \
    asm volatile("ldmatrix.sync.aligned.m8n8.x4.trans.shared.b16 {%0,%1,%2,%3}, [%4];" \
        : "=r"((r)[0]), "=r"((r)[1]), "=r"((r)[2]), "=r"((r)[3]) : "r"(a))

__device__ __forceinline__ void mma16816(float* c, const uint32_t* a,
                                         uint32_t b0, uint32_t b1) {
    asm volatile(
        "mma.sync.aligned.m16n8k16.row.col.f32.f16.f16.f32 "
        "{%0,%1,%2,%3}, {%4,%5,%6,%7}, {%8,%9}, {%0,%1,%2,%3};\n"
        : "+f"(c[0]), "+f"(c[1]), "+f"(c[2]), "+f"(c[3])
        : "r"(a[0]), "r"(a[1]), "r"(a[2]), "r"(a[3]), "r"(b0), "r"(b1));
}

// ---------------------------------------------------------------------------
// FP16 NT-GEMM: C[M,N] = A[M,K] @ B[N,K]^T (+ bias); A,B K-major __half.
// Block tile 128(M) x BN(N) x 32(K halves); BN in {128, 256}. 256 threads,
// 8 warps = 2(M) x 4(N); warp tile 64 x BN/4. 5-stage cp.async pipeline,
// one __syncthreads per k-tile, double-buffered register fragments.
// BIAS: 0 none, 1 bias[col] (per-z via sBias), 3 outer bias[row]*bias2[col].
// F16OUT: 1 -> Ch, 0 -> Cf.
// ---------------------------------------------------------------------------
#define BKH 32                      // K halves per stage
#define ROWB 80                     // bytes per smem row (32 halves + pad)
#define A_BYTES (128 * ROWB)        // 10240
#define NSTAGE 5

template <int BIAS, int F16OUT, int BN>
__global__ void __launch_bounds__(256, 1) hgemm(
    const __half* __restrict__ A, const __half* __restrict__ B,
    const float* __restrict__ bias, const float* __restrict__ bias2,
    float* __restrict__ Cf, __half* __restrict__ Ch,
    int M, int N, int K, long sA, long sB, long sC, long sBias, long sBias2)
{
    constexpr int NT = BN / 32;          // n-subtiles per warp (8 or 4)
    constexpr int NP = NT / 2;           // b-fragment pairs
    constexpr int B_BYTES = BN * ROWB;
    constexpr int STAGEB = A_BYTES + B_BYTES;
    constexpr int WNC = BN / 4;          // cols per warp

    A += (long)blockIdx.z * sA;
    B += (long)blockIdx.z * sB;
    if (BIAS) bias += (long)blockIdx.z * sBias;
    if (BIAS == 3) bias2 += (long)blockIdx.z * sBias2;

    extern __shared__ char smem[];
    const uint32_t sbase = smem_u32(smem);

    const int tid  = threadIdx.x;
    const int lane = tid & 31;
    const int warp = tid >> 5;
    const int wm   = warp & 1;
    const int wn   = warp >> 1;

    const int bm = blockIdx.y * 128;
    const int bn = blockIdx.x * BN;

    auto issue = [&](int stage, int k0) {
        const __half* Ab = A + (long)bm * K + k0;
        const __half* Bb = B + (long)bn * K + k0;
        const uint32_t sa = sbase + stage * STAGEB;
        const uint32_t sb = sa + A_BYTES;
#pragma unroll
        for (int i = 0; i < 2; i++) {
            const int c = tid + i * 256;
            const int r = c >> 2, kc = c & 3;
            cp_async16(sa + r * ROWB + kc * 16, Ab + (long)r * K + kc * 8);
        }
#pragma unroll
        for (int i = 0; i < BN / 64; i++) {
            const int c = tid + i * 256;
            const int r = c >> 2, kc = c & 3;
            cp_async16(sb + r * ROWB + kc * 16, Bb + (long)r * K + kc * 8);
        }
        cp_commit();
    };

    float acc[4][NT][4];
#pragma unroll
    for (int i = 0; i < 4; i++)
#pragma unroll
        for (int j = 0; j < NT; j++)
#pragma unroll
            for (int r = 0; r < 4; r++) acc[i][j][r] = 0.0f;

    const int T = K / BKH;
    issue(0, 0);
    issue(1, BKH);
    issue(2, 2 * BKH);

    const int aRow = wm * 64 + (lane & 15);
    const int aKB  = (lane >> 4) * 16;
    const int bRow = wn * WNC + ((lane >> 4) & 1) * 8 + (lane & 7);
    const int bKB  = ((lane >> 3) & 1) * 16;

    uint32_t af[2][4][4], bf[2][NP][4];

    for (int t = 0; t < T; t++) {
        if (t + 3 < T) { issue((t + 3) % NSTAGE, (t + 3) * BKH); cp_wait<3>(); }
        else           { cp_wait<0>(); }
        __syncthreads();

        const uint32_t sa = sbase + (t % NSTAGE) * STAGEB;
        const uint32_t sb = sa + A_BYTES;

#pragma unroll
        for (int mt = 0; mt < 4; mt++)
            LDSM_X4(af[0][mt], sa + (aRow + mt * 16) * ROWB + aKB);
#pragma unroll
        for (int np = 0; np < NP; np++)
            LDSM_X4(bf[0][np], sb + (bRow + np * 16) * ROWB + bKB);
#pragma unroll
        for (int mt = 0; mt < 4; mt++)
            LDSM_X4(af[1][mt], sa + (aRow + mt * 16) * ROWB + 32 + aKB);
#pragma unroll
        for (int np = 0; np < NP; np++)
            LDSM_X4(bf[1][np], sb + (bRow + np * 16) * ROWB + 32 + bKB);

#pragma unroll
        for (int kk = 0; kk < 2; kk++)
#pragma unroll
            for (int mt = 0; mt < 4; mt++)
#pragma unroll
                for (int nt = 0; nt < NT; nt++)
                    mma16816(acc[mt][nt], af[kk][mt],
                             bf[kk][nt >> 1][(nt & 1) * 2],
                             bf[kk][nt >> 1][(nt & 1) * 2 + 1]);
    }

#pragma unroll
    for (int mt = 0; mt < 4; mt++) {
        const int row0 = bm + wm * 64 + mt * 16 + (lane >> 2);
        const float rb0 = (BIAS == 3) ? bias[row0] : 0.0f;
        const float rb1 = (BIAS == 3) ? bias[row0 + 8] : 0.0f;
#pragma unroll
        for (int nt = 0; nt < NT; nt++) {
            const int col = bn + wn * WNC + nt * 8 + (lane & 3) * 2;
            float b0x = 0.f, b0y = 0.f, b1x = 0.f, b1y = 0.f;
            if (BIAS == 1) {
                const float2 bb = *(const float2*)(bias + col);
                b0x = bb.x; b0y = bb.y; b1x = bb.x; b1y = bb.y;
            } else if (BIAS == 3) {
                const float2 sv = *(const float2*)(bias2 + col);
                b0x = rb0 * sv.x; b0y = rb0 * sv.y;
                b1x = rb1 * sv.x; b1y = rb1 * sv.y;
            }
            const float c0 = acc[mt][nt][0] + b0x;
            const float c1 = acc[mt][nt][1] + b0y;
            const float c2 = acc[mt][nt][2] + b1x;
            const float c3 = acc[mt][nt][3] + b1y;
            if (F16OUT) {
                __half* p = Ch + (long)blockIdx.z * sC + (long)row0 * N + col;
                *(__half2*)p                 = __floats2half2_rn(c0, c1);
                *(__half2*)(p + (long)8 * N) = __floats2half2_rn(c2, c3);
            } else {
                float* p = Cf + (long)blockIdx.z * sC + (long)row0 * N + col;
                *(float2*)p                 = make_float2(c0, c1);
                *(float2*)(p + (long)8 * N) = make_float2(c2, c3);
            }
        }
    }
}

#define SMEM_256 (NSTAGE * (A_BYTES + 256 * ROWB))   // 153600
#define SMEM_128 (NSTAGE * (A_BYTES + 128 * ROWB))   // 102400

// ---------------------------------------------------------------------------
// FP16 TN-GEMM: C[M,N] = A^T @ B with A stored [K,M], B stored [K,N] (f16).
// Both operands via ldmatrix.trans. Frag double-buffered.
// ---------------------------------------------------------------------------
#define TN_RA 272                    // 128 halves + 16B pad
#define TN_RB 528                    // 256 halves + 16B pad
#define TN_AB (32 * TN_RA)           // 8704
#define TN_BB (32 * TN_RB)           // 16896
#define TN_STAGE (TN_AB + TN_BB)     // 25600
#define TN_SMEM (NSTAGE * TN_STAGE)  // 128000

__global__ void __launch_bounds__(256, 1) hgemm_tn(
    const __half* __restrict__ A, const __half* __restrict__ B,
    __half* __restrict__ Ch,
    int M, int N, int K, int lda, int ldb, long sA, long sB, long sC)
{
    A += (long)blockIdx.z * sA;
    B += (long)blockIdx.z * sB;

    extern __shared__ char smem[];
    const uint32_t sbase = smem_u32(smem);

    const int tid  = threadIdx.x;
    const int lane = tid & 31;
    const int warp = tid >> 5;
    const int wm   = warp & 1;
    const int wn   = warp >> 1;

    const int bm = blockIdx.y * 128;
    const int bn = blockIdx.x * 256;

    auto issue = [&](int stage, int k0) {
        const __half* Ab = A + (long)k0 * lda + bm;
        const __half* Bb = B + (long)k0 * ldb + bn;
        const uint32_t sa = sbase + stage * TN_STAGE;
        const uint32_t sb = sa + TN_AB;
#pragma unroll
        for (int i = 0; i < 2; i++) {
            const int c = tid + i * 256;
            const int r = c >> 4, kc = c & 15;
            cp_async16(sa + r * TN_RA + kc * 16, Ab + (long)r * lda + kc * 8);
        }
#pragma unroll
        for (int i = 0; i < 4; i++) {
            const int c = tid + i * 256;
            const int r = c >> 5, kc = c & 31;
            cp_async16(sb + r * TN_RB + kc * 16, Bb + (long)r * ldb + kc * 8);
        }
        cp_commit();
    };

    float acc[4][8][4];
#pragma unroll
    for (int i = 0; i < 4; i++)
#pragma unroll
        for (int j = 0; j < 8; j++)
#pragma unroll
            for (int r = 0; r < 4; r++) acc[i][j][r] = 0.0f;

    const int T = K / BKH;
    issue(0, 0);
    issue(1, BKH);
    issue(2, 2 * BKH);

    const int aK  = (lane & 7) + ((lane >> 4) & 1) * 8;
    const int aM2 = (wm * 64 + ((lane >> 3) & 1) * 8) * 2;
    const int bK  = (lane & 7) + ((lane >> 3) & 1) * 8;
    const int bN2 = (wn * 64 + (lane >> 4) * 8) * 2;

    uint32_t af[2][4][4], bf[2][4][4];

    for (int t = 0; t < T; t++) {
        if (t + 3 < T) { issue((t + 3) % NSTAGE, (t + 3) * BKH); cp_wait<3>(); }
        else           { cp_wait<0>(); }
        __syncthreads();

        const uint32_t sa = sbase + (t % NSTAGE) * TN_STAGE;
        const uint32_t sb = sa + TN_AB;

#pragma unroll
        for (int mt = 0; mt < 4; mt++)
            LDSM_X4_T(af[0][mt], sa + aK * TN_RA + aM2 + mt * 32);
#pragma unroll
        for (int np = 0; np < 4; np++)
            LDSM_X4_T(bf[0][np], sb + bK * TN_RB + bN2 + np * 32);
#pragma unroll
        for (int mt = 0; mt < 4; mt++)
            LDSM_X4_T(af[1][mt], sa + (16 + aK) * TN_RA + aM2 + mt * 32);
#pragma unroll
        for (int np = 0; np < 4; np++)
            LDSM_X4_T(bf[1][np], sb + (16 + bK) * TN_RB + bN2 + np * 32);

#pragma unroll
        for (int kk = 0; kk < 2; kk++)
#pragma unroll
            for (int mt = 0; mt < 4; mt++)
#pragma unroll
                for (int nt = 0; nt < 8; nt++)
                    mma16816(acc[mt][nt], af[kk][mt],
                             bf[kk][nt >> 1][(nt & 1) * 2],
                             bf[kk][nt >> 1][(nt & 1) * 2 + 1]);
    }

#pragma unroll
    for (int mt = 0; mt < 4; mt++) {
        const int row0 = bm + wm * 64 + mt * 16 + (lane >> 2);
#pragma unroll
        for (int nt = 0; nt < 8; nt++) {
            const int col = bn + wn * 64 + nt * 8 + (lane & 3) * 2;
            __half* p = Ch + (long)blockIdx.z * sC + (long)row0 * N + col;
            *(__half2*)p = __floats2half2_rn(acc[mt][nt][0], acc[mt][nt][1]);
            *(__half2*)(p + (long)8 * N) =
                __floats2half2_rn(acc[mt][nt][2], acc[mt][nt][3]);
        }
    }
}

// ---------------------------------------------------------------------------
// f32 -> f16 conversion, z-batched over up to 3 tensors
// ---------------------------------------------------------------------------
__global__ void __launch_bounds__(256) f32to16z_kernel(
    const float* __restrict__ x0, const float* __restrict__ x1,
    const float* __restrict__ x2,
    __half* __restrict__ y0, __half* __restrict__ y1, __half* __restrict__ y2,
    int n)
{
    const float* x = (blockIdx.z == 0) ? x0 : (blockIdx.z == 1) ? x1 : x2;
    __half*      y = (blockIdx.z == 0) ? y0 : (blockIdx.z == 1) ? y1 : y2;
    const int i = (blockIdx.x * 256 + threadIdx.x) * 4;
    if (i < n) {
        const float4 v = *(const float4*)(x + i);
        *(__half2*)(y + i)     = __floats2half2_rn(v.x, v.y);
        *(__half2*)(y + i + 2) = __floats2half2_rn(v.z, v.w);
    }
}

// ---------------------------------------------------------------------------
// f32 [1024,1024] -> transposed f16, z-batched over 2 tensors
// ---------------------------------------------------------------------------
__global__ void __launch_bounds__(256) f32to16Tz_kernel(
    const float* __restrict__ x0, const float* __restrict__ x1,
    __half* __restrict__ y0, __half* __restrict__ y1)
{
    const float* x = blockIdx.z ? x1 : x0;
    __half*      y = blockIdx.z ? y1 : y0;
    __shared__ float tile[32][33];
    const int tx = threadIdx.x & 31;
    const int ty = threadIdx.x >> 5;
    const int bx = blockIdx.x * 32;
    const int by = blockIdx.y * 32;
#pragma unroll
    for (int j = 0; j < 4; j++)
        tile[ty + j * 8][tx] = x[(long)(by + ty + j * 8) * D_MODEL + bx + tx];
    __syncthreads();
#pragma unroll
    for (int j = 0; j < 4; j++)
        y[(long)(bx + ty + j * 8) * D_MODEL + by + tx] =
            __float2half(tile[tx][ty + j * 8]);
}

// ---------------------------------------------------------------------------
// beff[i] = sum_e W[i,e]*bin[e] + badd[i], z-batched; block (0,z=0) also
// zeroes svec (ordered before colsum by stream order).
// ---------------------------------------------------------------------------
__global__ void __launch_bounds__(256) beffz_kernel(
    const float* __restrict__ W0, const float* __restrict__ bin0,
    const float* __restrict__ badd0, float* __restrict__ out0,
    const float* __restrict__ W1, const float* __restrict__ bin1,
    const float* __restrict__ badd1, float* __restrict__ out1,
    float* __restrict__ svec)
{
    if (blockIdx.z == 0 && blockIdx.x == 0) {
        for (int i = threadIdx.x; i < NB * D_MODEL; i += 256) svec[i] = 0.0f;
    }
    const float* W    = blockIdx.z ? W1 : W0;
    const float* bin  = blockIdx.z ? bin1 : bin0;
    const float* badd = blockIdx.z ? badd1 : badd0;
    float* out        = blockIdx.z ? out1 : out0;

    const int row  = blockIdx.x * 8 + (threadIdx.x >> 5);
    const int lane = threadIdx.x & 31;
    const float* w = W + (long)row * D_MODEL;
    float s = 0.0f;
    for (int e = lane * 4; e < D_MODEL; e += 128) {
        const float4 wv = *(const float4*)(w + e);
        const float4 bv = *(const float4*)(bin + e);
        s += wv.x * bv.x + wv.y * bv.y + wv.z * bv.z + wv.w * bv.w;
    }
#pragma unroll
    for (int o = 16; o; o >>= 1) s += __shfl_xor_sync(0xFFFFFFFF, s, o);
    if (lane == 0) out[row] = s + badd[row];
}

// ---------------------------------------------------------------------------
// Row softmax over last dim (1024), f16 in-place. Warp per row (shuffle
// reductions, no smem, no block barriers). 8 rows per block.
// ---------------------------------------------------------------------------
__global__ void __launch_bounds__(256) row_softmax_kernel(__half* __restrict__ X)
{
    const int row  = blockIdx.x * 8 + (threadIdx.x >> 5);
    const int lane = threadIdx.x & 31;
    __half2* x = (__half2*)(X + (long)row * D_MODEL);

    float2 v[16];
    float m = -1e30f;
#pragma unroll
    for (int i = 0; i < 16; i++) {
        v[i] = __half22float2(x[lane + i * 32]);
        m = fmaxf(m, fmaxf(v[i].x, v[i].y));
    }
#pragma unroll
    for (int o = 16; o; o >>= 1) m = fmaxf(m, __shfl_xor_sync(0xFFFFFFFF, m, o));

    float sum = 0.0f;
#pragma unroll
    for (int i = 0; i < 16; i++) {
        v[i].x = __expf(v[i].x - m);
        v[i].y = __expf(v[i].y - m);
        sum += v[i].x + v[i].y;
    }
#pragma unroll
    for (int o = 16; o; o >>= 1) sum += __shfl_xor_sync(0xFFFFFFFF, sum, o);
    const float inv = 1.0f / sum;

#pragma unroll
    for (int i = 0; i < 16; i++)
        x[lane + i * 32] = __floats2half2_rn(v[i].x * inv, v[i].y * inv);
}

// ---------------------------------------------------------------------------
// Column sums of S: svec[b][d] += sum_{q in chunk} S[b][q][d]
// grid (2, 16, NB): x = half2-col block (256 half2), y = q chunk (128 rows)
// ---------------------------------------------------------------------------
__global__ void __launch_bounds__(256) colsum_kernel(
    const __half* __restrict__ S, float* __restrict__ svec)
{
    const int b = blockIdx.z;
    const int e2 = blockIdx.x * 256 + threadIdx.x;
    const int q0 = blockIdx.y * 128;
    const __half2* x = (const __half2*)(S + (long)b * TQ * D_MODEL) + e2;
    float sx = 0.0f, sy = 0.0f;
#pragma unroll 4
    for (int q = q0; q < q0 + 128; q++) {
        const float2 v = __half22float2(x[(long)q * (D_MODEL / 2)]);
        sx += v.x; sy += v.y;
    }
    atomicAdd(svec + b * D_MODEL + e2 * 2,     sx);
    atomicAdd(svec + b * D_MODEL + e2 * 2 + 1, sy);
}

// ---------------------------------------------------------------------------
// Column softmax over T_kv (axis=-2), f16 in-place, half2 columns.
// 1024 threads: 32 half2-cols x 32 threads/col (4x the memory parallelism
// of the 256-thread version; launch is only 64 blocks so threads are the
// only way to add parallelism without cross-block reduction).
// ---------------------------------------------------------------------------
__global__ void __launch_bounds__(1024) col_softmax_kernel(__half* __restrict__ X)
{
    const int b = blockIdx.y;
    const int c = threadIdx.x & 31;
    const int s = threadIdx.x >> 5;            // 0..31
    const int e2 = blockIdx.x * 32 + c;

    __half2* x = (__half2*)(X + (long)b * TKV * D_MODEL) + e2;
    __shared__ float2 red[32][32];
    const int LD2 = D_MODEL / 2;

    float mx = -1e30f, my = -1e30f;
    for (int k = s; k < TKV; k += 32) {
        const float2 v = __half22float2(x[(long)k * LD2]);
        mx = fmaxf(mx, v.x); my = fmaxf(my, v.y);
    }
    red[s][c] = make_float2(mx, my);
    __syncthreads();
    if (s == 0) {
        float2 mm = red[0][c];
#pragma unroll
        for (int i = 1; i < 32; i++) {
            mm.x = fmaxf(mm.x, red[i][c].x);
            mm.y = fmaxf(mm.y, red[i][c].y);
        }
        red[0][c] = mm;
    }
    __syncthreads();
    mx = red[0][c].x; my = red[0][c].y;
    __syncthreads();

    float sx = 0.0f, sy = 0.0f;
    for (int k = s; k < TKV; k += 32) {
        const float2 v = __half22float2(x[(long)k * LD2]);
        sx += __expf(v.x - mx); sy += __expf(v.y - my);
    }
    red[s][c] = make_float2(sx, sy);
    __syncthreads();
    if (s == 0) {
        float2 ss = red[0][c];
#pragma unroll
        for (int i = 1; i < 32; i++) {
            ss.x += red[i][c].x; ss.y += red[i][c].y;
        }
        red[0][c] = ss;
    }
    __syncthreads();
    const float ix = 1.0f / red[0][c].x;
    const float iy = 1.0f / red[0][c].y;

    for (int k = s; k < TKV; k += 32) {
        const long idx = (long)k * LD2;
        const float2 v = __half22float2(x[idx]);
        x[idx] = __floats2half2_rn(__expf(v.x - mx) * ix, __expf(v.y - my) * iy);
    }
}

// ---------------------------------------------------------------------------
// Orchestration:
//   WeffU|V = (Wu@Wl | WV@WA), beff folded        [z-batched NT GEMM, BN=128]
//   logits  = (lat|inp) @ Weff^T + beff (f16)     [z-batched NT GEMM, BN=256]
//   S = row_softmax(logU) in place; svec = colsum(S)
//   Amat = col_softmax(logV) in place
//   X_b  = S_b^T @ lat_b                    [d2,d]   (TN GEMM)
//   PT_b = Wo @ X_b^T + bo (x) s_b          [e,d2]
//   o_b  = Amat_b @ PT_b^T                  [k,e]    (f32 out)
// ---------------------------------------------------------------------------
extern "C" void kernel_launch(void* const* d_in, const int* in_sizes, int n_in,
                              void* d_out, int out_size)
{
    const float* latent = (const float*)d_in[0];
    const float* input  = (const float*)d_in[1];
    const float* Wl = (const float*)d_in[2];
    const float* bl = (const float*)d_in[3];
    const float* Wu = (const float*)d_in[4];
    const float* bu = (const float*)d_in[5];
    const float* WA = (const float*)d_in[6];
    const float* bA = (const float*)d_in[7];
    const float* WV = (const float*)d_in[8];
    const float* bV = (const float*)d_in[9];
    const float* Wo = (const float*)d_in[10];
    const float* bo = (const float*)d_in[11];
    float* out = (float*)d_out;

    __half *act, *w16, *weff, *logits, *x16, *mt16;
    float *beff, *svec;
    cudaGetSymbolAddress((void**)&act,    g_act);
    cudaGetSymbolAddress((void**)&w16,    g_W16);
    cudaGetSymbolAddress((void**)&weff,   g_Weff);
    cudaGetSymbolAddress((void**)&beff,   g_beff);
    cudaGetSymbolAddress((void**)&logits, g_logits);
    cudaGetSymbolAddress((void**)&x16,    g_X16);
    cudaGetSymbolAddress((void**)&mt16,   g_MT16);
    cudaGetSymbolAddress((void**)&svec,   g_s);

    const long NW = (long)D_MODEL * D_MODEL;
    const long NACT = (long)MQ * D_MODEL;
    __half* Wu16  = w16 + 0 * NW;
    __half* WV16  = w16 + 1 * NW;
    __half* Wo16  = w16 + 2 * NW;
    __half* WlT16 = w16 + 3 * NW;
    __half* lat16 = act;
    __half* inp16 = act + NACT;
    __half* logU  = logits;
    __half* logV  = logits + NACT;

    cudaFuncSetAttribute(hgemm<0,1,128>, cudaFuncAttributeMaxDynamicSharedMemorySize, SMEM_128);
    cudaFuncSetAttribute(hgemm<1,1,256>, cudaFuncAttributeMaxDynamicSharedMemorySize, SMEM_256);
    cudaFuncSetAttribute(hgemm<3,1,256>, cudaFuncAttributeMaxDynamicSharedMemorySize, SMEM_256);
    cudaFuncSetAttribute(hgemm<0,0,256>, cudaFuncAttributeMaxDynamicSharedMemorySize, SMEM_256);
    cudaFuncSetAttribute(hgemm_tn, cudaFuncAttributeMaxDynamicSharedMemorySize, TN_SMEM);

    const dim3 blk(256);

    // Converts (z-batched)
    f32to16z_kernel<<<dim3((int)(NACT / 1024), 1, 2), blk>>>(
        latent, input, nullptr, lat16, inp16, nullptr, (int)NACT);
    f32to16z_kernel<<<dim3((int)(NW / 1024), 1, 3), blk>>>(
        Wu, WV, Wo, Wu16, WV16, Wo16, (int)NW);
    f32to16Tz_kernel<<<dim3(32, 32, 2), blk>>>(Wl, WA, WlT16, WlT16 + NW);

    // Folded biases (z-batched; also zeroes svec)
    beffz_kernel<<<dim3(128, 1, 2), blk>>>(Wu, bl, bu, beff,
                                           WV, bA, bV, beff + D_MODEL, svec);

    // Weff = (Wu@Wl | WV@WA): z-batched, BN=128 -> 128 CTAs (fills chip)
    hgemm<0,1,128><<<dim3(8, 8, 2), blk, SMEM_128>>>(
        Wu16, WlT16, nullptr, nullptr, nullptr, weff,
        D_MODEL, D_MODEL, D_MODEL, NW, NW, NW, 0, 0);

    // logits = (lat|inp) @ Weff^T + beff  (f16 out)
    hgemm<1,1,256><<<dim3(4, 64, 2), blk, SMEM_256>>>(
        act, weff, beff, nullptr, nullptr, logits,
        MQ, D_MODEL, D_MODEL, NACT, NW, NACT, D_MODEL, 0);

    // S = row softmax (in place on logU); svec = column sums of S
    row_softmax_kernel<<<MQ / 8, blk>>>(logU);
    colsum_kernel<<<dim3(2, 16, NB), blk>>>(logU, svec);

    // Amat = col softmax (in place on logV)
    col_softmax_kernel<<<dim3(D_MODEL / 64, NB), 1024>>>(logV);

    // X_b = S_b^T @ lat_b   (TN)   M=1024(d2), N=1024(d), K=2048(q)
    hgemm_tn<<<dim3(4, 8, NB), blk, TN_SMEM>>>(
        logU, lat16, x16,
        D_MODEL, D_MODEL, TQ, D_MODEL, D_MODEL,
        (long)TQ * D_MODEL, (long)TQ * D_MODEL, NW);

    // PT_b = Wo @ X_b^T + bo (x) s_b   M=1024(e), N=1024(d2), K=1024(d)
    hgemm<3,1,256><<<dim3(4, 8, NB), blk, SMEM_256>>>(
        Wo16, x16, bo, svec, nullptr, mt16,
        D_MODEL, D_MODEL, D_MODEL,
        0, NW, NW, 0, (long)D_MODEL);

    // o_b = Amat_b @ PT_b^T   M=2048(k), N=1024(e), K=1024(d2)  (f32 out)
    hgemm<0,0,256><<<dim3(4, 16, NB), blk, SMEM_256>>>(
        logV, mt16, nullptr, nullptr, out, nullptr,
        TKV, D_MODEL, D_MODEL,
        (long)TKV * D_MODEL, NW, (long)TKV * D_MODEL, 0, 0);
}

// round 16
// speedup vs baseline: 9.1082x; 1.0751x over previous
#include <cuda_runtime.h>
#include <cuda_fp16.h>
#include <cstdint>

#define D_MODEL 1024
#define NB 4
#define TQ 2048
#define TKV 2048
#define MQ (NB * TQ)

// ---------------------------------------------------------------------------
// Static scratch (no runtime allocation allowed)
// ---------------------------------------------------------------------------
__device__ __half g_act   [2 * MQ * D_MODEL];        // lat16 | inp16   (32 MB)
__device__ __half g_W16   [5 * D_MODEL * D_MODEL];   // Wu, WV, Wo, Wl^T, WA^T
__device__ __half g_Weff  [2 * D_MODEL * D_MODEL];   // Wu@Wl | WV@WA
__device__ float  g_beff  [2 * D_MODEL];             // folded biases
__device__ __half g_logits[2 * MQ * D_MODEL];        // u | V logits f16 (32 MB)
__device__ __half g_X16   [NB * D_MODEL * D_MODEL];  // X = S^T@lat     ( 8 MB)
__device__ __half g_MT16  [NB * D_MODEL * D_MODEL];  // P^T [b][e][d]   ( 8 MB)
__device__ float  g_s     [NB * D_MODEL];            // s[d] = sum_q S[q,d]

// ---------------------------------------------------------------------------
// PTX helpers
// ---------------------------------------------------------------------------
__device__ __forceinline__ uint32_t smem_u32(const void* p) {
    uint32_t a;
    asm("{ .reg .u64 t; cvta.to.shared.u64 t, %1; cvt.u32.u64 %0, t; }"
        : "=r"(a) : "l"(p));
    return a;
}
__device__ __forceinline__ void cp_async16(uint32_t smem, const void* g) {
    asm volatile("cp.async.cg.shared.global [%0], [%1], 16;\n" :: "r"(smem), "l"(g));
}
__device__ __forceinline__ void cp_commit() {
    asm volatile("cp.async.commit_group;\n" ::: "memory");
}
template <int N>
__device__ __forceinline__ void cp_wait() {
    asm volatile("cp.async.wait_group %0;\n" :: "n"(N) : "memory");
}
#define LDSM_X4(r, a)                                                         \
    asm volatile("ldmatrix.sync.aligned.m8n8.x4.shared.b16 {%0,%1,%2,%3}, [%4];" \
        : "=r"((r)[0]), "=r"((r)[1]), "=r"((r)[2]), "=r"((r)[3]) : "r"(a))
#define LDSM_X4_T(r, a)                                                       \
    asm volatile("ldmatrix.sync.aligned.m8n8.x4.trans.shared.b16 {%0,%1,%2,%3}, [%4];" \
        : "=r"((r)[0]), "=r"((r)[1]), "=r"((r)[2]), "=r"((r)[3]) : "r"(a))

__device__ __forceinline__ void mma16816(float* c, const uint32_t* a,
                                         uint32_t b0, uint32_t b1) {
    asm volatile(
        "mma.sync.aligned.m16n8k16.row.col.f32.f16.f16.f32 "
        "{%0,%1,%2,%3}, {%4,%5,%6,%7}, {%8,%9}, {%0,%1,%2,%3};\n"
        : "+f"(c[0]), "+f"(c[1]), "+f"(c[2]), "+f"(c[3])
        : "r"(a[0]), "r"(a[1]), "r"(a[2]), "r"(a[3]), "r"(b0), "r"(b1));
}

// ---------------------------------------------------------------------------
// FP16 NT-GEMM: C[M,N] = A[M,K] @ B[N,K]^T (+ bias); A,B K-major __half.
// Block tile 128(M) x BN(N) x 64(K halves); BN in {128, 256}. 256 threads,
// 8 warps = 2(M) x 4(N); warp tile 64 x BN/4. 4-stage cp.async pipeline
// (issue t+2 at loop top; one barrier per k-tile -- 4 stages is the minimum
// safe count for skew<=1), double-buffered register fragments over 4 k16
// steps. BIAS: 0 none, 1 bias[col], 3 outer bias[row]*bias2[col].
// F16OUT: 1 -> Ch, 0 -> Cf.
// ---------------------------------------------------------------------------
#define BKH 64                      // K halves per stage
#define ROWB 144                    // bytes per smem row (64 halves + 16B pad)
#define A_BYTES (128 * ROWB)        // 18432
#define NSTAGE 4

template <int BIAS, int F16OUT, int BN>
__global__ void __launch_bounds__(256, 1) hgemm(
    const __half* __restrict__ A, const __half* __restrict__ B,
    const float* __restrict__ bias, const float* __restrict__ bias2,
    float* __restrict__ Cf, __half* __restrict__ Ch,
    int M, int N, int K, long sA, long sB, long sC, long sBias, long sBias2)
{
    constexpr int NT = BN / 32;          // n-subtiles per warp (8 or 4)
    constexpr int NP = NT / 2;           // b-fragment pairs
    constexpr int B_BYTES = BN * ROWB;
    constexpr int STAGEB = A_BYTES + B_BYTES;
    constexpr int WNC = BN / 4;          // cols per warp

    A += (long)blockIdx.z * sA;
    B += (long)blockIdx.z * sB;
    if (BIAS) bias += (long)blockIdx.z * sBias;
    if (BIAS == 3) bias2 += (long)blockIdx.z * sBias2;

    extern __shared__ char smem[];
    const uint32_t sbase = smem_u32(smem);

    const int tid  = threadIdx.x;
    const int lane = tid & 31;
    const int warp = tid >> 5;
    const int wm   = warp & 1;
    const int wn   = warp >> 1;

    const int bm = blockIdx.y * 128;
    const int bn = blockIdx.x * BN;

    auto issue = [&](int stage, int k0) {
        const __half* Ab = A + (long)bm * K + k0;
        const __half* Bb = B + (long)bn * K + k0;
        const uint32_t sa = sbase + stage * STAGEB;
        const uint32_t sb = sa + A_BYTES;
#pragma unroll
        for (int i = 0; i < 4; i++) {            // A: 128 rows x 8 chunks
            const int c = tid + i * 256;
            const int r = c >> 3, kc = c & 7;
            cp_async16(sa + r * ROWB + kc * 16, Ab + (long)r * K + kc * 8);
        }
#pragma unroll
        for (int i = 0; i < BN / 32; i++) {      // B: BN rows x 8 chunks
            const int c = tid + i * 256;
            const int r = c >> 3, kc = c & 7;
            cp_async16(sb + r * ROWB + kc * 16, Bb + (long)r * K + kc * 8);
        }
        cp_commit();
    };

    float acc[4][NT][4];
#pragma unroll
    for (int i = 0; i < 4; i++)
#pragma unroll
        for (int j = 0; j < NT; j++)
#pragma unroll
            for (int r = 0; r < 4; r++) acc[i][j][r] = 0.0f;

    const int T = K / BKH;
    issue(0, 0);
    issue(1, BKH);

    const int aRow = wm * 64 + (lane & 15);
    const int aKB  = (lane >> 4) * 16;
    const int bRow = wn * WNC + ((lane >> 4) & 1) * 8 + (lane & 7);
    const int bKB  = ((lane >> 3) & 1) * 16;

    uint32_t af[2][4][4], bf[2][NP][4];

    for (int t = 0; t < T; t++) {
        if (t + 2 < T) { issue((t + 2) % NSTAGE, (t + 2) * BKH); cp_wait<2>(); }
        else           { cp_wait<0>(); }
        __syncthreads();

        const uint32_t sa = sbase + (t % NSTAGE) * STAGEB;
        const uint32_t sb = sa + A_BYTES;

        // load kk=0,1 fragments
#pragma unroll
        for (int kk = 0; kk < 2; kk++) {
#pragma unroll
            for (int mt = 0; mt < 4; mt++)
                LDSM_X4(af[kk][mt], sa + (aRow + mt * 16) * ROWB + kk * 32 + aKB);
#pragma unroll
            for (int np = 0; np < NP; np++)
                LDSM_X4(bf[kk][np], sb + (bRow + np * 16) * ROWB + kk * 32 + bKB);
        }

#pragma unroll
        for (int kk = 0; kk < 4; kk++) {
#pragma unroll
            for (int mt = 0; mt < 4; mt++)
#pragma unroll
                for (int nt = 0; nt < NT; nt++)
                    mma16816(acc[mt][nt], af[kk & 1][mt],
                             bf[kk & 1][nt >> 1][(nt & 1) * 2],
                             bf[kk & 1][nt >> 1][(nt & 1) * 2 + 1]);
            if (kk + 2 < 4) {
                const int kn = kk + 2;
#pragma unroll
                for (int mt = 0; mt < 4; mt++)
                    LDSM_X4(af[kk & 1][mt],
                            sa + (aRow + mt * 16) * ROWB + kn * 32 + aKB);
#pragma unroll
                for (int np = 0; np < NP; np++)
                    LDSM_X4(bf[kk & 1][np],
                            sb + (bRow + np * 16) * ROWB + kn * 32 + bKB);
            }
        }
    }

#pragma unroll
    for (int mt = 0; mt < 4; mt++) {
        const int row0 = bm + wm * 64 + mt * 16 + (lane >> 2);
        const float rb0 = (BIAS == 3) ? bias[row0] : 0.0f;
        const float rb1 = (BIAS == 3) ? bias[row0 + 8] : 0.0f;
#pragma unroll
        for (int nt = 0; nt < NT; nt++) {
            const int col = bn + wn * WNC + nt * 8 + (lane & 3) * 2;
            float b0x = 0.f, b0y = 0.f, b1x = 0.f, b1y = 0.f;
            if (BIAS == 1) {
                const float2 bb = *(const float2*)(bias + col);
                b0x = bb.x; b0y = bb.y; b1x = bb.x; b1y = bb.y;
            } else if (BIAS == 3) {
                const float2 sv = *(const float2*)(bias2 + col);
                b0x = rb0 * sv.x; b0y = rb0 * sv.y;
                b1x = rb1 * sv.x; b1y = rb1 * sv.y;
            }
            const float c0 = acc[mt][nt][0] + b0x;
            const float c1 = acc[mt][nt][1] + b0y;
            const float c2 = acc[mt][nt][2] + b1x;
            const float c3 = acc[mt][nt][3] + b1y;
            if (F16OUT) {
                __half* p = Ch + (long)blockIdx.z * sC + (long)row0 * N + col;
                *(__half2*)p                 = __floats2half2_rn(c0, c1);
                *(__half2*)(p + (long)8 * N) = __floats2half2_rn(c2, c3);
            } else {
                float* p = Cf + (long)blockIdx.z * sC + (long)row0 * N + col;
                *(float2*)p                 = make_float2(c0, c1);
                *(float2*)(p + (long)8 * N) = make_float2(c2, c3);
            }
        }
    }
}

#define SMEM_256 (NSTAGE * (A_BYTES + 256 * ROWB))   // 221184
#define SMEM_128 (NSTAGE * (A_BYTES + 128 * ROWB))   // 147456

// ---------------------------------------------------------------------------
// FP16 TN-GEMM: C[M,N] = A^T @ B with A stored [K,M], B stored [K,N] (f16).
// Both operands via ldmatrix.trans. BKH=64, NSTAGE=4, frag double-buffered.
// ---------------------------------------------------------------------------
#define TN_RA 272                    // 128 halves + 16B pad
#define TN_RB 528                    // 256 halves + 16B pad
#define TN_AB (BKH * TN_RA)          // 17408
#define TN_BB (BKH * TN_RB)          // 33792
#define TN_STAGE (TN_AB + TN_BB)     // 51200
#define TN_SMEM (NSTAGE * TN_STAGE)  // 204800

__global__ void __launch_bounds__(256, 1) hgemm_tn(
    const __half* __restrict__ A, const __half* __restrict__ B,
    __half* __restrict__ Ch,
    int M, int N, int K, int lda, int ldb, long sA, long sB, long sC)
{
    A += (long)blockIdx.z * sA;
    B += (long)blockIdx.z * sB;

    extern __shared__ char smem[];
    const uint32_t sbase = smem_u32(smem);

    const int tid  = threadIdx.x;
    const int lane = tid & 31;
    const int warp = tid >> 5;
    const int wm   = warp & 1;
    const int wn   = warp >> 1;

    const int bm = blockIdx.y * 128;
    const int bn = blockIdx.x * 256;

    auto issue = [&](int stage, int k0) {
        const __half* Ab = A + (long)k0 * lda + bm;
        const __half* Bb = B + (long)k0 * ldb + bn;
        const uint32_t sa = sbase + stage * TN_STAGE;
        const uint32_t sb = sa + TN_AB;
#pragma unroll
        for (int i = 0; i < 4; i++) {            // A: 64 rows x 16 chunks
            const int c = tid + i * 256;
            const int r = c >> 4, kc = c & 15;
            cp_async16(sa + r * TN_RA + kc * 16, Ab + (long)r * lda + kc * 8);
        }
#pragma unroll
        for (int i = 0; i < 8; i++) {            // B: 64 rows x 32 chunks
            const int c = tid + i * 256;
            const int r = c >> 5, kc = c & 31;
            cp_async16(sb + r * TN_RB + kc * 16, Bb + (long)r * ldb + kc * 8);
        }
        cp_commit();
    };

    float acc[4][8][4];
#pragma unroll
    for (int i = 0; i < 4; i++)
#pragma unroll
        for (int j = 0; j < 8; j++)
#pragma unroll
            for (int r = 0; r < 4; r++) acc[i][j][r] = 0.0f;

    const int T = K / BKH;
    issue(0, 0);
    issue(1, BKH);

    const int aK  = (lane & 7) + ((lane >> 4) & 1) * 8;
    const int aM2 = (wm * 64 + ((lane >> 3) & 1) * 8) * 2;
    const int bK  = (lane & 7) + ((lane >> 3) & 1) * 8;
    const int bN2 = (wn * 64 + (lane >> 4) * 8) * 2;

    uint32_t af[2][4][4], bf[2][4][4];

    for (int t = 0; t < T; t++) {
        if (t + 2 < T) { issue((t + 2) % NSTAGE, (t + 2) * BKH); cp_wait<2>(); }
        else           { cp_wait<0>(); }
        __syncthreads();

        const uint32_t sa = sbase + (t % NSTAGE) * TN_STAGE;
        const uint32_t sb = sa + TN_AB;

#pragma unroll
        for (int kk = 0; kk < 2; kk++) {
#pragma unroll
            for (int mt = 0; mt < 4; mt++)
                LDSM_X4_T(af[kk][mt], sa + (kk * 16 + aK) * TN_RA + aM2 + mt * 32);
#pragma unroll
            for (int np = 0; np < 4; np++)
                LDSM_X4_T(bf[kk][np], sb + (kk * 16 + bK) * TN_RB + bN2 + np * 32);
        }

#pragma unroll
        for (int kk = 0; kk < 4; kk++) {
#pragma unroll
            for (int mt = 0; mt < 4; mt++)
#pragma unroll
                for (int nt = 0; nt < 8; nt++)
                    mma16816(acc[mt][nt], af[kk & 1][mt],
                             bf[kk & 1][nt >> 1][(nt & 1) * 2],
                             bf[kk & 1][nt >> 1][(nt & 1) * 2 + 1]);
            if (kk + 2 < 4) {
                const int kn = kk + 2;
#pragma unroll
                for (int mt = 0; mt < 4; mt++)
                    LDSM_X4_T(af[kk & 1][mt],
                              sa + (kn * 16 + aK) * TN_RA + aM2 + mt * 32);
#pragma unroll
                for (int np = 0; np < 4; np++)
                    LDSM_X4_T(bf[kk & 1][np],
                              sb + (kn * 16 + bK) * TN_RB + bN2 + np * 32);
            }
        }
    }

#pragma unroll
    for (int mt = 0; mt < 4; mt++) {
        const int row0 = bm + wm * 64 + mt * 16 + (lane >> 2);
#pragma unroll
        for (int nt = 0; nt < 8; nt++) {
            const int col = bn + wn * 64 + nt * 8 + (lane & 3) * 2;
            __half* p = Ch + (long)blockIdx.z * sC + (long)row0 * N + col;
            *(__half2*)p = __floats2half2_rn(acc[mt][nt][0], acc[mt][nt][1]);
            *(__half2*)(p + (long)8 * N) =
                __floats2half2_rn(acc[mt][nt][2], acc[mt][nt][3]);
        }
    }
}

// ---------------------------------------------------------------------------
// f32 -> f16 conversion, z-batched over up to 3 tensors. If binZ != null,
// each block (which covers exactly one 1024-element row when n == 1024*rows)
// also computes beffZ[row] = W[row,:]�binZ + baddZ[row] (fused fold: no extra
// DRAM pass over the weights).
// ---------------------------------------------------------------------------
__global__ void __launch_bounds__(256) f32to16z_kernel(
    const float* __restrict__ x0, const float* __restrict__ x1,
    const float* __restrict__ x2,
    __half* __restrict__ y0, __half* __restrict__ y1, __half* __restrict__ y2,
    const float* __restrict__ bin0, const float* __restrict__ bin1,
    const float* __restrict__ badd0, const float* __restrict__ badd1,
    float* __restrict__ bout0, float* __restrict__ bout1,
    int n)
{
    const int z = blockIdx.z;
    const float* x = (z == 0) ? x0 : (z == 1) ? x1 : x2;
    __half*      y = (z == 0) ? y0 : (z == 1) ? y1 : y2;
    const float* bin  = (z == 0) ? bin0 : (z == 1) ? bin1 : nullptr;
    const int i = (blockIdx.x * 256 + threadIdx.x) * 4;
    float4 v = make_float4(0.f, 0.f, 0.f, 0.f);
    if (i < n) {
        v = *(const float4*)(x + i);
        *(__half2*)(y + i)     = __floats2half2_rn(v.x, v.y);
        *(__half2*)(y + i + 2) = __floats2half2_rn(v.z, v.w);
    }
    if (bin != nullptr) {
        // block == one row of 1024; fold dot(W[row,:], bin) + badd[row]
        const int col = threadIdx.x * 4;
        const float4 bv = *(const float4*)(bin + col);
        float s = v.x * bv.x + v.y * bv.y + v.z * bv.z + v.w * bv.w;
#pragma unroll
        for (int o = 16; o; o >>= 1) s += __shfl_xor_sync(0xFFFFFFFF, s, o);
        __shared__ float red[8];
        if ((threadIdx.x & 31) == 0) red[threadIdx.x >> 5] = s;
        __syncthreads();
        if (threadIdx.x == 0) {
            float t = 0.0f;
#pragma unroll
            for (int w = 0; w < 8; w++) t += red[w];
            const float* badd = (z == 0) ? badd0 : badd1;
            float* bout       = (z == 0) ? bout0 : bout1;
            bout[blockIdx.x] = t + badd[blockIdx.x];
        }
    }
}

// ---------------------------------------------------------------------------
// f32 [1024,1024] -> transposed f16, z-batched over 2 tensors
// ---------------------------------------------------------------------------
__global__ void __launch_bounds__(256) f32to16Tz_kernel(
    const float* __restrict__ x0, const float* __restrict__ x1,
    __half* __restrict__ y0, __half* __restrict__ y1)
{
    const float* x = blockIdx.z ? x1 : x0;
    __half*      y = blockIdx.z ? y1 : y0;
    __shared__ float tile[32][33];
    const int tx = threadIdx.x & 31;
    const int ty = threadIdx.x >> 5;
    const int bx = blockIdx.x * 32;
    const int by = blockIdx.y * 32;
#pragma unroll
    for (int j = 0; j < 4; j++)
        tile[ty + j * 8][tx] = x[(long)(by + ty + j * 8) * D_MODEL + bx + tx];
    __syncthreads();
#pragma unroll
    for (int j = 0; j < 4; j++)
        y[(long)(bx + ty + j * 8) * D_MODEL + by + tx] =
            __float2half(tile[tx][ty + j * 8]);
}

// ---------------------------------------------------------------------------
// Row softmax over last dim (1024), f16 in-place. Warp per row (shuffle
// reductions). Block 0 also zeroes svec (stream-ordered before colsum).
// ---------------------------------------------------------------------------
__global__ void __launch_bounds__(256) row_softmax_kernel(
    __half* __restrict__ X, float* __restrict__ svec)
{
    if (blockIdx.x == 0) {
        for (int i = threadIdx.x; i < NB * D_MODEL; i += 256) svec[i] = 0.0f;
    }
    const int row  = blockIdx.x * 8 + (threadIdx.x >> 5);
    const int lane = threadIdx.x & 31;
    __half2* x = (__half2*)(X + (long)row * D_MODEL);

    float2 v[16];
    float m = -1e30f;
#pragma unroll
    for (int i = 0; i < 16; i++) {
        v[i] = __half22float2(x[lane + i * 32]);
        m = fmaxf(m, fmaxf(v[i].x, v[i].y));
    }
#pragma unroll
    for (int o = 16; o; o >>= 1) m = fmaxf(m, __shfl_xor_sync(0xFFFFFFFF, m, o));

    float sum = 0.0f;
#pragma unroll
    for (int i = 0; i < 16; i++) {
        v[i].x = __expf(v[i].x - m);
        v[i].y = __expf(v[i].y - m);
        sum += v[i].x + v[i].y;
    }
#pragma unroll
    for (int o = 16; o; o >>= 1) sum += __shfl_xor_sync(0xFFFFFFFF, sum, o);
    const float inv = 1.0f / sum;

#pragma unroll
    for (int i = 0; i < 16; i++)
        x[lane + i * 32] = __floats2half2_rn(v[i].x * inv, v[i].y * inv);
}

// ---------------------------------------------------------------------------
// Column sums of S: svec[b][d] += sum_{q in chunk} S[b][q][d]
// ---------------------------------------------------------------------------
__global__ void __launch_bounds__(256) colsum_kernel(
    const __half* __restrict__ S, float* __restrict__ svec)
{
    const int b = blockIdx.z;
    const int e2 = blockIdx.x * 256 + threadIdx.x;
    const int q0 = blockIdx.y * 128;
    const __half2* x = (const __half2*)(S + (long)b * TQ * D_MODEL) + e2;
    float sx = 0.0f, sy = 0.0f;
#pragma unroll 4
    for (int q = q0; q < q0 + 128; q++) {
        const float2 v = __half22float2(x[(long)q * (D_MODEL / 2)]);
        sx += v.x; sy += v.y;
    }
    atomicAdd(svec + b * D_MODEL + e2 * 2,     sx);
    atomicAdd(svec + b * D_MODEL + e2 * 2 + 1, sy);
}

// ---------------------------------------------------------------------------
// Column softmax over T_kv (axis=-2), f16 in-place, half2 columns, 1024 thr.
// ---------------------------------------------------------------------------
__global__ void __launch_bounds__(1024) col_softmax_kernel(__half* __restrict__ X)
{
    const int b = blockIdx.y;
    const int c = threadIdx.x & 31;
    const int s = threadIdx.x >> 5;            // 0..31
    const int e2 = blockIdx.x * 32 + c;

    __half2* x = (__half2*)(X + (long)b * TKV * D_MODEL) + e2;
    __shared__ float2 red[32][32];
    const int LD2 = D_MODEL / 2;

    float mx = -1e30f, my = -1e30f;
    for (int k = s; k < TKV; k += 32) {
        const float2 v = __half22float2(x[(long)k * LD2]);
        mx = fmaxf(mx, v.x); my = fmaxf(my, v.y);
    }
    red[s][c] = make_float2(mx, my);
    __syncthreads();
    if (s == 0) {
        float2 mm = red[0][c];
#pragma unroll
        for (int i = 1; i < 32; i++) {
            mm.x = fmaxf(mm.x, red[i][c].x);
            mm.y = fmaxf(mm.y, red[i][c].y);
        }
        red[0][c] = mm;
    }
    __syncthreads();
    mx = red[0][c].x; my = red[0][c].y;
    __syncthreads();

    float sx = 0.0f, sy = 0.0f;
    for (int k = s; k < TKV; k += 32) {
        const float2 v = __half22float2(x[(long)k * LD2]);
        sx += __expf(v.x - mx); sy += __expf(v.y - my);
    }
    red[s][c] = make_float2(sx, sy);
    __syncthreads();
    if (s == 0) {
        float2 ss = red[0][c];
#pragma unroll
        for (int i = 1; i < 32; i++) {
            ss.x += red[i][c].x; ss.y += red[i][c].y;
        }
        red[0][c] = ss;
    }
    __syncthreads();
    const float ix = 1.0f / red[0][c].x;
    const float iy = 1.0f / red[0][c].y;

    for (int k = s; k < TKV; k += 32) {
        const long idx = (long)k * LD2;
        const float2 v = __half22float2(x[idx]);
        x[idx] = __floats2half2_rn(__expf(v.x - mx) * ix, __expf(v.y - my) * iy);
    }
}

// ---------------------------------------------------------------------------
// Orchestration:
//   weight convert also folds beffU|V (one row per block, no extra pass)
//   WeffU|V = (Wu@Wl | WV@WA)                     [z-batched NT GEMM, BN=128]
//   logits  = (lat|inp) @ Weff^T + beff (f16)     [z-batched NT GEMM, BN=256]
//   S = row_softmax(logU) in place (+svec zero); svec = colsum(S)
//   Amat = col_softmax(logV) in place
//   X_b  = S_b^T @ lat_b                    [d2,d]   (TN GEMM)
//   PT_b = Wo @ X_b^T + bo (x) s_b          [e,d2]
//   o_b  = Amat_b @ PT_b^T                  [k,e]    (f32 out)
// ---------------------------------------------------------------------------
extern "C" void kernel_launch(void* const* d_in, const int* in_sizes, int n_in,
                              void* d_out, int out_size)
{
    const float* latent = (const float*)d_in[0];
    const float* input  = (const float*)d_in[1];
    const float* Wl = (const float*)d_in[2];
    const float* bl = (const float*)d_in[3];
    const float* Wu = (const float*)d_in[4];
    const float* bu = (const float*)d_in[5];
    const float* WA = (const float*)d_in[6];
    const float* bA = (const float*)d_in[7];
    const float* WV = (const float*)d_in[8];
    const float* bV = (const float*)d_in[9];
    const float* Wo = (const float*)d_in[10];
    const float* bo = (const float*)d_in[11];
    float* out = (float*)d_out;

    __half *act, *w16, *weff, *logits, *x16, *mt16;
    float *beff, *svec;
    cudaGetSymbolAddress((void**)&act,    g_act);
    cudaGetSymbolAddress((void**)&w16,    g_W16);
    cudaGetSymbolAddress((void**)&weff,   g_Weff);
    cudaGetSymbolAddress((void**)&beff,   g_beff);
    cudaGetSymbolAddress((void**)&logits, g_logits);
    cudaGetSymbolAddress((void**)&x16,    g_X16);
    cudaGetSymbolAddress((void**)&mt16,   g_MT16);
    cudaGetSymbolAddress((void**)&svec,   g_s);

    const long NW = (long)D_MODEL * D_MODEL;
    const long NACT = (long)MQ * D_MODEL;
    __half* Wu16  = w16 + 0 * NW;
    __half* WV16  = w16 + 1 * NW;
    __half* Wo16  = w16 + 2 * NW;
    __half* WlT16 = w16 + 3 * NW;
    __half* lat16 = act;
    __half* inp16 = act + NACT;
    __half* logU  = logits;
    __half* logV  = logits + NACT;

    cudaFuncSetAttribute(hgemm<0,1,128>, cudaFuncAttributeMaxDynamicSharedMemorySize, SMEM_128);
    cudaFuncSetAttribute(hgemm<1,1,256>, cudaFuncAttributeMaxDynamicSharedMemorySize, SMEM_256);
    cudaFuncSetAttribute(hgemm<3,1,256>, cudaFuncAttributeMaxDynamicSharedMemorySize, SMEM_256);
    cudaFuncSetAttribute(hgemm<0,0,256>, cudaFuncAttributeMaxDynamicSharedMemorySize, SMEM_256);
    cudaFuncSetAttribute(hgemm_tn, cudaFuncAttributeMaxDynamicSharedMemorySize, TN_SMEM);

    const dim3 blk(256);

    // Activation converts (no fold)
    f32to16z_kernel<<<dim3((int)(NACT / 1024), 1, 2), blk>>>(
        latent, input, nullptr, lat16, inp16, nullptr,
        nullptr, nullptr, nullptr, nullptr, nullptr, nullptr, (int)NACT);
    // Weight converts WITH beff fold (z0: Wu�bl+bu, z1: WV�bA+bV, z2: Wo plain)
    f32to16z_kernel<<<dim3((int)(NW / 1024), 1, 3), blk>>>(
        Wu, WV, Wo, Wu16, WV16, Wo16,
        bl, bA, bu, bV, beff, beff + D_MODEL, (int)NW);
    f32to16Tz_kernel<<<dim3(32, 32, 2), blk>>>(Wl, WA, WlT16, WlT16 + NW);

    // Weff = (Wu@Wl | WV@WA): z-batched, BN=128 -> 128 CTAs
    hgemm<0,1,128><<<dim3(8, 8, 2), blk, SMEM_128>>>(
        Wu16, WlT16, nullptr, nullptr, nullptr, weff,
        D_MODEL, D_MODEL, D_MODEL, NW, NW, NW, 0, 0);

    // logits = (lat|inp) @ Weff^T + beff  (f16 out)
    hgemm<1,1,256><<<dim3(4, 64, 2), blk, SMEM_256>>>(
        act, weff, beff, nullptr, nullptr, logits,
        MQ, D_MODEL, D_MODEL, NACT, NW, NACT, D_MODEL, 0);

    // S = row softmax (in place on logU; also zeroes svec); colsum
    row_softmax_kernel<<<MQ / 8, blk>>>(logU, svec);
    colsum_kernel<<<dim3(2, 16, NB), blk>>>(logU, svec);

    // Amat = col softmax (in place on logV)
    col_softmax_kernel<<<dim3(D_MODEL / 64, NB), 1024>>>(logV);

    // X_b = S_b^T @ lat_b   (TN)   M=1024(d2), N=1024(d), K=2048(q)
    hgemm_tn<<<dim3(4, 8, NB), blk, TN_SMEM>>>(
        logU, lat16, x16,
        D_MODEL, D_MODEL, TQ, D_MODEL, D_MODEL,
        (long)TQ * D_MODEL, (long)TQ * D_MODEL, NW);

    // PT_b = Wo @ X_b^T + bo (x) s_b   M=1024(e), N=1024(d2), K=1024(d)
    hgemm<3,1,256><<<dim3(4, 8, NB), blk, SMEM_256>>>(
        Wo16, x16, bo, svec, nullptr, mt16,
        D_MODEL, D_MODEL, D_MODEL,
        0, NW, NW, 0, (long)D_MODEL);

    // o_b = Amat_b @ PT_b^T   M=2048(k), N=1024(e), K=1024(d2)  (f32 out)
    hgemm<0,0,256><<<dim3(4, 16, NB), blk, SMEM_256>>>(
        logV, mt16, nullptr, nullptr, out, nullptr,
        TKV, D_MODEL, D_MODEL,
        (long)TKV * D_MODEL, NW, (long)TKV * D_MODEL, 0, 0);
}